// round 10
// baseline (speedup 1.0000x reference)
#include <cuda_runtime.h>
#include <cuda_fp16.h>
#include <math.h>
#include <stdint.h>

#define NIMG 800
typedef unsigned long long u64;

// ---------------- scratch ----------------
__device__ float g_pool1[(size_t)NIMG * 1764 * 64];
__device__ float g_raw  [(size_t)NIMG * 1764 * 64];
__device__ float g_pool2[(size_t)NIMG * 441 * 64];
__device__ float g_pool3[(size_t)NIMG * 100 * 64];
__device__ float g_pool4[(size_t)NIMG * 25 * 64];
__device__ float g_part [(size_t)NIMG * 128];        // per-image stats partials
__device__ float g_Z[2 * NIMG * 128];
__device__ float g_outs[5 * 21 * 32 * 64];
__device__ float g_ab[25 * 64 * 2];

// ---------------- warp mma (fp16 in, f32 acc) ----------------
__device__ __forceinline__ void mma16816(float* d, uint32_t a0, uint32_t a1,
                                         uint32_t a2, uint32_t a3,
                                         uint32_t b0, uint32_t b1) {
    asm volatile(
        "mma.sync.aligned.m16n8k16.row.col.f32.f16.f16.f32 "
        "{%0,%1,%2,%3}, {%4,%5,%6,%7}, {%8,%9}, {%0,%1,%2,%3};"
        : "+f"(d[0]), "+f"(d[1]), "+f"(d[2]), "+f"(d[3])
        : "r"(a0), "r"(a1), "r"(a2), "r"(a3), "r"(b0), "r"(b1));
}

// ================= conv1mma: layer 1 via im2col MMA, fused stats + pool =================
// K = 27 (9 taps x 3 ch) padded to 32. Tile = one pool-row pair (172 padded positions).
// Output: pool1 [g][42*42][64] channels-last + part[g][128]. No raw to global.
__global__ void __launch_bounds__(256) conv1mma_kernel(
    const float* __restrict__ xs, const float* __restrict__ xq,
    const float* __restrict__ w, const float* __restrict__ bias,
    float* __restrict__ pool1, float* __restrict__ part)
{
    constexpr int WP = 86, P = WP * WP;          // padded image
    constexpr int AR = 80;                       // A/B row stride bytes (conflict-free)
    constexpr int OFF_P  = 1024;                 // padded image f32, guard 96 entries each side
    constexpr int PENT = 96 + P + 96;            // 7588 entries x3 floats
    constexpr int OFF_AH = OFF_P + PENT * 12;    // 92080
    constexpr int OFF_AL = OFF_AH + 176 * AR;
    constexpr int OFF_B  = OFF_AL + 176 * AR;
    constexpr int OFF_RAW = OFF_B + 64 * AR;

    extern __shared__ __align__(16) char smem[];
    int tid = threadIdx.x;
    int g = blockIdx.x;
    float* bias_sh = (float*)(smem + 16);
    if (tid < 64) bias_sh[tid] = bias[tid];

    // stage padded image (NHWC -> interleaved [sp][c]) with zero guards
    {
        int b = g & 31, slot = g >> 5;
        const float* src = (slot < 20)
            ? (xs + (size_t)(b * 20 + slot) * 84 * 84 * 3)
            : (xq + (size_t)(b * 5 + (slot - 20)) * 84 * 84 * 3);
        float* Pp = (float*)(smem + OFF_P);
        for (int i = tid; i < PENT * 3; i += 256) {
            int sp = i / 3 - 96 * 1;             // entry index over [ -96, P+96 )
            int c = i - (sp + 96) * 3;
            float v = 0.f;
            if (sp >= 0 && sp < P) {
                int py = sp / WP, px = sp - py * WP;
                if (px >= 1 && px <= 84 && py >= 1 && py <= 84)
                    v = src[(size_t)((py - 1) * 84 + (px - 1)) * 3 + c];
            }
            Pp[i] = v;
        }
    }
    // stage B: w flat [k][oc] (k = (ky*3+kx)*3+c), fp16, zeros for k>=27
    for (int i = tid; i < 64 * 32; i += 256) {
        int oc = i >> 5, k = i & 31;
        float v = (k < 27) ? w[k * 64 + oc] : 0.f;
        *(__half*)(smem + OFF_B + oc * AR + k * 2) = __float2half_rn(v);
    }

    int warp = tid >> 5, lane = tid & 31;
    int g_row = lane >> 2, four = lane & 3;
    int nmt = (warp < 3) ? 2 : 1;

    float ps[8][2], qs[8][2];
#pragma unroll
    for (int nt = 0; nt < 8; nt++) { ps[nt][0]=0.f; ps[nt][1]=0.f; qs[nt][0]=0.f; qs[nt][1]=0.f; }

    const float* Pbase = (float*)(smem + OFF_P) + 96 * 3;

    for (int yp = 0; yp < 42; yp++) {
        int s0 = (2 * yp + 1) * WP;              // output row pair (2yp+1, 2yp+2)
        __syncthreads();                          // prev MMA done reading A; prev pool done
        // ---- build im2col A (hi/lo fp16): rows 0..175, k 0..31 ----
        for (int i = tid; i < 176 * 32; i += 256) {
            int m = i >> 5, k = i & 31;
            float v = 0.f;
            if (k < 27) {
                int t = k / 3, c = k - t * 3;
                int shift = (t / 3 - 1) * WP + (t % 3 - 1);
                v = Pbase[(s0 + m + shift) * 3 + c];
            }
            __half h = __float2half_rn(v);
            *(__half*)(smem + OFF_AH + m * AR + k * 2) = h;
            *(__half*)(smem + OFF_AL + m * AR + k * 2) = __float2half_rn(v - __half2float(h));
        }
        __syncthreads();

        // ---- MMA: warp covers mt = warp (+ 8+warp for warps 0-2) ----
        float d[2][8][4];
#pragma unroll
        for (int im = 0; im < 2; im++)
#pragma unroll
            for (int nt = 0; nt < 8; nt++)
#pragma unroll
                for (int i = 0; i < 4; i++) d[im][nt][i] = 0.f;

#pragma unroll 1
        for (int pass = 0; pass < 2; pass++) {
            const char* abase = smem + (pass ? OFF_AL : OFF_AH);
#pragma unroll
            for (int kc = 0; kc < 2; kc++) {
                int cb = kc * 32 + four * 4;
#pragma unroll
                for (int im = 0; im < 2; im++) {
                    if (im >= nmt) break;
                    int mt = (im == 0) ? warp : (8 + warp);
                    const char* ap = abase + (mt * 16 + g_row) * AR + cb;
                    uint32_t a0 = *(const uint32_t*)ap;
                    uint32_t a1 = *(const uint32_t*)(ap + 8 * AR);
                    uint32_t a2 = *(const uint32_t*)(ap + 16);
                    uint32_t a3 = *(const uint32_t*)(ap + 8 * AR + 16);
#pragma unroll
                    for (int nt = 0; nt < 8; nt++) {
                        const char* bp = smem + OFF_B + (nt * 8 + g_row) * AR + cb;
                        uint32_t b0 = *(const uint32_t*)bp;
                        uint32_t b1 = *(const uint32_t*)(bp + 16);
                        mma16816(d[im][nt], a0, a1, a2, a3, b0, b1);
                    }
                }
            }
        }

        // ---- write raw tile to smem + fused stats ----
        float* rawp = (float*)(smem + OFF_RAW);
#pragma unroll
        for (int im = 0; im < 2; im++) {
            if (im >= nmt) break;
            int mt = (im == 0) ? warp : (8 + warp);
#pragma unroll
            for (int rr = 0; rr < 2; rr++) {
                int m = mt * 16 + g_row + rr * 8;
                if (m < 172) {
                    int px = (m >= WP) ? (m - WP) : m;
                    bool valid = (px >= 1 && px <= 84);
#pragma unroll
                    for (int nt = 0; nt < 8; nt++) {
                        int oc = nt * 8 + four * 2;
                        float vx = d[im][nt][rr * 2]     + bias_sh[oc];
                        float vy = d[im][nt][rr * 2 + 1] + bias_sh[oc + 1];
                        *(float2*)(rawp + m * 64 + oc) = make_float2(vx, vy);
                        if (valid) {
                            ps[nt][0] += vx; qs[nt][0] += vx * vx;
                            ps[nt][1] += vy; qs[nt][1] += vy * vy;
                        }
                    }
                }
            }
        }
        __syncthreads();

        // ---- pool 2x2 from smem raw, write pool1 channels-last ----
        for (int i = tid; i < 42 * 64; i += 256) {
            int ox = i >> 6, c = i & 63;
            int m0 = 2 * ox + 1;
            float v = fmaxf(fmaxf(rawp[m0 * 64 + c], rawp[(m0 + 1) * 64 + c]),
                            fmaxf(rawp[(m0 + WP) * 64 + c], rawp[(m0 + WP + 1) * 64 + c]));
            pool1[((size_t)g * 1764 + yp * 42 + ox) * 64 + c] = v;
        }
    }

    // ---- stats reduction -> part[g][128] ----
#pragma unroll
    for (int nt = 0; nt < 8; nt++)
#pragma unroll
        for (int j = 0; j < 2; j++) {
#pragma unroll
            for (int off = 16; off >= 4; off >>= 1) {
                ps[nt][j] += __shfl_down_sync(~0u, ps[nt][j], off);
                qs[nt][j] += __shfl_down_sync(~0u, qs[nt][j], off);
            }
        }
    __syncthreads();
    float* wst = (float*)(smem + OFF_AH);
    if (lane < 4) {
#pragma unroll
        for (int nt = 0; nt < 8; nt++)
#pragma unroll
            for (int j = 0; j < 2; j++) {
                int oc = nt * 8 + lane * 2 + j;
                wst[warp * 128 + oc]      = ps[nt][j];
                wst[warp * 128 + 64 + oc] = qs[nt][j];
            }
    }
    __syncthreads();
    if (tid < 128) {
        float s = 0.f;
#pragma unroll
        for (int wi = 0; wi < 8; wi++) s += wst[wi * 128 + tid];
        part[(size_t)g * 128 + tid] = s;
    }
}

// ================= mmaconv: layers 2-4 (unchanged from R9) =================
template <int NX, int NT>
__global__ void __launch_bounds__(256) mmaconv_kernel(
    const float* __restrict__ in, const float* __restrict__ abp,
    const float* __restrict__ w, const float* __restrict__ bias,
    float* __restrict__ raw, float* __restrict__ part)
{
    constexpr int W = NX + 2, P = W * W, PIX = NX * NX;
    constexpr int ROWS = 2 * W + 260;
    constexpr int SROW = 144;
    constexpr int BTAP = 64 * SROW;
    constexpr int OFF_B  = 1024;
    constexpr int OFF_SH = OFF_B + 9 * BTAP;
    constexpr int OFF_SL = OFF_SH + ROWS * SROW;

    extern __shared__ __align__(16) char smem[];
    int tid = threadIdx.x;
    int g = blockIdx.x, slot = g >> 5;
    float* bias_sh = (float*)(smem + 16);
    float* ab_sh   = (float*)(smem + 304);
    if (tid < 64) bias_sh[tid] = bias[tid];
    if (tid < 128) ab_sh[tid] = abp[slot * 128 + tid];

    for (int i = tid; i < 9 * 64 * 64; i += 256) {
        int t = i >> 12, r = i & 4095, ci = r >> 6, oc = r & 63;
        *(__half*)(smem + OFF_B + (t * 64 + oc) * SROW + ci * 2) = __float2half_rn(w[i]);
    }

    int warp = tid >> 5, lane = tid & 31;
    int g_row = lane >> 2, four = lane & 3;
    int mbase = warp * 32;

    float ps[8][2], qs[8][2];
#pragma unroll
    for (int nt = 0; nt < 8; nt++) { ps[nt][0]=0.f; ps[nt][1]=0.f; qs[nt][0]=0.f; qs[nt][1]=0.f; }

    for (int tile = 0; tile < NT; tile++) {
        int s0 = tile * 256;
        __syncthreads();
        for (int i = tid; i < ROWS * 16; i += 256) {
            int r = i >> 4, c4 = (i & 15) * 4;
            int sp = s0 - W - 1 + r;
            float4 v = make_float4(0.f, 0.f, 0.f, 0.f);
            if (sp >= 0 && sp < P) {
                int py = sp / W, px = sp - py * W;
                if (px >= 1 && px <= NX && py >= 1 && py <= NX) {
                    float4 rv = *(const float4*)&in[((size_t)g * PIX + (py - 1) * NX + (px - 1)) * 64 + c4];
                    v.x = fmaxf(fmaf(ab_sh[(c4 + 0) * 2], rv.x, ab_sh[(c4 + 0) * 2 + 1]), 0.f);
                    v.y = fmaxf(fmaf(ab_sh[(c4 + 1) * 2], rv.y, ab_sh[(c4 + 1) * 2 + 1]), 0.f);
                    v.z = fmaxf(fmaf(ab_sh[(c4 + 2) * 2], rv.z, ab_sh[(c4 + 2) * 2 + 1]), 0.f);
                    v.w = fmaxf(fmaf(ab_sh[(c4 + 3) * 2], rv.w, ab_sh[(c4 + 3) * 2 + 1]), 0.f);
                }
            }
            __half hx = __float2half_rn(v.x), hy = __float2half_rn(v.y);
            __half hz = __float2half_rn(v.z), hw = __float2half_rn(v.w);
            __half lx = __float2half_rn(v.x - __half2float(hx));
            __half ly = __float2half_rn(v.y - __half2float(hy));
            __half lz = __float2half_rn(v.z - __half2float(hz));
            __half lw = __float2half_rn(v.w - __half2float(hw));
            __half2 h01 = __halves2half2(hx, hy), h23 = __halves2half2(hz, hw);
            __half2 l01 = __halves2half2(lx, ly), l23 = __halves2half2(lz, lw);
            *(uint2*)(smem + OFF_SH + r * SROW + c4 * 2) =
                make_uint2(*(uint32_t*)&h01, *(uint32_t*)&h23);
            *(uint2*)(smem + OFF_SL + r * SROW + c4 * 2) =
                make_uint2(*(uint32_t*)&l01, *(uint32_t*)&l23);
        }
        __syncthreads();

        float d[2][8][4];
#pragma unroll
        for (int mt = 0; mt < 2; mt++)
#pragma unroll
            for (int nt = 0; nt < 8; nt++)
#pragma unroll
                for (int i = 0; i < 4; i++) d[mt][nt][i] = 0.f;

#pragma unroll 1
        for (int pass = 0; pass < 2; pass++) {
            const char* abase = smem + (pass ? OFF_SL : OFF_SH);
#pragma unroll 1
            for (int t = 0; t < 9; t++) {
                int rshift = (t / 3) * W + (t % 3);
                const char* bt = smem + OFF_B + t * BTAP;
#pragma unroll
                for (int kc = 0; kc < 4; kc++) {
                    int cb = kc * 32 + four * 4;
                    uint32_t a[2][4];
#pragma unroll
                    for (int mt = 0; mt < 2; mt++) {
                        const char* ap = abase + (mbase + mt * 16 + rshift + g_row) * SROW + cb;
                        a[mt][0] = *(const uint32_t*)ap;
                        a[mt][1] = *(const uint32_t*)(ap + 8 * SROW);
                        a[mt][2] = *(const uint32_t*)(ap + 16);
                        a[mt][3] = *(const uint32_t*)(ap + 8 * SROW + 16);
                    }
#pragma unroll
                    for (int nt = 0; nt < 8; nt++) {
                        const char* bp = bt + (nt * 8 + g_row) * SROW + cb;
                        uint32_t b0 = *(const uint32_t*)bp;
                        uint32_t b1 = *(const uint32_t*)(bp + 16);
                        mma16816(d[0][nt], a[0][0], a[0][1], a[0][2], a[0][3], b0, b1);
                        mma16816(d[1][nt], a[1][0], a[1][1], a[1][2], a[1][3], b0, b1);
                    }
                }
            }
        }

#pragma unroll
        for (int mt = 0; mt < 2; mt++)
#pragma unroll
            for (int rr = 0; rr < 2; rr++) {
                int m = mbase + mt * 16 + g_row + rr * 8;
                int sp = s0 + m;
                bool ok = false;
                float* o = 0;
                if (sp < P) {
                    int py = sp / W, px = sp - py * W;
                    if (px >= 1 && px <= NX && py >= 1 && py <= NX) {
                        ok = true;
                        o = raw + ((size_t)g * PIX + (py - 1) * NX + (px - 1)) * 64;
                    }
                }
#pragma unroll
                for (int nt = 0; nt < 8; nt++) {
                    int oc = nt * 8 + four * 2;
                    float vx = d[mt][nt][rr * 2]     + bias_sh[oc];
                    float vy = d[mt][nt][rr * 2 + 1] + bias_sh[oc + 1];
                    if (ok) {
                        *(float2*)(o + oc) = make_float2(vx, vy);
                        ps[nt][0] += vx; qs[nt][0] += vx * vx;
                        ps[nt][1] += vy; qs[nt][1] += vy * vy;
                    }
                }
            }
    }

#pragma unroll
    for (int nt = 0; nt < 8; nt++)
#pragma unroll
        for (int j = 0; j < 2; j++) {
#pragma unroll
            for (int off = 16; off >= 4; off >>= 1) {
                ps[nt][j] += __shfl_down_sync(~0u, ps[nt][j], off);
                qs[nt][j] += __shfl_down_sync(~0u, qs[nt][j], off);
            }
        }
    __syncthreads();
    float* wst = (float*)(smem + OFF_SH);
    if (lane < 4) {
#pragma unroll
        for (int nt = 0; nt < 8; nt++)
#pragma unroll
            for (int j = 0; j < 2; j++) {
                int oc = nt * 8 + lane * 2 + j;
                wst[warp * 128 + oc]      = ps[nt][j];
                wst[warp * 128 + 64 + oc] = qs[nt][j];
            }
    }
    __syncthreads();
    if (tid < 128) {
        float s = 0.f;
#pragma unroll
        for (int wi = 0; wi < 8; wi++) s += wst[wi * 128 + tid];
        part[(size_t)g * 128 + tid] = s;
    }
}

// ---------------- per-slot BN affine from per-image partials [g][128] ----------------
__global__ void __launch_bounds__(64) abfin2_kernel(const float* __restrict__ part,
    const float* __restrict__ gamma, const float* __restrict__ beta,
    float* __restrict__ ab, float invCnt)
{
    int slot = blockIdx.x, c = threadIdx.x;
    float s = 0.f, q = 0.f;
    for (int b = 0; b < 32; b++) {
        s += part[(size_t)(slot * 32 + b) * 128 + c];
        q += part[(size_t)(slot * 32 + b) * 128 + 64 + c];
    }
    float mn = s * invCnt;
    float var = q * invCnt - mn * mn;
    float sc = gamma[c] * rsqrtf(var + 1e-3f);
    ab[(slot * 64 + c) * 2] = sc;
    ab[(slot * 64 + c) * 2 + 1] = beta[c] - mn * sc;
}

// ---------------- 2x2 maxpool on channels-last raw (pre-BN, exact) ----------------
template <int NX>
__global__ void __launch_bounds__(256) poolCL_kernel(const float* __restrict__ raw,
                                                    float* __restrict__ out)
{
    constexpr int Np = NX / 2;
    long idx = (long)blockIdx.x * 256 + threadIdx.x;
    if (idx >= (long)NIMG * Np * Np * 64) return;
    int c = (int)(idx & 63); long t = idx >> 6;
    int ox = (int)(t % Np); t /= Np;
    int oy = (int)(t % Np); int g = (int)(t / Np);
    const float* p = raw + ((size_t)g * NX * NX + (2 * oy) * NX + 2 * ox) * 64 + c;
    float v = fmaxf(fmaxf(p[0], p[64]), fmaxf(p[(size_t)NX * 64], p[(size_t)NX * 64 + 64]));
    out[idx] = v;
}

// ---------------- gemmz ----------------
__global__ void __launch_bounds__(256) gemmz_kernel(
    const float* __restrict__ emb, const float* __restrict__ abp,
    const float* __restrict__ fk, const float* __restrict__ fb,
    const float* __restrict__ bk, const float* __restrict__ bb,
    float* __restrict__ Z)
{
    int gb = blockIdx.x, dir = blockIdx.y;
    const float* W = dir ? bk : fk;
    const float* bias = dir ? bb : fb;
    float* Zo = Z + (size_t)dir * NIMG * 128;
    __shared__ float A_sh[32][33];
    __shared__ __align__(16) float B_sh[32][128];
    int tid = threadIdx.x, jj = tid & 31, gg = tid >> 5;
    float acc[4][4] = {};
    for (int d0 = 0; d0 < 1600; d0 += 32) {
        for (int i = tid; i < 1024; i += 256) {
            int r = i >> 5, dd = i & 31, d = d0 + dd, c = d & 63;
            float raw = emb[(size_t)(gb * 32 + r) * 1600 + d];
            A_sh[r][dd] = fmaxf(fmaf(abp[(gb * 64 + c) * 2], raw, abp[(gb * 64 + c) * 2 + 1]), 0.f);
        }
        for (int i = tid; i < 4096; i += 256)
            B_sh[i >> 7][i & 127] = W[(size_t)(d0 + (i >> 7)) * 128 + (i & 127)];
        __syncthreads();
#pragma unroll
        for (int dd = 0; dd < 32; dd++) {
            float4 bv = *(const float4*)&B_sh[dd][jj * 4];
#pragma unroll
            for (int r = 0; r < 4; r++) {
                float a = A_sh[gg * 4 + r][dd];
                acc[r][0] += a * bv.x; acc[r][1] += a * bv.y;
                acc[r][2] += a * bv.z; acc[r][3] += a * bv.w;
            }
        }
        __syncthreads();
    }
#pragma unroll
    for (int r = 0; r < 4; r++)
#pragma unroll
        for (int c = 0; c < 4; c++)
            Zo[(size_t)(gb * 32 + gg * 4 + r) * 128 + jj * 4 + c] = acc[r][c] + bias[jj * 4 + c];
}

// ---------------- LSTM ----------------
__global__ void __launch_bounds__(672) lstm_kernel(
    const float* __restrict__ Z,
    const float* __restrict__ fr, const float* __restrict__ br,
    float* __restrict__ outs)
{
    int q = blockIdx.x, dir = blockIdx.y;
    const float* R = dir ? br : fr;
    const float* Zp = Z + (size_t)dir * NIMG * 128;
    __shared__ float Wh[32][128];
    __shared__ float h_sh[21][32], c_sh[21][32];
    int tid = threadIdx.x;
    for (int i = tid; i < 4096; i += 672) Wh[i >> 7][i & 127] = R[i];
    int p = tid >> 5, j = tid & 31;
    h_sh[p][j] = 0.f; c_sh[p][j] = 0.f;
    __syncthreads();
    int slot = (p < 20) ? p : (20 + q);
    for (int step = 0; step < 32; step++) {
        int t = dir ? (31 - step) : step;
        const float* zr = Zp + (size_t)(slot * 32 + t) * 128;
        float z0 = zr[j], z1 = zr[32 + j], z2 = zr[64 + j], z3 = zr[96 + j];
#pragma unroll
        for (int k = 0; k < 32; k++) {
            float hk = h_sh[p][k];
            z0 += hk * Wh[k][j]; z1 += hk * Wh[k][32 + j];
            z2 += hk * Wh[k][64 + j]; z3 += hk * Wh[k][96 + j];
        }
        float ig = 1.f / (1.f + expf(-z0)), fg = 1.f / (1.f + expf(-z1));
        float gg = tanhf(z2), og = 1.f / (1.f + expf(-z3));
        float cn = fg * c_sh[p][j] + ig * gg;
        float hn = og * tanhf(cn);
        __syncthreads();
        h_sh[p][j] = hn; c_sh[p][j] = cn;
        outs[(size_t)((q * 21 + p) * 32 + t) * 64 + dir * 32 + j] = hn;
        __syncthreads();
    }
}

// ---------------- attention + CE + acc ----------------
__global__ void __launch_bounds__(256) final_kernel(
    const float* __restrict__ outs,
    const int* __restrict__ ysup, const int* __restrict__ yqry,
    float* __restrict__ out)
{
    __shared__ float ce_sh[160], eq_sh[160];
    int tid = threadIdx.x;
    if (tid < 160) {
        int q = tid / 32, b = tid % 32;
        const float* qry = outs + (size_t)((q * 21 + 20) * 32 + b) * 64;
        float logit[20];
        for (int s = 0; s < 20; s++) {
            const float* sp = outs + (size_t)((q * 21 + s) * 32 + b) * 64;
            float d = 0.f, n2 = 0.f;
            for (int k = 0; k < 64; k++) { d += qry[k] * sp[k]; n2 += sp[k] * sp[k]; }
            logit[s] = d * rsqrtf(fmaxf(n2, 1e-10f));
        }
        float mx = logit[0];
        for (int s = 1; s < 20; s++) mx = fmaxf(mx, logit[s]);
        float den = 0.f;
        for (int s = 0; s < 20; s++) { logit[s] = expf(logit[s] - mx); den += logit[s]; }
        float invden = 1.f / den;
        float preds[20];
        for (int wq = 0; wq < 20; wq++) preds[wq] = 0.f;
        for (int s = 0; s < 20; s++) preds[ysup[b * 20 + s]] += logit[s] * invden;
        int yq = yqry[b * 5 + q];
        float pv = fminf(fmaxf(preds[yq], 1e-7f), 1.f - 1e-7f);
        ce_sh[tid] = -logf(pv);
        int best = 0;
        for (int wq = 1; wq < 20; wq++) if (preds[wq] > preds[best]) best = wq;
        eq_sh[tid] = (best == yq) ? 1.f : 0.f;
    }
    __syncthreads();
    if (tid < 32) {
        float s = 0.f;
        for (int q = 0; q < 5; q++) s += ce_sh[q * 32 + tid];
        out[tid] = s * 0.2f;
    }
    if (tid == 0) {
        float s = 0.f;
        for (int i = 0; i < 160; i++) s += eq_sh[i];
        out[32] = s / 160.f;
    }
}

// ---------------- launch ----------------
extern "C" void kernel_launch(void* const* d_in, const int* in_sizes, int n_in,
                              void* d_out, int out_size)
{
    (void)in_sizes; (void)n_in; (void)out_size;
    const float* xs = (const float*)d_in[0];
    const int* ysup = (const int*)d_in[1];
    const float* xq = (const float*)d_in[2];
    const int* yqry = (const int*)d_in[3];
    const float *k1=(const float*)d_in[4],  *b1=(const float*)d_in[5],  *g1=(const float*)d_in[6],  *be1=(const float*)d_in[7];
    const float *k2=(const float*)d_in[8],  *b2=(const float*)d_in[9],  *g2=(const float*)d_in[10], *be2=(const float*)d_in[11];
    const float *k3=(const float*)d_in[12], *b3=(const float*)d_in[13], *g3=(const float*)d_in[14], *be3=(const float*)d_in[15];
    const float *k4=(const float*)d_in[16], *b4=(const float*)d_in[17], *g4=(const float*)d_in[18], *be4=(const float*)d_in[19];
    const float *fk=(const float*)d_in[20], *fr=(const float*)d_in[21], *fb=(const float*)d_in[22];
    const float *bk=(const float*)d_in[23], *br=(const float*)d_in[24], *bb=(const float*)d_in[25];

    float *pool1, *raw, *pool2, *pool3, *pool4, *part, *Z, *outs, *ab;
    cudaGetSymbolAddress((void**)&pool1, g_pool1);
    cudaGetSymbolAddress((void**)&raw, g_raw);
    cudaGetSymbolAddress((void**)&pool2, g_pool2);
    cudaGetSymbolAddress((void**)&pool3, g_pool3);
    cudaGetSymbolAddress((void**)&pool4, g_pool4);
    cudaGetSymbolAddress((void**)&part, g_part);
    cudaGetSymbolAddress((void**)&Z, g_Z);
    cudaGetSymbolAddress((void**)&outs, g_outs);
    cudaGetSymbolAddress((void**)&ab, g_ab);

    // conv1mma smem: 1024 + (96+7396+96)*12 + 2*176*80 + 64*80 + 176*64*4
    const int SM1  = 1024 + 7588 * 12 + 2 * 176 * 80 + 64 * 80 + 176 * 64 * 4;  // 170416
    const int SM42 = 1024 + 9 * 64 * 144 + 2 * (2 * 44 + 260) * 144;  // 184192
    const int SM21 = 1024 + 9 * 64 * 144 + 2 * (2 * 23 + 260) * 144;  // 172096
    const int SM10 = 1024 + 9 * 64 * 144 + 2 * (2 * 12 + 260) * 144;  // 165760
    cudaFuncSetAttribute(conv1mma_kernel,      cudaFuncAttributeMaxDynamicSharedMemorySize, SM1);
    cudaFuncSetAttribute(mmaconv_kernel<42,8>, cudaFuncAttributeMaxDynamicSharedMemorySize, SM42);
    cudaFuncSetAttribute(mmaconv_kernel<21,3>, cudaFuncAttributeMaxDynamicSharedMemorySize, SM21);
    cudaFuncSetAttribute(mmaconv_kernel<10,1>, cudaFuncAttributeMaxDynamicSharedMemorySize, SM10);

    // L1: MMA conv + fused stats + fused pool -> pool1
    conv1mma_kernel<<<NIMG, 256, SM1>>>(xs, xq, k1, b1, pool1, part);
    abfin2_kernel<<<25, 64>>>(part, g1, be1, ab, 1.f / (32.f * 7056.f));
    // L2: mma conv on 42 (stats fused)
    mmaconv_kernel<42,8><<<NIMG, 256, SM42>>>(pool1, ab, k2, b2, raw, part);
    poolCL_kernel<42><<<(NIMG*441*64 + 255)/256, 256>>>(raw, pool2);
    abfin2_kernel<<<25, 64>>>(part, g2, be2, ab, 1.f / (32.f * 1764.f));
    // L3: mma conv on 21
    mmaconv_kernel<21,3><<<NIMG, 256, SM21>>>(pool2, ab, k3, b3, raw, part);
    poolCL_kernel<21><<<(NIMG*100*64 + 255)/256, 256>>>(raw, pool3);
    abfin2_kernel<<<25, 64>>>(part, g3, be3, ab, 1.f / (32.f * 441.f));
    // L4: mma conv on 10
    mmaconv_kernel<10,1><<<NIMG, 256, SM10>>>(pool3, ab, k4, b4, raw, part);
    poolCL_kernel<10><<<(NIMG*25*64 + 255)/256, 256>>>(raw, pool4);
    abfin2_kernel<<<25, 64>>>(part, g4, be4, ab, 1.f / (32.f * 100.f));

    gemmz_kernel<<<dim3(25, 2), 256>>>(pool4, ab, fk, fb, bk, bb, Z);
    lstm_kernel<<<dim3(5, 2), 672>>>(Z, fr, br, outs);
    final_kernel<<<1, 256>>>(outs, ysup, yqry, (float*)d_out);
}

// round 11
// speedup vs baseline: 1.0793x; 1.0793x over previous
#include <cuda_runtime.h>
#include <cuda_fp16.h>
#include <math.h>
#include <stdint.h>

#define NIMG 800
typedef unsigned long long u64;

// ---------------- scratch ----------------
__device__ float g_pool1[(size_t)NIMG * 1764 * 64];
__device__ float g_raw  [(size_t)NIMG * 1764 * 64];
__device__ float g_pool2[(size_t)NIMG * 441 * 64];
__device__ float g_pool3[(size_t)NIMG * 100 * 64];
__device__ float g_pool4[(size_t)NIMG * 25 * 64];
__device__ float g_part [(size_t)NIMG * 128];
__device__ float g_Z[2 * NIMG * 128];
__device__ float g_outs[5 * 21 * 32 * 64];
__device__ float g_ab[25 * 64 * 2];

// ---------------- warp mma (fp16 in, f32 acc) ----------------
__device__ __forceinline__ void mma16816(float* d, uint32_t a0, uint32_t a1,
                                         uint32_t a2, uint32_t a3,
                                         uint32_t b0, uint32_t b1) {
    asm volatile(
        "mma.sync.aligned.m16n8k16.row.col.f32.f16.f16.f32 "
        "{%0,%1,%2,%3}, {%4,%5,%6,%7}, {%8,%9}, {%0,%1,%2,%3};"
        : "+f"(d[0]), "+f"(d[1]), "+f"(d[2]), "+f"(d[3])
        : "r"(a0), "r"(a1), "r"(a2), "r"(a3), "r"(b0), "r"(b1));
}
__device__ __forceinline__ uint32_t packh2(__half a, __half b) {
    __half2 h = __halves2half2(a, b);
    return *(uint32_t*)&h;
}

// ================= conv1mma2: layer 1, direct fragment gather =================
// K = 27 (9 taps x 3 ch) padded to 32 (B zero-padded). Tile = one pool-row pair.
// A fragments gathered per-lane straight from the staged padded fp32 image.
// Fused stats + pool; raw never leaves smem.
__global__ void __launch_bounds__(256) conv1mma2_kernel(
    const float* __restrict__ xs, const float* __restrict__ xq,
    const float* __restrict__ w, const float* __restrict__ bias,
    float* __restrict__ pool1, float* __restrict__ part)
{
    constexpr int WP = 86, P = WP * WP;          // 7396
    constexpr int PENT = 96 + P + 96;            // 7588 entries x 3 floats
    constexpr int AR = 80;                       // B row stride bytes
    constexpr int OFF_P   = 1024;
    constexpr int OFF_B   = OFF_P + PENT * 12;   // 92080
    constexpr int OFF_RAW = OFF_B + 64 * AR;     // 97200 (+45056 -> 142256)

    extern __shared__ __align__(16) char smem[];
    int tid = threadIdx.x;
    int g = blockIdx.x;
    float* bias_sh = (float*)(smem + 16);
    if (tid < 64) bias_sh[tid] = bias[tid];

    // stage padded image [entry][c] fp32 with 96-entry zero guards both sides
    {
        int b = g & 31, slot = g >> 5;
        const float* src = (slot < 20)
            ? (xs + (size_t)(b * 20 + slot) * 84 * 84 * 3)
            : (xq + (size_t)(b * 5 + (slot - 20)) * 84 * 84 * 3);
        float* Pp = (float*)(smem + OFF_P);
        for (int i = tid; i < PENT * 3; i += 256) {
            int sp = i / 3 - 96;
            int c = i - (sp + 96) * 3;
            float v = 0.f;
            if (sp >= 0 && sp < P) {
                int py = sp / WP, px = sp - py * WP;
                if (px >= 1 && px <= 84 && py >= 1 && py <= 84)
                    v = src[(size_t)((py - 1) * 84 + (px - 1)) * 3 + c];
            }
            Pp[i] = v;
        }
    }
    // stage B: [oc][k] fp16, zero for k >= 27  (w layout: k*64 + oc)
    for (int i = tid; i < 64 * 32; i += 256) {
        int oc = i >> 5, k = i & 31;
        float v = (k < 27) ? w[k * 64 + oc] : 0.f;
        *(__half*)(smem + OFF_B + oc * AR + k * 2) = __float2half_rn(v);
    }
    __syncthreads();

    int warp = tid >> 5, lane = tid & 31;
    int g_row = lane >> 2, four = lane & 3;
    int nmt = (warp < 3) ? 2 : 1;

    // per-lane gather offsets: rel[kc][kh][h] = shift(tap)*3 + ch, k = kc*16+kh*8+four*2+h
    int rel[8];
#pragma unroll
    for (int kc = 0; kc < 2; kc++)
#pragma unroll
        for (int kh = 0; kh < 2; kh++)
#pragma unroll
            for (int h = 0; h < 2; h++) {
                int k = kc * 16 + kh * 8 + four * 2 + h;
                int t = k / 3, c = k - 3 * t;
                int shift = (t / 3 - 1) * WP + (t % 3 - 1);
                rel[kc * 4 + kh * 2 + h] = shift * 3 + c;
            }

    const float* Pimg = (float*)(smem + OFF_P) + 96 * 3;
    float* rawp = (float*)(smem + OFF_RAW);

    float ps[8][2], qs[8][2];
#pragma unroll
    for (int nt = 0; nt < 8; nt++) { ps[nt][0]=0.f; ps[nt][1]=0.f; qs[nt][0]=0.f; qs[nt][1]=0.f; }

    for (int yp = 0; yp < 42; yp++) {
        int s0 = (2 * yp + 1) * WP;
        float d[2][8][4];
#pragma unroll
        for (int im = 0; im < 2; im++)
#pragma unroll
            for (int nt = 0; nt < 8; nt++)
#pragma unroll
                for (int i = 0; i < 4; i++) d[im][nt][i] = 0.f;

#pragma unroll
        for (int kc = 0; kc < 2; kc++)
#pragma unroll
            for (int im = 0; im < 2; im++) {
                if (im >= nmt) break;
                int mt = im ? (8 + warp) : warp;
                uint32_t ah[4], al[4];
#pragma unroll
                for (int r = 0; r < 4; r++) {
                    int row = mt * 16 + g_row + (r & 1) * 8;
                    int base = (s0 + row) * 3;
                    int kh = r >> 1;
                    float v0 = Pimg[base + rel[kc * 4 + kh * 2 + 0]];
                    float v1 = Pimg[base + rel[kc * 4 + kh * 2 + 1]];
                    __half h0 = __float2half_rn(v0), h1 = __float2half_rn(v1);
                    __half l0 = __float2half_rn(v0 - __half2float(h0));
                    __half l1 = __float2half_rn(v1 - __half2float(h1));
                    ah[r] = packh2(h0, h1);
                    al[r] = packh2(l0, l1);
                }
#pragma unroll
                for (int nt = 0; nt < 8; nt++) {
                    const char* bp = smem + OFF_B + (nt * 8 + g_row) * AR + kc * 32 + four * 4;
                    uint32_t b0 = *(const uint32_t*)bp;
                    uint32_t b1 = *(const uint32_t*)(bp + 16);
                    mma16816(d[im][nt], ah[0], ah[1], ah[2], ah[3], b0, b1);
                    mma16816(d[im][nt], al[0], al[1], al[2], al[3], b0, b1);
                }
            }

        // ---- raw to smem + fused stats ----
#pragma unroll
        for (int im = 0; im < 2; im++) {
            if (im >= nmt) break;
            int mt = im ? (8 + warp) : warp;
#pragma unroll
            for (int rr = 0; rr < 2; rr++) {
                int m = mt * 16 + g_row + rr * 8;
                bool stat = false;
                if (m < 172) {
                    int px = (m >= WP) ? (m - WP) : m;
                    stat = (px >= 1 && px <= 84);
                }
#pragma unroll
                for (int nt = 0; nt < 8; nt++) {
                    int oc = nt * 8 + four * 2;
                    float vx = d[im][nt][rr * 2]     + bias_sh[oc];
                    float vy = d[im][nt][rr * 2 + 1] + bias_sh[oc + 1];
                    *(float2*)(rawp + m * 64 + oc) = make_float2(vx, vy);
                    if (stat) {
                        ps[nt][0] += vx; qs[nt][0] += vx * vx;
                        ps[nt][1] += vy; qs[nt][1] += vy * vy;
                    }
                }
            }
        }
        __syncthreads();
        // ---- pool 2x2 -> pool1 channels-last ----
        for (int i = tid; i < 42 * 64; i += 256) {
            int ox = i >> 6, c = i & 63;
            int m0 = 2 * ox + 1;
            float v = fmaxf(fmaxf(rawp[m0 * 64 + c], rawp[(m0 + 1) * 64 + c]),
                            fmaxf(rawp[(m0 + WP) * 64 + c], rawp[(m0 + WP + 1) * 64 + c]));
            pool1[((size_t)g * 1764 + yp * 42 + ox) * 64 + c] = v;
        }
        __syncthreads();
    }

    // ---- stats reduction -> part[g][128] ----
#pragma unroll
    for (int nt = 0; nt < 8; nt++)
#pragma unroll
        for (int j = 0; j < 2; j++) {
#pragma unroll
            for (int off = 16; off >= 4; off >>= 1) {
                ps[nt][j] += __shfl_down_sync(~0u, ps[nt][j], off);
                qs[nt][j] += __shfl_down_sync(~0u, qs[nt][j], off);
            }
        }
    float* wst = rawp;
    if (lane < 4) {
#pragma unroll
        for (int nt = 0; nt < 8; nt++)
#pragma unroll
            for (int j = 0; j < 2; j++) {
                int oc = nt * 8 + lane * 2 + j;
                wst[warp * 128 + oc]      = ps[nt][j];
                wst[warp * 128 + 64 + oc] = qs[nt][j];
            }
    }
    __syncthreads();
    if (tid < 128) {
        float s = 0.f;
#pragma unroll
        for (int wi = 0; wi < 8; wi++) s += wst[wi * 128 + tid];
        part[(size_t)g * 128 + tid] = s;
    }
}

// ================= mmaconv: layers 2-4 (unchanged from R9) =================
template <int NX, int NT>
__global__ void __launch_bounds__(256) mmaconv_kernel(
    const float* __restrict__ in, const float* __restrict__ abp,
    const float* __restrict__ w, const float* __restrict__ bias,
    float* __restrict__ raw, float* __restrict__ part)
{
    constexpr int W = NX + 2, P = W * W, PIX = NX * NX;
    constexpr int ROWS = 2 * W + 260;
    constexpr int SROW = 144;
    constexpr int BTAP = 64 * SROW;
    constexpr int OFF_B  = 1024;
    constexpr int OFF_SH = OFF_B + 9 * BTAP;
    constexpr int OFF_SL = OFF_SH + ROWS * SROW;

    extern __shared__ __align__(16) char smem[];
    int tid = threadIdx.x;
    int g = blockIdx.x, slot = g >> 5;
    float* bias_sh = (float*)(smem + 16);
    float* ab_sh   = (float*)(smem + 304);
    if (tid < 64) bias_sh[tid] = bias[tid];
    if (tid < 128) ab_sh[tid] = abp[slot * 128 + tid];

    for (int i = tid; i < 9 * 64 * 64; i += 256) {
        int t = i >> 12, r = i & 4095, ci = r >> 6, oc = r & 63;
        *(__half*)(smem + OFF_B + (t * 64 + oc) * SROW + ci * 2) = __float2half_rn(w[i]);
    }

    int warp = tid >> 5, lane = tid & 31;
    int g_row = lane >> 2, four = lane & 3;
    int mbase = warp * 32;

    float ps[8][2], qs[8][2];
#pragma unroll
    for (int nt = 0; nt < 8; nt++) { ps[nt][0]=0.f; ps[nt][1]=0.f; qs[nt][0]=0.f; qs[nt][1]=0.f; }

    for (int tile = 0; tile < NT; tile++) {
        int s0 = tile * 256;
        __syncthreads();
        for (int i = tid; i < ROWS * 16; i += 256) {
            int r = i >> 4, c4 = (i & 15) * 4;
            int sp = s0 - W - 1 + r;
            float4 v = make_float4(0.f, 0.f, 0.f, 0.f);
            if (sp >= 0 && sp < P) {
                int py = sp / W, px = sp - py * W;
                if (px >= 1 && px <= NX && py >= 1 && py <= NX) {
                    float4 rv = *(const float4*)&in[((size_t)g * PIX + (py - 1) * NX + (px - 1)) * 64 + c4];
                    v.x = fmaxf(fmaf(ab_sh[(c4 + 0) * 2], rv.x, ab_sh[(c4 + 0) * 2 + 1]), 0.f);
                    v.y = fmaxf(fmaf(ab_sh[(c4 + 1) * 2], rv.y, ab_sh[(c4 + 1) * 2 + 1]), 0.f);
                    v.z = fmaxf(fmaf(ab_sh[(c4 + 2) * 2], rv.z, ab_sh[(c4 + 2) * 2 + 1]), 0.f);
                    v.w = fmaxf(fmaf(ab_sh[(c4 + 3) * 2], rv.w, ab_sh[(c4 + 3) * 2 + 1]), 0.f);
                }
            }
            __half hx = __float2half_rn(v.x), hy = __float2half_rn(v.y);
            __half hz = __float2half_rn(v.z), hw = __float2half_rn(v.w);
            __half lx = __float2half_rn(v.x - __half2float(hx));
            __half ly = __float2half_rn(v.y - __half2float(hy));
            __half lz = __float2half_rn(v.z - __half2float(hz));
            __half lw = __float2half_rn(v.w - __half2float(hw));
            __half2 h01 = __halves2half2(hx, hy), h23 = __halves2half2(hz, hw);
            __half2 l01 = __halves2half2(lx, ly), l23 = __halves2half2(lz, lw);
            *(uint2*)(smem + OFF_SH + r * SROW + c4 * 2) =
                make_uint2(*(uint32_t*)&h01, *(uint32_t*)&h23);
            *(uint2*)(smem + OFF_SL + r * SROW + c4 * 2) =
                make_uint2(*(uint32_t*)&l01, *(uint32_t*)&l23);
        }
        __syncthreads();

        float d[2][8][4];
#pragma unroll
        for (int mt = 0; mt < 2; mt++)
#pragma unroll
            for (int nt = 0; nt < 8; nt++)
#pragma unroll
                for (int i = 0; i < 4; i++) d[mt][nt][i] = 0.f;

#pragma unroll 1
        for (int pass = 0; pass < 2; pass++) {
            const char* abase = smem + (pass ? OFF_SL : OFF_SH);
#pragma unroll 1
            for (int t = 0; t < 9; t++) {
                int rshift = (t / 3) * W + (t % 3);
                const char* bt = smem + OFF_B + t * BTAP;
#pragma unroll
                for (int kc = 0; kc < 4; kc++) {
                    int cb = kc * 32 + four * 4;
                    uint32_t a[2][4];
#pragma unroll
                    for (int mt = 0; mt < 2; mt++) {
                        const char* ap = abase + (mbase + mt * 16 + rshift + g_row) * SROW + cb;
                        a[mt][0] = *(const uint32_t*)ap;
                        a[mt][1] = *(const uint32_t*)(ap + 8 * SROW);
                        a[mt][2] = *(const uint32_t*)(ap + 16);
                        a[mt][3] = *(const uint32_t*)(ap + 8 * SROW + 16);
                    }
#pragma unroll
                    for (int nt = 0; nt < 8; nt++) {
                        const char* bp = bt + (nt * 8 + g_row) * SROW + cb;
                        uint32_t b0 = *(const uint32_t*)bp;
                        uint32_t b1 = *(const uint32_t*)(bp + 16);
                        mma16816(d[0][nt], a[0][0], a[0][1], a[0][2], a[0][3], b0, b1);
                        mma16816(d[1][nt], a[1][0], a[1][1], a[1][2], a[1][3], b0, b1);
                    }
                }
            }
        }

#pragma unroll
        for (int mt = 0; mt < 2; mt++)
#pragma unroll
            for (int rr = 0; rr < 2; rr++) {
                int m = mbase + mt * 16 + g_row + rr * 8;
                int sp = s0 + m;
                bool ok = false;
                float* o = 0;
                if (sp < P) {
                    int py = sp / W, px = sp - py * W;
                    if (px >= 1 && px <= NX && py >= 1 && py <= NX) {
                        ok = true;
                        o = raw + ((size_t)g * PIX + (py - 1) * NX + (px - 1)) * 64;
                    }
                }
#pragma unroll
                for (int nt = 0; nt < 8; nt++) {
                    int oc = nt * 8 + four * 2;
                    float vx = d[mt][nt][rr * 2]     + bias_sh[oc];
                    float vy = d[mt][nt][rr * 2 + 1] + bias_sh[oc + 1];
                    if (ok) {
                        *(float2*)(o + oc) = make_float2(vx, vy);
                        ps[nt][0] += vx; qs[nt][0] += vx * vx;
                        ps[nt][1] += vy; qs[nt][1] += vy * vy;
                    }
                }
            }
    }

#pragma unroll
    for (int nt = 0; nt < 8; nt++)
#pragma unroll
        for (int j = 0; j < 2; j++) {
#pragma unroll
            for (int off = 16; off >= 4; off >>= 1) {
                ps[nt][j] += __shfl_down_sync(~0u, ps[nt][j], off);
                qs[nt][j] += __shfl_down_sync(~0u, qs[nt][j], off);
            }
        }
    __syncthreads();
    float* wst = (float*)(smem + OFF_SH);
    if (lane < 4) {
#pragma unroll
        for (int nt = 0; nt < 8; nt++)
#pragma unroll
            for (int j = 0; j < 2; j++) {
                int oc = nt * 8 + lane * 2 + j;
                wst[warp * 128 + oc]      = ps[nt][j];
                wst[warp * 128 + 64 + oc] = qs[nt][j];
            }
    }
    __syncthreads();
    if (tid < 128) {
        float s = 0.f;
#pragma unroll
        for (int wi = 0; wi < 8; wi++) s += wst[wi * 128 + tid];
        part[(size_t)g * 128 + tid] = s;
    }
}

// ---------------- per-slot BN affine from per-image partials [g][128] ----------------
__global__ void __launch_bounds__(64) abfin2_kernel(const float* __restrict__ part,
    const float* __restrict__ gamma, const float* __restrict__ beta,
    float* __restrict__ ab, float invCnt)
{
    int slot = blockIdx.x, c = threadIdx.x;
    float s = 0.f, q = 0.f;
    for (int b = 0; b < 32; b++) {
        s += part[(size_t)(slot * 32 + b) * 128 + c];
        q += part[(size_t)(slot * 32 + b) * 128 + 64 + c];
    }
    float mn = s * invCnt;
    float var = q * invCnt - mn * mn;
    float sc = gamma[c] * rsqrtf(var + 1e-3f);
    ab[(slot * 64 + c) * 2] = sc;
    ab[(slot * 64 + c) * 2 + 1] = beta[c] - mn * sc;
}

// ---------------- 2x2 maxpool on channels-last raw (pre-BN, exact) ----------------
template <int NX>
__global__ void __launch_bounds__(256) poolCL_kernel(const float* __restrict__ raw,
                                                    float* __restrict__ out)
{
    constexpr int Np = NX / 2;
    long idx = (long)blockIdx.x * 256 + threadIdx.x;
    if (idx >= (long)NIMG * Np * Np * 64) return;
    int c = (int)(idx & 63); long t = idx >> 6;
    int ox = (int)(t % Np); t /= Np;
    int oy = (int)(t % Np); int g = (int)(t / Np);
    const float* p = raw + ((size_t)g * NX * NX + (2 * oy) * NX + 2 * ox) * 64 + c;
    float v = fmaxf(fmaxf(p[0], p[64]), fmaxf(p[(size_t)NX * 64], p[(size_t)NX * 64 + 64]));
    out[idx] = v;
}

// ---------------- gemmz ----------------
__global__ void __launch_bounds__(256) gemmz_kernel(
    const float* __restrict__ emb, const float* __restrict__ abp,
    const float* __restrict__ fk, const float* __restrict__ fb,
    const float* __restrict__ bk, const float* __restrict__ bb,
    float* __restrict__ Z)
{
    int gb = blockIdx.x, dir = blockIdx.y;
    const float* W = dir ? bk : fk;
    const float* bias = dir ? bb : fb;
    float* Zo = Z + (size_t)dir * NIMG * 128;
    __shared__ float A_sh[32][33];
    __shared__ __align__(16) float B_sh[32][128];
    int tid = threadIdx.x, jj = tid & 31, gg = tid >> 5;
    float acc[4][4] = {};
    for (int d0 = 0; d0 < 1600; d0 += 32) {
        for (int i = tid; i < 1024; i += 256) {
            int r = i >> 5, dd = i & 31, d = d0 + dd, c = d & 63;
            float raw = emb[(size_t)(gb * 32 + r) * 1600 + d];
            A_sh[r][dd] = fmaxf(fmaf(abp[(gb * 64 + c) * 2], raw, abp[(gb * 64 + c) * 2 + 1]), 0.f);
        }
        for (int i = tid; i < 4096; i += 256)
            B_sh[i >> 7][i & 127] = W[(size_t)(d0 + (i >> 7)) * 128 + (i & 127)];
        __syncthreads();
#pragma unroll
        for (int dd = 0; dd < 32; dd++) {
            float4 bv = *(const float4*)&B_sh[dd][jj * 4];
#pragma unroll
            for (int r = 0; r < 4; r++) {
                float a = A_sh[gg * 4 + r][dd];
                acc[r][0] += a * bv.x; acc[r][1] += a * bv.y;
                acc[r][2] += a * bv.z; acc[r][3] += a * bv.w;
            }
        }
        __syncthreads();
    }
#pragma unroll
    for (int r = 0; r < 4; r++)
#pragma unroll
        for (int c = 0; c < 4; c++)
            Zo[(size_t)(gb * 32 + gg * 4 + r) * 128 + jj * 4 + c] = acc[r][c] + bias[jj * 4 + c];
}

// ---------------- LSTM ----------------
__global__ void __launch_bounds__(672) lstm_kernel(
    const float* __restrict__ Z,
    const float* __restrict__ fr, const float* __restrict__ br,
    float* __restrict__ outs)
{
    int q = blockIdx.x, dir = blockIdx.y;
    const float* R = dir ? br : fr;
    const float* Zp = Z + (size_t)dir * NIMG * 128;
    __shared__ float Wh[32][128];
    __shared__ float h_sh[21][32], c_sh[21][32];
    int tid = threadIdx.x;
    for (int i = tid; i < 4096; i += 672) Wh[i >> 7][i & 127] = R[i];
    int p = tid >> 5, j = tid & 31;
    h_sh[p][j] = 0.f; c_sh[p][j] = 0.f;
    __syncthreads();
    int slot = (p < 20) ? p : (20 + q);
    for (int step = 0; step < 32; step++) {
        int t = dir ? (31 - step) : step;
        const float* zr = Zp + (size_t)(slot * 32 + t) * 128;
        float z0 = zr[j], z1 = zr[32 + j], z2 = zr[64 + j], z3 = zr[96 + j];
#pragma unroll
        for (int k = 0; k < 32; k++) {
            float hk = h_sh[p][k];
            z0 += hk * Wh[k][j]; z1 += hk * Wh[k][32 + j];
            z2 += hk * Wh[k][64 + j]; z3 += hk * Wh[k][96 + j];
        }
        float ig = 1.f / (1.f + expf(-z0)), fg = 1.f / (1.f + expf(-z1));
        float gg = tanhf(z2), og = 1.f / (1.f + expf(-z3));
        float cn = fg * c_sh[p][j] + ig * gg;
        float hn = og * tanhf(cn);
        __syncthreads();
        h_sh[p][j] = hn; c_sh[p][j] = cn;
        outs[(size_t)((q * 21 + p) * 32 + t) * 64 + dir * 32 + j] = hn;
        __syncthreads();
    }
}

// ---------------- attention + CE + acc ----------------
__global__ void __launch_bounds__(256) final_kernel(
    const float* __restrict__ outs,
    const int* __restrict__ ysup, const int* __restrict__ yqry,
    float* __restrict__ out)
{
    __shared__ float ce_sh[160], eq_sh[160];
    int tid = threadIdx.x;
    if (tid < 160) {
        int q = tid / 32, b = tid % 32;
        const float* qry = outs + (size_t)((q * 21 + 20) * 32 + b) * 64;
        float logit[20];
        for (int s = 0; s < 20; s++) {
            const float* sp = outs + (size_t)((q * 21 + s) * 32 + b) * 64;
            float d = 0.f, n2 = 0.f;
            for (int k = 0; k < 64; k++) { d += qry[k] * sp[k]; n2 += sp[k] * sp[k]; }
            logit[s] = d * rsqrtf(fmaxf(n2, 1e-10f));
        }
        float mx = logit[0];
        for (int s = 1; s < 20; s++) mx = fmaxf(mx, logit[s]);
        float den = 0.f;
        for (int s = 0; s < 20; s++) { logit[s] = expf(logit[s] - mx); den += logit[s]; }
        float invden = 1.f / den;
        float preds[20];
        for (int wq = 0; wq < 20; wq++) preds[wq] = 0.f;
        for (int s = 0; s < 20; s++) preds[ysup[b * 20 + s]] += logit[s] * invden;
        int yq = yqry[b * 5 + q];
        float pv = fminf(fmaxf(preds[yq], 1e-7f), 1.f - 1e-7f);
        ce_sh[tid] = -logf(pv);
        int best = 0;
        for (int wq = 1; wq < 20; wq++) if (preds[wq] > preds[best]) best = wq;
        eq_sh[tid] = (best == yq) ? 1.f : 0.f;
    }
    __syncthreads();
    if (tid < 32) {
        float s = 0.f;
        for (int q = 0; q < 5; q++) s += ce_sh[q * 32 + tid];
        out[tid] = s * 0.2f;
    }
    if (tid == 0) {
        float s = 0.f;
        for (int i = 0; i < 160; i++) s += eq_sh[i];
        out[32] = s / 160.f;
    }
}

// ---------------- launch ----------------
extern "C" void kernel_launch(void* const* d_in, const int* in_sizes, int n_in,
                              void* d_out, int out_size)
{
    (void)in_sizes; (void)n_in; (void)out_size;
    const float* xs = (const float*)d_in[0];
    const int* ysup = (const int*)d_in[1];
    const float* xq = (const float*)d_in[2];
    const int* yqry = (const int*)d_in[3];
    const float *k1=(const float*)d_in[4],  *b1=(const float*)d_in[5],  *g1=(const float*)d_in[6],  *be1=(const float*)d_in[7];
    const float *k2=(const float*)d_in[8],  *b2=(const float*)d_in[9],  *g2=(const float*)d_in[10], *be2=(const float*)d_in[11];
    const float *k3=(const float*)d_in[12], *b3=(const float*)d_in[13], *g3=(const float*)d_in[14], *be3=(const float*)d_in[15];
    const float *k4=(const float*)d_in[16], *b4=(const float*)d_in[17], *g4=(const float*)d_in[18], *be4=(const float*)d_in[19];
    const float *fk=(const float*)d_in[20], *fr=(const float*)d_in[21], *fb=(const float*)d_in[22];
    const float *bk=(const float*)d_in[23], *br=(const float*)d_in[24], *bb=(const float*)d_in[25];

    float *pool1, *raw, *pool2, *pool3, *pool4, *part, *Z, *outs, *ab;
    cudaGetSymbolAddress((void**)&pool1, g_pool1);
    cudaGetSymbolAddress((void**)&raw, g_raw);
    cudaGetSymbolAddress((void**)&pool2, g_pool2);
    cudaGetSymbolAddress((void**)&pool3, g_pool3);
    cudaGetSymbolAddress((void**)&pool4, g_pool4);
    cudaGetSymbolAddress((void**)&part, g_part);
    cudaGetSymbolAddress((void**)&Z, g_Z);
    cudaGetSymbolAddress((void**)&outs, g_outs);
    cudaGetSymbolAddress((void**)&ab, g_ab);

    const int SM1  = 1024 + 7588 * 12 + 64 * 80 + 176 * 64 * 4;       // 142256
    const int SM42 = 1024 + 9 * 64 * 144 + 2 * (2 * 44 + 260) * 144;  // 184192
    const int SM21 = 1024 + 9 * 64 * 144 + 2 * (2 * 23 + 260) * 144;  // 172096
    const int SM10 = 1024 + 9 * 64 * 144 + 2 * (2 * 12 + 260) * 144;  // 165760
    cudaFuncSetAttribute(conv1mma2_kernel,     cudaFuncAttributeMaxDynamicSharedMemorySize, SM1);
    cudaFuncSetAttribute(mmaconv_kernel<42,8>, cudaFuncAttributeMaxDynamicSharedMemorySize, SM42);
    cudaFuncSetAttribute(mmaconv_kernel<21,3>, cudaFuncAttributeMaxDynamicSharedMemorySize, SM21);
    cudaFuncSetAttribute(mmaconv_kernel<10,1>, cudaFuncAttributeMaxDynamicSharedMemorySize, SM10);

    // L1: MMA conv, direct fragment gather, fused stats + pool
    conv1mma2_kernel<<<NIMG, 256, SM1>>>(xs, xq, k1, b1, pool1, part);
    abfin2_kernel<<<25, 64>>>(part, g1, be1, ab, 1.f / (32.f * 7056.f));
    // L2: mma conv on 42 (stats fused)
    mmaconv_kernel<42,8><<<NIMG, 256, SM42>>>(pool1, ab, k2, b2, raw, part);
    poolCL_kernel<42><<<(NIMG*441*64 + 255)/256, 256>>>(raw, pool2);
    abfin2_kernel<<<25, 64>>>(part, g2, be2, ab, 1.f / (32.f * 1764.f));
    // L3: mma conv on 21
    mmaconv_kernel<21,3><<<NIMG, 256, SM21>>>(pool2, ab, k3, b3, raw, part);
    poolCL_kernel<21><<<(NIMG*100*64 + 255)/256, 256>>>(raw, pool3);
    abfin2_kernel<<<25, 64>>>(part, g3, be3, ab, 1.f / (32.f * 441.f));
    // L4: mma conv on 10
    mmaconv_kernel<10,1><<<NIMG, 256, SM10>>>(pool3, ab, k4, b4, raw, part);
    poolCL_kernel<10><<<(NIMG*25*64 + 255)/256, 256>>>(raw, pool4);
    abfin2_kernel<<<25, 64>>>(part, g4, be4, ab, 1.f / (32.f * 100.f));

    gemmz_kernel<<<dim3(25, 2), 256>>>(pool4, ab, fk, fb, bk, bb, Z);
    lstm_kernel<<<dim3(5, 2), 672>>>(Z, fr, br, outs);
    final_kernel<<<1, 256>>>(outs, ysup, yqry, (float*)d_out);
}

// round 12
// speedup vs baseline: 1.0829x; 1.0033x over previous
#include <cuda_runtime.h>
#include <cuda_fp16.h>
#include <math.h>
#include <stdint.h>

#define NIMG 800
typedef unsigned long long u64;

// ---------------- scratch ----------------
__device__ float g_pool1[(size_t)NIMG * 1764 * 64];
__device__ float g_raw  [(size_t)NIMG * 1764 * 64];
__device__ float g_pool2[(size_t)NIMG * 441 * 64];
__device__ float g_pool3[(size_t)NIMG * 100 * 64];
__device__ float g_pool4[(size_t)NIMG * 25 * 64];
__device__ float g_part [(size_t)NIMG * 128];
__device__ float g_Z[2 * NIMG * 128];
__device__ float g_outs[5 * 21 * 32 * 64];
__device__ float g_ab[25 * 64 * 2];

// ---------------- warp mma (fp16 in, f32 acc) ----------------
__device__ __forceinline__ void mma16816(float* d, uint32_t a0, uint32_t a1,
                                         uint32_t a2, uint32_t a3,
                                         uint32_t b0, uint32_t b1) {
    asm volatile(
        "mma.sync.aligned.m16n8k16.row.col.f32.f16.f16.f32 "
        "{%0,%1,%2,%3}, {%4,%5,%6,%7}, {%8,%9}, {%0,%1,%2,%3};"
        : "+f"(d[0]), "+f"(d[1]), "+f"(d[2]), "+f"(d[3])
        : "r"(a0), "r"(a1), "r"(a2), "r"(a3), "r"(b0), "r"(b1));
}
__device__ __forceinline__ uint32_t packh2(__half a, __half b) {
    __half2 h = __halves2half2(a, b);
    return *(uint32_t*)&h;
}

// ================= conv1mma2: layer 1, direct fragment gather (unchanged R11) =================
__global__ void __launch_bounds__(256) conv1mma2_kernel(
    const float* __restrict__ xs, const float* __restrict__ xq,
    const float* __restrict__ w, const float* __restrict__ bias,
    float* __restrict__ pool1, float* __restrict__ part)
{
    constexpr int WP = 86, P = WP * WP;
    constexpr int PENT = 96 + P + 96;
    constexpr int AR = 80;
    constexpr int OFF_P   = 1024;
    constexpr int OFF_B   = OFF_P + PENT * 12;
    constexpr int OFF_RAW = OFF_B + 64 * AR;

    extern __shared__ __align__(16) char smem[];
    int tid = threadIdx.x;
    int g = blockIdx.x;
    float* bias_sh = (float*)(smem + 16);
    if (tid < 64) bias_sh[tid] = bias[tid];

    {
        int b = g & 31, slot = g >> 5;
        const float* src = (slot < 20)
            ? (xs + (size_t)(b * 20 + slot) * 84 * 84 * 3)
            : (xq + (size_t)(b * 5 + (slot - 20)) * 84 * 84 * 3);
        float* Pp = (float*)(smem + OFF_P);
        for (int i = tid; i < PENT * 3; i += 256) {
            int sp = i / 3 - 96;
            int c = i - (sp + 96) * 3;
            float v = 0.f;
            if (sp >= 0 && sp < P) {
                int py = sp / WP, px = sp - py * WP;
                if (px >= 1 && px <= 84 && py >= 1 && py <= 84)
                    v = src[(size_t)((py - 1) * 84 + (px - 1)) * 3 + c];
            }
            Pp[i] = v;
        }
    }
    for (int i = tid; i < 64 * 32; i += 256) {
        int oc = i >> 5, k = i & 31;
        float v = (k < 27) ? w[k * 64 + oc] : 0.f;
        *(__half*)(smem + OFF_B + oc * AR + k * 2) = __float2half_rn(v);
    }
    __syncthreads();

    int warp = tid >> 5, lane = tid & 31;
    int g_row = lane >> 2, four = lane & 3;
    int nmt = (warp < 3) ? 2 : 1;

    int rel[8];
#pragma unroll
    for (int kc = 0; kc < 2; kc++)
#pragma unroll
        for (int kh = 0; kh < 2; kh++)
#pragma unroll
            for (int h = 0; h < 2; h++) {
                int k = kc * 16 + kh * 8 + four * 2 + h;
                int t = k / 3, c = k - 3 * t;
                int shift = (t / 3 - 1) * WP + (t % 3 - 1);
                rel[kc * 4 + kh * 2 + h] = shift * 3 + c;
            }

    const float* Pimg = (float*)(smem + OFF_P) + 96 * 3;
    float* rawp = (float*)(smem + OFF_RAW);

    float ps[8][2], qs[8][2];
#pragma unroll
    for (int nt = 0; nt < 8; nt++) { ps[nt][0]=0.f; ps[nt][1]=0.f; qs[nt][0]=0.f; qs[nt][1]=0.f; }

    for (int yp = 0; yp < 42; yp++) {
        int s0 = (2 * yp + 1) * WP;
        float d[2][8][4];
#pragma unroll
        for (int im = 0; im < 2; im++)
#pragma unroll
            for (int nt = 0; nt < 8; nt++)
#pragma unroll
                for (int i = 0; i < 4; i++) d[im][nt][i] = 0.f;

#pragma unroll
        for (int kc = 0; kc < 2; kc++)
#pragma unroll
            for (int im = 0; im < 2; im++) {
                if (im >= nmt) break;
                int mt = im ? (8 + warp) : warp;
                uint32_t ah[4], al[4];
#pragma unroll
                for (int r = 0; r < 4; r++) {
                    int row = mt * 16 + g_row + (r & 1) * 8;
                    int base = (s0 + row) * 3;
                    int kh = r >> 1;
                    float v0 = Pimg[base + rel[kc * 4 + kh * 2 + 0]];
                    float v1 = Pimg[base + rel[kc * 4 + kh * 2 + 1]];
                    __half h0 = __float2half_rn(v0), h1 = __float2half_rn(v1);
                    __half l0 = __float2half_rn(v0 - __half2float(h0));
                    __half l1 = __float2half_rn(v1 - __half2float(h1));
                    ah[r] = packh2(h0, h1);
                    al[r] = packh2(l0, l1);
                }
#pragma unroll
                for (int nt = 0; nt < 8; nt++) {
                    const char* bp = smem + OFF_B + (nt * 8 + g_row) * AR + kc * 32 + four * 4;
                    uint32_t b0 = *(const uint32_t*)bp;
                    uint32_t b1 = *(const uint32_t*)(bp + 16);
                    mma16816(d[im][nt], ah[0], ah[1], ah[2], ah[3], b0, b1);
                    mma16816(d[im][nt], al[0], al[1], al[2], al[3], b0, b1);
                }
            }

#pragma unroll
        for (int im = 0; im < 2; im++) {
            if (im >= nmt) break;
            int mt = im ? (8 + warp) : warp;
#pragma unroll
            for (int rr = 0; rr < 2; rr++) {
                int m = mt * 16 + g_row + rr * 8;
                bool stat = false;
                if (m < 172) {
                    int px = (m >= WP) ? (m - WP) : m;
                    stat = (px >= 1 && px <= 84);
                }
#pragma unroll
                for (int nt = 0; nt < 8; nt++) {
                    int oc = nt * 8 + four * 2;
                    float vx = d[im][nt][rr * 2]     + bias_sh[oc];
                    float vy = d[im][nt][rr * 2 + 1] + bias_sh[oc + 1];
                    *(float2*)(rawp + m * 64 + oc) = make_float2(vx, vy);
                    if (stat) {
                        ps[nt][0] += vx; qs[nt][0] += vx * vx;
                        ps[nt][1] += vy; qs[nt][1] += vy * vy;
                    }
                }
            }
        }
        __syncthreads();
        for (int i = tid; i < 42 * 64; i += 256) {
            int ox = i >> 6, c = i & 63;
            int m0 = 2 * ox + 1;
            float v = fmaxf(fmaxf(rawp[m0 * 64 + c], rawp[(m0 + 1) * 64 + c]),
                            fmaxf(rawp[(m0 + WP) * 64 + c], rawp[(m0 + WP + 1) * 64 + c]));
            pool1[((size_t)g * 1764 + yp * 42 + ox) * 64 + c] = v;
        }
        __syncthreads();
    }

#pragma unroll
    for (int nt = 0; nt < 8; nt++)
#pragma unroll
        for (int j = 0; j < 2; j++) {
#pragma unroll
            for (int off = 16; off >= 4; off >>= 1) {
                ps[nt][j] += __shfl_down_sync(~0u, ps[nt][j], off);
                qs[nt][j] += __shfl_down_sync(~0u, qs[nt][j], off);
            }
        }
    float* wst = rawp;
    if (lane < 4) {
#pragma unroll
        for (int nt = 0; nt < 8; nt++)
#pragma unroll
            for (int j = 0; j < 2; j++) {
                int oc = nt * 8 + lane * 2 + j;
                wst[warp * 128 + oc]      = ps[nt][j];
                wst[warp * 128 + 64 + oc] = qs[nt][j];
            }
    }
    __syncthreads();
    if (tid < 128) {
        float s = 0.f;
#pragma unroll
        for (int wi = 0; wi < 8; wi++) s += wst[wi * 128 + tid];
        part[(size_t)g * 128 + tid] = s;
    }
}

// ================= mmaconv: layers 2-4, VALID-ROW PACKED tiles =================
// M-dim = valid output pixels m in [0, NX*NX). A fragments gathered from staged
// padded strip at stripr(m) = (m-s0) + 2*(m/NX - s0/NX), + tap shift.
template <int NX, int NT>
__global__ void __launch_bounds__(256) mmaconv_kernel(
    const float* __restrict__ in, const float* __restrict__ abp,
    const float* __restrict__ w, const float* __restrict__ bias,
    float* __restrict__ raw, float* __restrict__ part)
{
    constexpr int W = NX + 2, P = W * W, PIX = NX * NX;
    constexpr int ROWS = 256 + 512 / NX + 2 * W + 8;
    constexpr int SROW = 144;
    constexpr int BTAP = 64 * SROW;
    constexpr int OFF_B  = 1024;
    constexpr int OFF_SH = OFF_B + 9 * BTAP;
    constexpr int OFF_SL = OFF_SH + ROWS * SROW;

    extern __shared__ __align__(16) char smem[];
    int tid = threadIdx.x;
    int g = blockIdx.x, slot = g >> 5;
    float* bias_sh = (float*)(smem + 16);
    float* ab_sh   = (float*)(smem + 304);
    if (tid < 64) bias_sh[tid] = bias[tid];
    if (tid < 128) ab_sh[tid] = abp[slot * 128 + tid];

    for (int i = tid; i < 9 * 64 * 64; i += 256) {
        int t = i >> 12, r = i & 4095, ci = r >> 6, oc = r & 63;
        *(__half*)(smem + OFF_B + (t * 64 + oc) * SROW + ci * 2) = __float2half_rn(w[i]);
    }

    int warp = tid >> 5, lane = tid & 31;
    int g_row = lane >> 2, four = lane & 3;
    int mbase = warp * 32;

    float ps[8][2], qs[8][2];
#pragma unroll
    for (int nt = 0; nt < 8; nt++) { ps[nt][0]=0.f; ps[nt][1]=0.f; qs[nt][0]=0.f; qs[nt][1]=0.f; }

    for (int tile = 0; tile < NT; tile++) {
        int s0 = tile * 256;
        int q0 = s0 / NX;
        int spbase = (q0 + 1) * W + (s0 - q0 * NX) + 1 - W - 1;  // sp(s0) - W - 1
        __syncthreads();
        // ---- stage strip: sp = spbase + r ----
        for (int i = tid; i < ROWS * 16; i += 256) {
            int r = i >> 4, c4 = (i & 15) * 4;
            int sp = spbase + r;
            float4 v = make_float4(0.f, 0.f, 0.f, 0.f);
            if (sp >= 0 && sp < P) {
                int py = sp / W, px = sp - py * W;
                if (px >= 1 && px <= NX && py >= 1 && py <= NX) {
                    float4 rv = *(const float4*)&in[((size_t)g * PIX + (py - 1) * NX + (px - 1)) * 64 + c4];
                    v.x = fmaxf(fmaf(ab_sh[(c4 + 0) * 2], rv.x, ab_sh[(c4 + 0) * 2 + 1]), 0.f);
                    v.y = fmaxf(fmaf(ab_sh[(c4 + 1) * 2], rv.y, ab_sh[(c4 + 1) * 2 + 1]), 0.f);
                    v.z = fmaxf(fmaf(ab_sh[(c4 + 2) * 2], rv.z, ab_sh[(c4 + 2) * 2 + 1]), 0.f);
                    v.w = fmaxf(fmaf(ab_sh[(c4 + 3) * 2], rv.w, ab_sh[(c4 + 3) * 2 + 1]), 0.f);
                }
            }
            __half hx = __float2half_rn(v.x), hy = __float2half_rn(v.y);
            __half hz = __float2half_rn(v.z), hw = __float2half_rn(v.w);
            __half lx = __float2half_rn(v.x - __half2float(hx));
            __half ly = __float2half_rn(v.y - __half2float(hy));
            __half lz = __float2half_rn(v.z - __half2float(hz));
            __half lw = __float2half_rn(v.w - __half2float(hw));
            __half2 h01 = __halves2half2(hx, hy), h23 = __halves2half2(hz, hw);
            __half2 l01 = __halves2half2(lx, ly), l23 = __halves2half2(lz, lw);
            *(uint2*)(smem + OFF_SH + r * SROW + c4 * 2) =
                make_uint2(*(uint32_t*)&h01, *(uint32_t*)&h23);
            *(uint2*)(smem + OFF_SL + r * SROW + c4 * 2) =
                make_uint2(*(uint32_t*)&l01, *(uint32_t*)&l23);
        }
        __syncthreads();

        // per-warp strip rows for the 4 fragment rows (2 mt x 2 halves)
        int rA[2][2];
#pragma unroll
        for (int mt = 0; mt < 2; mt++)
#pragma unroll
            for (int h = 0; h < 2; h++) {
                int m = s0 + mbase + mt * 16 + h * 8 + g_row;
                rA[mt][h] = (m - s0) + 2 * (m / NX - q0);
            }

        float d[2][8][4];
#pragma unroll
        for (int mt = 0; mt < 2; mt++)
#pragma unroll
            for (int nt = 0; nt < 8; nt++)
#pragma unroll
                for (int i = 0; i < 4; i++) d[mt][nt][i] = 0.f;

#pragma unroll 1
        for (int pass = 0; pass < 2; pass++) {
            const char* abase = smem + (pass ? OFF_SL : OFF_SH);
#pragma unroll 1
            for (int t = 0; t < 9; t++) {
                int rshift = (t / 3) * W + (t % 3);
                const char* bt = smem + OFF_B + t * BTAP;
#pragma unroll
                for (int kc = 0; kc < 4; kc++) {
                    int cb = kc * 32 + four * 4;
                    uint32_t a[2][4];
#pragma unroll
                    for (int mt = 0; mt < 2; mt++) {
                        const char* ap0 = abase + (rA[mt][0] + rshift) * SROW + cb;
                        const char* ap1 = abase + (rA[mt][1] + rshift) * SROW + cb;
                        a[mt][0] = *(const uint32_t*)ap0;
                        a[mt][1] = *(const uint32_t*)ap1;
                        a[mt][2] = *(const uint32_t*)(ap0 + 16);
                        a[mt][3] = *(const uint32_t*)(ap1 + 16);
                    }
#pragma unroll
                    for (int nt = 0; nt < 8; nt++) {
                        const char* bp = bt + (nt * 8 + g_row) * SROW + cb;
                        uint32_t b0 = *(const uint32_t*)bp;
                        uint32_t b1 = *(const uint32_t*)(bp + 16);
                        mma16816(d[0][nt], a[0][0], a[0][1], a[0][2], a[0][3], b0, b1);
                        mma16816(d[1][nt], a[1][0], a[1][1], a[1][2], a[1][3], b0, b1);
                    }
                }
            }
        }

        // ---- epilogue: m is the valid pixel index directly ----
#pragma unroll
        for (int mt = 0; mt < 2; mt++)
#pragma unroll
            for (int rr = 0; rr < 2; rr++) {
                int m = s0 + mbase + mt * 16 + g_row + rr * 8;
                if (m < PIX) {
                    float* o = raw + ((size_t)g * PIX + m) * 64;
#pragma unroll
                    for (int nt = 0; nt < 8; nt++) {
                        int oc = nt * 8 + four * 2;
                        float vx = d[mt][nt][rr * 2]     + bias_sh[oc];
                        float vy = d[mt][nt][rr * 2 + 1] + bias_sh[oc + 1];
                        *(float2*)(o + oc) = make_float2(vx, vy);
                        ps[nt][0] += vx; qs[nt][0] += vx * vx;
                        ps[nt][1] += vy; qs[nt][1] += vy * vy;
                    }
                }
            }
    }

#pragma unroll
    for (int nt = 0; nt < 8; nt++)
#pragma unroll
        for (int j = 0; j < 2; j++) {
#pragma unroll
            for (int off = 16; off >= 4; off >>= 1) {
                ps[nt][j] += __shfl_down_sync(~0u, ps[nt][j], off);
                qs[nt][j] += __shfl_down_sync(~0u, qs[nt][j], off);
            }
        }
    __syncthreads();
    float* wst = (float*)(smem + OFF_SH);
    if (lane < 4) {
#pragma unroll
        for (int nt = 0; nt < 8; nt++)
#pragma unroll
            for (int j = 0; j < 2; j++) {
                int oc = nt * 8 + lane * 2 + j;
                wst[warp * 128 + oc]      = ps[nt][j];
                wst[warp * 128 + 64 + oc] = qs[nt][j];
            }
    }
    __syncthreads();
    if (tid < 128) {
        float s = 0.f;
#pragma unroll
        for (int wi = 0; wi < 8; wi++) s += wst[wi * 128 + tid];
        part[(size_t)g * 128 + tid] = s;
    }
}

// ---------------- per-slot BN affine ----------------
__global__ void __launch_bounds__(64) abfin2_kernel(const float* __restrict__ part,
    const float* __restrict__ gamma, const float* __restrict__ beta,
    float* __restrict__ ab, float invCnt)
{
    int slot = blockIdx.x, c = threadIdx.x;
    float s = 0.f, q = 0.f;
    for (int b = 0; b < 32; b++) {
        s += part[(size_t)(slot * 32 + b) * 128 + c];
        q += part[(size_t)(slot * 32 + b) * 128 + 64 + c];
    }
    float mn = s * invCnt;
    float var = q * invCnt - mn * mn;
    float sc = gamma[c] * rsqrtf(var + 1e-3f);
    ab[(slot * 64 + c) * 2] = sc;
    ab[(slot * 64 + c) * 2 + 1] = beta[c] - mn * sc;
}

// ---------------- 2x2 maxpool on channels-last raw (valid-index layout) ----------------
template <int NX>
__global__ void __launch_bounds__(256) poolCL_kernel(const float* __restrict__ raw,
                                                    float* __restrict__ out)
{
    constexpr int Np = NX / 2;
    long idx = (long)blockIdx.x * 256 + threadIdx.x;
    if (idx >= (long)NIMG * Np * Np * 64) return;
    int c = (int)(idx & 63); long t = idx >> 6;
    int ox = (int)(t % Np); t /= Np;
    int oy = (int)(t % Np); int g = (int)(t / Np);
    const float* p = raw + ((size_t)g * NX * NX + (2 * oy) * NX + 2 * ox) * 64 + c;
    float v = fmaxf(fmaxf(p[0], p[64]), fmaxf(p[(size_t)NX * 64], p[(size_t)NX * 64 + 64]));
    out[idx] = v;
}

// ---------------- gemmz ----------------
__global__ void __launch_bounds__(256) gemmz_kernel(
    const float* __restrict__ emb, const float* __restrict__ abp,
    const float* __restrict__ fk, const float* __restrict__ fb,
    const float* __restrict__ bk, const float* __restrict__ bb,
    float* __restrict__ Z)
{
    int gb = blockIdx.x, dir = blockIdx.y;
    const float* W = dir ? bk : fk;
    const float* bias = dir ? bb : fb;
    float* Zo = Z + (size_t)dir * NIMG * 128;
    __shared__ float A_sh[32][33];
    __shared__ __align__(16) float B_sh[32][128];
    int tid = threadIdx.x, jj = tid & 31, gg = tid >> 5;
    float acc[4][4] = {};
    for (int d0 = 0; d0 < 1600; d0 += 32) {
        for (int i = tid; i < 1024; i += 256) {
            int r = i >> 5, dd = i & 31, d = d0 + dd, c = d & 63;
            float raw = emb[(size_t)(gb * 32 + r) * 1600 + d];
            A_sh[r][dd] = fmaxf(fmaf(abp[(gb * 64 + c) * 2], raw, abp[(gb * 64 + c) * 2 + 1]), 0.f);
        }
        for (int i = tid; i < 4096; i += 256)
            B_sh[i >> 7][i & 127] = W[(size_t)(d0 + (i >> 7)) * 128 + (i & 127)];
        __syncthreads();
#pragma unroll
        for (int dd = 0; dd < 32; dd++) {
            float4 bv = *(const float4*)&B_sh[dd][jj * 4];
#pragma unroll
            for (int r = 0; r < 4; r++) {
                float a = A_sh[gg * 4 + r][dd];
                acc[r][0] += a * bv.x; acc[r][1] += a * bv.y;
                acc[r][2] += a * bv.z; acc[r][3] += a * bv.w;
            }
        }
        __syncthreads();
    }
#pragma unroll
    for (int r = 0; r < 4; r++)
#pragma unroll
        for (int c = 0; c < 4; c++)
            Zo[(size_t)(gb * 32 + gg * 4 + r) * 128 + jj * 4 + c] = acc[r][c] + bias[jj * 4 + c];
}

// ---------------- LSTM ----------------
__global__ void __launch_bounds__(672) lstm_kernel(
    const float* __restrict__ Z,
    const float* __restrict__ fr, const float* __restrict__ br,
    float* __restrict__ outs)
{
    int q = blockIdx.x, dir = blockIdx.y;
    const float* R = dir ? br : fr;
    const float* Zp = Z + (size_t)dir * NIMG * 128;
    __shared__ float Wh[32][128];
    __shared__ float h_sh[21][32], c_sh[21][32];
    int tid = threadIdx.x;
    for (int i = tid; i < 4096; i += 672) Wh[i >> 7][i & 127] = R[i];
    int p = tid >> 5, j = tid & 31;
    h_sh[p][j] = 0.f; c_sh[p][j] = 0.f;
    __syncthreads();
    int slot = (p < 20) ? p : (20 + q);
    for (int step = 0; step < 32; step++) {
        int t = dir ? (31 - step) : step;
        const float* zr = Zp + (size_t)(slot * 32 + t) * 128;
        float z0 = zr[j], z1 = zr[32 + j], z2 = zr[64 + j], z3 = zr[96 + j];
#pragma unroll
        for (int k = 0; k < 32; k++) {
            float hk = h_sh[p][k];
            z0 += hk * Wh[k][j]; z1 += hk * Wh[k][32 + j];
            z2 += hk * Wh[k][64 + j]; z3 += hk * Wh[k][96 + j];
        }
        float ig = 1.f / (1.f + expf(-z0)), fg = 1.f / (1.f + expf(-z1));
        float gg = tanhf(z2), og = 1.f / (1.f + expf(-z3));
        float cn = fg * c_sh[p][j] + ig * gg;
        float hn = og * tanhf(cn);
        __syncthreads();
        h_sh[p][j] = hn; c_sh[p][j] = cn;
        outs[(size_t)((q * 21 + p) * 32 + t) * 64 + dir * 32 + j] = hn;
        __syncthreads();
    }
}

// ---------------- attention + CE + acc ----------------
__global__ void __launch_bounds__(256) final_kernel(
    const float* __restrict__ outs,
    const int* __restrict__ ysup, const int* __restrict__ yqry,
    float* __restrict__ out)
{
    __shared__ float ce_sh[160], eq_sh[160];
    int tid = threadIdx.x;
    if (tid < 160) {
        int q = tid / 32, b = tid % 32;
        const float* qry = outs + (size_t)((q * 21 + 20) * 32 + b) * 64;
        float logit[20];
        for (int s = 0; s < 20; s++) {
            const float* sp = outs + (size_t)((q * 21 + s) * 32 + b) * 64;
            float d = 0.f, n2 = 0.f;
            for (int k = 0; k < 64; k++) { d += qry[k] * sp[k]; n2 += sp[k] * sp[k]; }
            logit[s] = d * rsqrtf(fmaxf(n2, 1e-10f));
        }
        float mx = logit[0];
        for (int s = 1; s < 20; s++) mx = fmaxf(mx, logit[s]);
        float den = 0.f;
        for (int s = 0; s < 20; s++) { logit[s] = expf(logit[s] - mx); den += logit[s]; }
        float invden = 1.f / den;
        float preds[20];
        for (int wq = 0; wq < 20; wq++) preds[wq] = 0.f;
        for (int s = 0; s < 20; s++) preds[ysup[b * 20 + s]] += logit[s] * invden;
        int yq = yqry[b * 5 + q];
        float pv = fminf(fmaxf(preds[yq], 1e-7f), 1.f - 1e-7f);
        ce_sh[tid] = -logf(pv);
        int best = 0;
        for (int wq = 1; wq < 20; wq++) if (preds[wq] > preds[best]) best = wq;
        eq_sh[tid] = (best == yq) ? 1.f : 0.f;
    }
    __syncthreads();
    if (tid < 32) {
        float s = 0.f;
        for (int q = 0; q < 5; q++) s += ce_sh[q * 32 + tid];
        out[tid] = s * 0.2f;
    }
    if (tid == 0) {
        float s = 0.f;
        for (int i = 0; i < 160; i++) s += eq_sh[i];
        out[32] = s / 160.f;
    }
}

// ---------------- launch ----------------
extern "C" void kernel_launch(void* const* d_in, const int* in_sizes, int n_in,
                              void* d_out, int out_size)
{
    (void)in_sizes; (void)n_in; (void)out_size;
    const float* xs = (const float*)d_in[0];
    const int* ysup = (const int*)d_in[1];
    const float* xq = (const float*)d_in[2];
    const int* yqry = (const int*)d_in[3];
    const float *k1=(const float*)d_in[4],  *b1=(const float*)d_in[5],  *g1=(const float*)d_in[6],  *be1=(const float*)d_in[7];
    const float *k2=(const float*)d_in[8],  *b2=(const float*)d_in[9],  *g2=(const float*)d_in[10], *be2=(const float*)d_in[11];
    const float *k3=(const float*)d_in[12], *b3=(const float*)d_in[13], *g3=(const float*)d_in[14], *be3=(const float*)d_in[15];
    const float *k4=(const float*)d_in[16], *b4=(const float*)d_in[17], *g4=(const float*)d_in[18], *be4=(const float*)d_in[19];
    const float *fk=(const float*)d_in[20], *fr=(const float*)d_in[21], *fb=(const float*)d_in[22];
    const float *bk=(const float*)d_in[23], *br=(const float*)d_in[24], *bb=(const float*)d_in[25];

    float *pool1, *raw, *pool2, *pool3, *pool4, *part, *Z, *outs, *ab;
    cudaGetSymbolAddress((void**)&pool1, g_pool1);
    cudaGetSymbolAddress((void**)&raw, g_raw);
    cudaGetSymbolAddress((void**)&pool2, g_pool2);
    cudaGetSymbolAddress((void**)&pool3, g_pool3);
    cudaGetSymbolAddress((void**)&pool4, g_pool4);
    cudaGetSymbolAddress((void**)&part, g_part);
    cudaGetSymbolAddress((void**)&Z, g_Z);
    cudaGetSymbolAddress((void**)&outs, g_outs);
    cudaGetSymbolAddress((void**)&ab, g_ab);

    const int SM1  = 1024 + 7588 * 12 + 64 * 80 + 176 * 64 * 4;               // 142256
    const int SM42 = 1024 + 9 * 64 * 144 + 2 * (256 + 512/42 + 2*44 + 8) * 144;  // 188800
    const int SM21 = 1024 + 9 * 64 * 144 + 2 * (256 + 512/21 + 2*23 + 8) * 144;  // 180160
    const int SM10 = 1024 + 9 * 64 * 144 + 2 * (256 + 512/10 + 2*12 + 8) * 144;  // 181600
    cudaFuncSetAttribute(conv1mma2_kernel,     cudaFuncAttributeMaxDynamicSharedMemorySize, SM1);
    cudaFuncSetAttribute(mmaconv_kernel<42,7>, cudaFuncAttributeMaxDynamicSharedMemorySize, SM42);
    cudaFuncSetAttribute(mmaconv_kernel<21,2>, cudaFuncAttributeMaxDynamicSharedMemorySize, SM21);
    cudaFuncSetAttribute(mmaconv_kernel<10,1>, cudaFuncAttributeMaxDynamicSharedMemorySize, SM10);

    // L1: MMA conv, direct fragment gather, fused stats + pool
    conv1mma2_kernel<<<NIMG, 256, SM1>>>(xs, xq, k1, b1, pool1, part);
    abfin2_kernel<<<25, 64>>>(part, g1, be1, ab, 1.f / (32.f * 7056.f));
    // L2: mma conv on 42 (valid-row packed, stats fused)
    mmaconv_kernel<42,7><<<NIMG, 256, SM42>>>(pool1, ab, k2, b2, raw, part);
    poolCL_kernel<42><<<(NIMG*441*64 + 255)/256, 256>>>(raw, pool2);
    abfin2_kernel<<<25, 64>>>(part, g2, be2, ab, 1.f / (32.f * 1764.f));
    // L3: mma conv on 21
    mmaconv_kernel<21,2><<<NIMG, 256, SM21>>>(pool2, ab, k3, b3, raw, part);
    poolCL_kernel<21><<<(NIMG*100*64 + 255)/256, 256>>>(raw, pool3);
    abfin2_kernel<<<25, 64>>>(part, g3, be3, ab, 1.f / (32.f * 441.f));
    // L4: mma conv on 10
    mmaconv_kernel<10,1><<<NIMG, 256, SM10>>>(pool3, ab, k4, b4, raw, part);
    poolCL_kernel<10><<<(NIMG*25*64 + 255)/256, 256>>>(raw, pool4);
    abfin2_kernel<<<25, 64>>>(part, g4, be4, ab, 1.f / (32.f * 100.f));

    gemmz_kernel<<<dim3(25, 2), 256>>>(pool4, ab, fk, fb, bk, bb, Z);
    lstm_kernel<<<dim3(5, 2), 672>>>(Z, fr, br, outs);
    final_kernel<<<1, 256>>>(outs, ysup, yqry, (float*)d_out);
}

// round 13
// speedup vs baseline: 1.1403x; 1.0530x over previous
#include <cuda_runtime.h>
#include <cuda_fp16.h>
#include <math.h>
#include <stdint.h>

#define NIMG 800
typedef unsigned long long u64;

// ---------------- scratch ----------------
__device__ float g_pool1[(size_t)NIMG * 1764 * 64];
__device__ float g_pool2[(size_t)NIMG * 441 * 64];
__device__ float g_pool3[(size_t)NIMG * 100 * 64];
__device__ float g_pool4[(size_t)NIMG * 25 * 64];
__device__ float g_part [(size_t)NIMG * 128];
__device__ float g_Z[2 * NIMG * 128];
__device__ float g_outs[5 * 21 * 32 * 64];
__device__ float g_ab[25 * 64 * 2];

// ---------------- warp mma (fp16 in, f32 acc) ----------------
__device__ __forceinline__ void mma16816(float* d, uint32_t a0, uint32_t a1,
                                         uint32_t a2, uint32_t a3,
                                         uint32_t b0, uint32_t b1) {
    asm volatile(
        "mma.sync.aligned.m16n8k16.row.col.f32.f16.f16.f32 "
        "{%0,%1,%2,%3}, {%4,%5,%6,%7}, {%8,%9}, {%0,%1,%2,%3};"
        : "+f"(d[0]), "+f"(d[1]), "+f"(d[2]), "+f"(d[3])
        : "r"(a0), "r"(a1), "r"(a2), "r"(a3), "r"(b0), "r"(b1));
}
__device__ __forceinline__ uint32_t packh2(__half a, __half b) {
    __half2 h = __halves2half2(a, b);
    return *(uint32_t*)&h;
}

// ================= conv1mma2: layer 1, direct fragment gather (validated R11) =================
__global__ void __launch_bounds__(256) conv1mma2_kernel(
    const float* __restrict__ xs, const float* __restrict__ xq,
    const float* __restrict__ w, const float* __restrict__ bias,
    float* __restrict__ pool1, float* __restrict__ part)
{
    constexpr int WP = 86, P = WP * WP;
    constexpr int PENT = 96 + P + 96;
    constexpr int AR = 80;
    constexpr int OFF_P   = 1024;
    constexpr int OFF_B   = OFF_P + PENT * 12;
    constexpr int OFF_RAW = OFF_B + 64 * AR;

    extern __shared__ __align__(16) char smem[];
    int tid = threadIdx.x;
    int g = blockIdx.x;
    float* bias_sh = (float*)(smem + 16);
    if (tid < 64) bias_sh[tid] = bias[tid];

    {
        int b = g & 31, slot = g >> 5;
        const float* src = (slot < 20)
            ? (xs + (size_t)(b * 20 + slot) * 84 * 84 * 3)
            : (xq + (size_t)(b * 5 + (slot - 20)) * 84 * 84 * 3);
        float* Pp = (float*)(smem + OFF_P);
        for (int i = tid; i < PENT * 3; i += 256) {
            int sp = i / 3 - 96;
            int c = i - (sp + 96) * 3;
            float v = 0.f;
            if (sp >= 0 && sp < P) {
                int py = sp / WP, px = sp - py * WP;
                if (px >= 1 && px <= 84 && py >= 1 && py <= 84)
                    v = src[(size_t)((py - 1) * 84 + (px - 1)) * 3 + c];
            }
            Pp[i] = v;
        }
    }
    for (int i = tid; i < 64 * 32; i += 256) {
        int oc = i >> 5, k = i & 31;
        float v = (k < 27) ? w[k * 64 + oc] : 0.f;
        *(__half*)(smem + OFF_B + oc * AR + k * 2) = __float2half_rn(v);
    }
    __syncthreads();

    int warp = tid >> 5, lane = tid & 31;
    int g_row = lane >> 2, four = lane & 3;
    int nmt = (warp < 3) ? 2 : 1;

    int rel[8];
#pragma unroll
    for (int kc = 0; kc < 2; kc++)
#pragma unroll
        for (int kh = 0; kh < 2; kh++)
#pragma unroll
            for (int h = 0; h < 2; h++) {
                int k = kc * 16 + kh * 8 + four * 2 + h;
                int t = k / 3, c = k - 3 * t;
                int shift = (t / 3 - 1) * WP + (t % 3 - 1);
                rel[kc * 4 + kh * 2 + h] = shift * 3 + c;
            }

    const float* Pimg = (float*)(smem + OFF_P) + 96 * 3;
    float* rawp = (float*)(smem + OFF_RAW);

    float ps[8][2], qs[8][2];
#pragma unroll
    for (int nt = 0; nt < 8; nt++) { ps[nt][0]=0.f; ps[nt][1]=0.f; qs[nt][0]=0.f; qs[nt][1]=0.f; }

    for (int yp = 0; yp < 42; yp++) {
        int s0 = (2 * yp + 1) * WP;
        float d[2][8][4];
#pragma unroll
        for (int im = 0; im < 2; im++)
#pragma unroll
            for (int nt = 0; nt < 8; nt++)
#pragma unroll
                for (int i = 0; i < 4; i++) d[im][nt][i] = 0.f;

#pragma unroll
        for (int kc = 0; kc < 2; kc++)
#pragma unroll
            for (int im = 0; im < 2; im++) {
                if (im >= nmt) break;
                int mt = im ? (8 + warp) : warp;
                uint32_t ah[4], al[4];
#pragma unroll
                for (int r = 0; r < 4; r++) {
                    int row = mt * 16 + g_row + (r & 1) * 8;
                    int base = (s0 + row) * 3;
                    int kh = r >> 1;
                    float v0 = Pimg[base + rel[kc * 4 + kh * 2 + 0]];
                    float v1 = Pimg[base + rel[kc * 4 + kh * 2 + 1]];
                    __half h0 = __float2half_rn(v0), h1 = __float2half_rn(v1);
                    __half l0 = __float2half_rn(v0 - __half2float(h0));
                    __half l1 = __float2half_rn(v1 - __half2float(h1));
                    ah[r] = packh2(h0, h1);
                    al[r] = packh2(l0, l1);
                }
#pragma unroll
                for (int nt = 0; nt < 8; nt++) {
                    const char* bp = smem + OFF_B + (nt * 8 + g_row) * AR + kc * 32 + four * 4;
                    uint32_t b0 = *(const uint32_t*)bp;
                    uint32_t b1 = *(const uint32_t*)(bp + 16);
                    mma16816(d[im][nt], ah[0], ah[1], ah[2], ah[3], b0, b1);
                    mma16816(d[im][nt], al[0], al[1], al[2], al[3], b0, b1);
                }
            }

#pragma unroll
        for (int im = 0; im < 2; im++) {
            if (im >= nmt) break;
            int mt = im ? (8 + warp) : warp;
#pragma unroll
            for (int rr = 0; rr < 2; rr++) {
                int m = mt * 16 + g_row + rr * 8;
                bool stat = false;
                if (m < 172) {
                    int px = (m >= WP) ? (m - WP) : m;
                    stat = (px >= 1 && px <= 84);
                }
#pragma unroll
                for (int nt = 0; nt < 8; nt++) {
                    int oc = nt * 8 + four * 2;
                    float vx = d[im][nt][rr * 2]     + bias_sh[oc];
                    float vy = d[im][nt][rr * 2 + 1] + bias_sh[oc + 1];
                    *(float2*)(rawp + m * 64 + oc) = make_float2(vx, vy);
                    if (stat) {
                        ps[nt][0] += vx; qs[nt][0] += vx * vx;
                        ps[nt][1] += vy; qs[nt][1] += vy * vy;
                    }
                }
            }
        }
        __syncthreads();
        for (int i = tid; i < 42 * 64; i += 256) {
            int ox = i >> 6, c = i & 63;
            int m0 = 2 * ox + 1;
            float v = fmaxf(fmaxf(rawp[m0 * 64 + c], rawp[(m0 + 1) * 64 + c]),
                            fmaxf(rawp[(m0 + WP) * 64 + c], rawp[(m0 + WP + 1) * 64 + c]));
            pool1[((size_t)g * 1764 + yp * 42 + ox) * 64 + c] = v;
        }
        __syncthreads();
    }

#pragma unroll
    for (int nt = 0; nt < 8; nt++)
#pragma unroll
        for (int j = 0; j < 2; j++) {
#pragma unroll
            for (int off = 16; off >= 4; off >>= 1) {
                ps[nt][j] += __shfl_down_sync(~0u, ps[nt][j], off);
                qs[nt][j] += __shfl_down_sync(~0u, qs[nt][j], off);
            }
        }
    float* wst = rawp;
    if (lane < 4) {
#pragma unroll
        for (int nt = 0; nt < 8; nt++)
#pragma unroll
            for (int j = 0; j < 2; j++) {
                int oc = nt * 8 + lane * 2 + j;
                wst[warp * 128 + oc]      = ps[nt][j];
                wst[warp * 128 + 64 + oc] = qs[nt][j];
            }
    }
    __syncthreads();
    if (tid < 128) {
        float s = 0.f;
#pragma unroll
        for (int wi = 0; wi < 8; wi++) s += wst[wi * 128 + tid];
        part[(size_t)g * 128 + tid] = s;
    }
}

// ================= mmaconv: layers 2-4, pool-row-aligned tiles, FUSED POOL =================
// Tile = TR image rows (valid-packed m). Raw tile lives only in smem (staging region,
// dead after MMA). Pool 2x2 from smem -> pooled out. Stats fused. No raw global buffer.
template <int NX, int TR, int NT>
__global__ void __launch_bounds__(256) mmaconv_kernel(
    const float* __restrict__ in, const float* __restrict__ abp,
    const float* __restrict__ w, const float* __restrict__ bias,
    float* __restrict__ pooled, float* __restrict__ part)
{
    constexpr int W = NX + 2, PIX = NX * NX, Np = NX / 2;
    constexpr int SROWS = (TR + 4) * W;
    constexpr int SROW = 144;
    constexpr int BTAP = 64 * SROW;
    constexpr int OFF_B  = 1024;
    constexpr int OFF_SH = OFF_B + 9 * BTAP;
    constexpr int OFF_SL = OFF_SH + SROWS * SROW;

    extern __shared__ __align__(16) char smem[];
    int tid = threadIdx.x;
    int g = blockIdx.x, slot = g >> 5;
    float* bias_sh = (float*)(smem + 16);
    float* ab_sh   = (float*)(smem + 304);
    if (tid < 64) bias_sh[tid] = bias[tid];
    if (tid < 128) ab_sh[tid] = abp[slot * 128 + tid];

    for (int i = tid; i < 9 * 64 * 64; i += 256) {
        int t = i >> 12, r = i & 4095, ci = r >> 6, oc = r & 63;
        *(__half*)(smem + OFF_B + (t * 64 + oc) * SROW + ci * 2) = __float2half_rn(w[i]);
    }

    int warp = tid >> 5, lane = tid & 31;
    int g_row = lane >> 2, four = lane & 3;

    float ps[8][2], qs[8][2];
#pragma unroll
    for (int nt = 0; nt < 8; nt++) { ps[nt][0]=0.f; ps[nt][1]=0.f; qs[nt][0]=0.f; qs[nt][1]=0.f; }

    float* rawp = (float*)(smem + OFF_SH);

    for (int tile = 0; tile < NT; tile++) {
        int r0 = tile * TR;
        int rows = (NX - r0 < TR) ? (NX - r0) : TR;
        int pxc = rows * NX;
        int mtiles = (pxc + 15) >> 4;
        bool v0 = warp < mtiles, v1 = warp + 8 < mtiles;

        __syncthreads();   // staging overwrite vs prev tile's pool reads
        // ---- stage strip: padded rows [r0, r0+rows+2), s = (p-r0)*W + px ----
        int nstrip = (rows + 2) * W;
        for (int i = tid; i < nstrip * 16; i += 256) {
            int s = i >> 4, c4 = (i & 15) * 4;
            int p = r0 + s / W, px = s % W;
            float4 v = make_float4(0.f, 0.f, 0.f, 0.f);
            if (px >= 1 && px <= NX && p >= 1 && p <= NX) {
                float4 rv = *(const float4*)&in[((size_t)g * PIX + (p - 1) * NX + (px - 1)) * 64 + c4];
                v.x = fmaxf(fmaf(ab_sh[(c4 + 0) * 2], rv.x, ab_sh[(c4 + 0) * 2 + 1]), 0.f);
                v.y = fmaxf(fmaf(ab_sh[(c4 + 1) * 2], rv.y, ab_sh[(c4 + 1) * 2 + 1]), 0.f);
                v.z = fmaxf(fmaf(ab_sh[(c4 + 2) * 2], rv.z, ab_sh[(c4 + 2) * 2 + 1]), 0.f);
                v.w = fmaxf(fmaf(ab_sh[(c4 + 3) * 2], rv.w, ab_sh[(c4 + 3) * 2 + 1]), 0.f);
            }
            __half hx = __float2half_rn(v.x), hy = __float2half_rn(v.y);
            __half hz = __float2half_rn(v.z), hw = __float2half_rn(v.w);
            __half lx = __float2half_rn(v.x - __half2float(hx));
            __half ly = __float2half_rn(v.y - __half2float(hy));
            __half lz = __float2half_rn(v.z - __half2float(hz));
            __half lw = __float2half_rn(v.w - __half2float(hw));
            *(uint2*)(smem + OFF_SH + s * SROW + c4 * 2) =
                make_uint2(packh2(hx, hy), packh2(hz, hw));
            *(uint2*)(smem + OFF_SL + s * SROW + c4 * 2) =
                make_uint2(packh2(lx, ly), packh2(lz, lw));
        }
        __syncthreads();

        // fragment base strip rows for valid mtiles
        int rA[2][2] = {{0, 0}, {0, 0}};
#pragma unroll
        for (int im = 0; im < 2; im++) {
            if (im == 0 ? v0 : v1) {
#pragma unroll
                for (int h = 0; h < 2; h++) {
                    int ml = (warp + im * 8) * 16 + h * 8 + g_row;
                    rA[im][h] = (ml / NX) * W + (ml % NX);
                }
            }
        }

        float d[2][8][4];
#pragma unroll
        for (int mt = 0; mt < 2; mt++)
#pragma unroll
            for (int nt = 0; nt < 8; nt++)
#pragma unroll
                for (int i = 0; i < 4; i++) d[mt][nt][i] = 0.f;

#pragma unroll 1
        for (int pass = 0; pass < 2; pass++) {
            const char* abase = smem + (pass ? OFF_SL : OFF_SH);
#pragma unroll 1
            for (int t = 0; t < 9; t++) {
                int rshift = (t / 3) * W + (t % 3);
                const char* bt = smem + OFF_B + t * BTAP;
#pragma unroll
                for (int kc = 0; kc < 4; kc++) {
                    int cb = kc * 32 + four * 4;
                    if (v0) {
                        uint32_t a0[4], a1[4];
                        {
                            const char* ap0 = abase + (rA[0][0] + rshift) * SROW + cb;
                            const char* ap1 = abase + (rA[0][1] + rshift) * SROW + cb;
                            a0[0] = *(const uint32_t*)ap0; a0[1] = *(const uint32_t*)ap1;
                            a0[2] = *(const uint32_t*)(ap0 + 16); a0[3] = *(const uint32_t*)(ap1 + 16);
                        }
                        if (v1) {
                            const char* ap0 = abase + (rA[1][0] + rshift) * SROW + cb;
                            const char* ap1 = abase + (rA[1][1] + rshift) * SROW + cb;
                            a1[0] = *(const uint32_t*)ap0; a1[1] = *(const uint32_t*)ap1;
                            a1[2] = *(const uint32_t*)(ap0 + 16); a1[3] = *(const uint32_t*)(ap1 + 16);
                        }
#pragma unroll
                        for (int nt = 0; nt < 8; nt++) {
                            const char* bp = bt + (nt * 8 + g_row) * SROW + cb;
                            uint32_t b0 = *(const uint32_t*)bp;
                            uint32_t b1 = *(const uint32_t*)(bp + 16);
                            mma16816(d[0][nt], a0[0], a0[1], a0[2], a0[3], b0, b1);
                            if (v1) mma16816(d[1][nt], a1[0], a1[1], a1[2], a1[3], b0, b1);
                        }
                    }
                }
            }
        }
        __syncthreads();   // all MMA staging reads done before raw overwrite

        // ---- raw tile -> smem (over staging) + fused stats ----
#pragma unroll
        for (int im = 0; im < 2; im++) {
            if (im == 0 ? !v0 : !v1) continue;
            int mt = warp + im * 8;
#pragma unroll
            for (int rr = 0; rr < 2; rr++) {
                int ml = mt * 16 + g_row + rr * 8;
                if (ml < pxc) {
#pragma unroll
                    for (int nt = 0; nt < 8; nt++) {
                        int oc = nt * 8 + four * 2;
                        float vx = d[im][nt][rr * 2]     + bias_sh[oc];
                        float vy = d[im][nt][rr * 2 + 1] + bias_sh[oc + 1];
                        *(float2*)(rawp + ml * 64 + oc) = make_float2(vx, vy);
                        ps[nt][0] += vx; qs[nt][0] += vx * vx;
                        ps[nt][1] += vy; qs[nt][1] += vy * vy;
                    }
                }
            }
        }
        __syncthreads();

        // ---- pool 2x2 from smem raw -> pooled out ----
        int pr0 = r0 >> 1;
        int rend = r0 + rows; if (rend > 2 * Np) rend = 2 * Np;
        int prn = (rend >> 1) - pr0;
        for (int i = tid; i < prn * Np * 64; i += 256) {
            int lpr = i / (Np * 64);
            int rest = i - lpr * (Np * 64);
            int ox = rest >> 6, c = rest & 63;
            int base = ((2 * lpr) * NX + 2 * ox) * 64 + c;
            float v = fmaxf(fmaxf(rawp[base], rawp[base + 64]),
                            fmaxf(rawp[base + NX * 64], rawp[base + NX * 64 + 64]));
            pooled[((size_t)g * (Np * Np) + (pr0 + lpr) * Np + ox) * 64 + c] = v;
        }
    }

    // ---- stats reduction -> part[g][128] ----
#pragma unroll
    for (int nt = 0; nt < 8; nt++)
#pragma unroll
        for (int j = 0; j < 2; j++) {
#pragma unroll
            for (int off = 16; off >= 4; off >>= 1) {
                ps[nt][j] += __shfl_down_sync(~0u, ps[nt][j], off);
                qs[nt][j] += __shfl_down_sync(~0u, qs[nt][j], off);
            }
        }
    __syncthreads();
    float* wst = (float*)(smem + OFF_SH);
    if (lane < 4) {
#pragma unroll
        for (int nt = 0; nt < 8; nt++)
#pragma unroll
            for (int j = 0; j < 2; j++) {
                int oc = nt * 8 + lane * 2 + j;
                wst[warp * 128 + oc]      = ps[nt][j];
                wst[warp * 128 + 64 + oc] = qs[nt][j];
            }
    }
    __syncthreads();
    if (tid < 128) {
        float s = 0.f;
#pragma unroll
        for (int wi = 0; wi < 8; wi++) s += wst[wi * 128 + tid];
        part[(size_t)g * 128 + tid] = s;
    }
}

// ---------------- per-slot BN affine ----------------
__global__ void __launch_bounds__(64) abfin2_kernel(const float* __restrict__ part,
    const float* __restrict__ gamma, const float* __restrict__ beta,
    float* __restrict__ ab, float invCnt)
{
    int slot = blockIdx.x, c = threadIdx.x;
    float s = 0.f, q = 0.f;
    for (int b = 0; b < 32; b++) {
        s += part[(size_t)(slot * 32 + b) * 128 + c];
        q += part[(size_t)(slot * 32 + b) * 128 + 64 + c];
    }
    float mn = s * invCnt;
    float var = q * invCnt - mn * mn;
    float sc = gamma[c] * rsqrtf(var + 1e-3f);
    ab[(slot * 64 + c) * 2] = sc;
    ab[(slot * 64 + c) * 2 + 1] = beta[c] - mn * sc;
}

// ---------------- gemmz ----------------
__global__ void __launch_bounds__(256) gemmz_kernel(
    const float* __restrict__ emb, const float* __restrict__ abp,
    const float* __restrict__ fk, const float* __restrict__ fb,
    const float* __restrict__ bk, const float* __restrict__ bb,
    float* __restrict__ Z)
{
    int gb = blockIdx.x, dir = blockIdx.y;
    const float* W = dir ? bk : fk;
    const float* bias = dir ? bb : fb;
    float* Zo = Z + (size_t)dir * NIMG * 128;
    __shared__ float A_sh[32][33];
    __shared__ __align__(16) float B_sh[32][128];
    int tid = threadIdx.x, jj = tid & 31, gg = tid >> 5;
    float acc[4][4] = {};
    for (int d0 = 0; d0 < 1600; d0 += 32) {
        for (int i = tid; i < 1024; i += 256) {
            int r = i >> 5, dd = i & 31, d = d0 + dd, c = d & 63;
            float raw = emb[(size_t)(gb * 32 + r) * 1600 + d];
            A_sh[r][dd] = fmaxf(fmaf(abp[(gb * 64 + c) * 2], raw, abp[(gb * 64 + c) * 2 + 1]), 0.f);
        }
        for (int i = tid; i < 4096; i += 256)
            B_sh[i >> 7][i & 127] = W[(size_t)(d0 + (i >> 7)) * 128 + (i & 127)];
        __syncthreads();
#pragma unroll
        for (int dd = 0; dd < 32; dd++) {
            float4 bv = *(const float4*)&B_sh[dd][jj * 4];
#pragma unroll
            for (int r = 0; r < 4; r++) {
                float a = A_sh[gg * 4 + r][dd];
                acc[r][0] += a * bv.x; acc[r][1] += a * bv.y;
                acc[r][2] += a * bv.z; acc[r][3] += a * bv.w;
            }
        }
        __syncthreads();
    }
#pragma unroll
    for (int r = 0; r < 4; r++)
#pragma unroll
        for (int c = 0; c < 4; c++)
            Zo[(size_t)(gb * 32 + gg * 4 + r) * 128 + jj * 4 + c] = acc[r][c] + bias[jj * 4 + c];
}

// ---------------- LSTM ----------------
__global__ void __launch_bounds__(672) lstm_kernel(
    const float* __restrict__ Z,
    const float* __restrict__ fr, const float* __restrict__ br,
    float* __restrict__ outs)
{
    int q = blockIdx.x, dir = blockIdx.y;
    const float* R = dir ? br : fr;
    const float* Zp = Z + (size_t)dir * NIMG * 128;
    __shared__ float Wh[32][128];
    __shared__ float h_sh[21][32], c_sh[21][32];
    int tid = threadIdx.x;
    for (int i = tid; i < 4096; i += 672) Wh[i >> 7][i & 127] = R[i];
    int p = tid >> 5, j = tid & 31;
    h_sh[p][j] = 0.f; c_sh[p][j] = 0.f;
    __syncthreads();
    int slot = (p < 20) ? p : (20 + q);
    for (int step = 0; step < 32; step++) {
        int t = dir ? (31 - step) : step;
        const float* zr = Zp + (size_t)(slot * 32 + t) * 128;
        float z0 = zr[j], z1 = zr[32 + j], z2 = zr[64 + j], z3 = zr[96 + j];
#pragma unroll
        for (int k = 0; k < 32; k++) {
            float hk = h_sh[p][k];
            z0 += hk * Wh[k][j]; z1 += hk * Wh[k][32 + j];
            z2 += hk * Wh[k][64 + j]; z3 += hk * Wh[k][96 + j];
        }
        float ig = 1.f / (1.f + expf(-z0)), fg = 1.f / (1.f + expf(-z1));
        float gg = tanhf(z2), og = 1.f / (1.f + expf(-z3));
        float cn = fg * c_sh[p][j] + ig * gg;
        float hn = og * tanhf(cn);
        __syncthreads();
        h_sh[p][j] = hn; c_sh[p][j] = cn;
        outs[(size_t)((q * 21 + p) * 32 + t) * 64 + dir * 32 + j] = hn;
        __syncthreads();
    }
}

// ---------------- attention + CE + acc ----------------
__global__ void __launch_bounds__(256) final_kernel(
    const float* __restrict__ outs,
    const int* __restrict__ ysup, const int* __restrict__ yqry,
    float* __restrict__ out)
{
    __shared__ float ce_sh[160], eq_sh[160];
    int tid = threadIdx.x;
    if (tid < 160) {
        int q = tid / 32, b = tid % 32;
        const float* qry = outs + (size_t)((q * 21 + 20) * 32 + b) * 64;
        float logit[20];
        for (int s = 0; s < 20; s++) {
            const float* sp = outs + (size_t)((q * 21 + s) * 32 + b) * 64;
            float d = 0.f, n2 = 0.f;
            for (int k = 0; k < 64; k++) { d += qry[k] * sp[k]; n2 += sp[k] * sp[k]; }
            logit[s] = d * rsqrtf(fmaxf(n2, 1e-10f));
        }
        float mx = logit[0];
        for (int s = 1; s < 20; s++) mx = fmaxf(mx, logit[s]);
        float den = 0.f;
        for (int s = 0; s < 20; s++) { logit[s] = expf(logit[s] - mx); den += logit[s]; }
        float invden = 1.f / den;
        float preds[20];
        for (int wq = 0; wq < 20; wq++) preds[wq] = 0.f;
        for (int s = 0; s < 20; s++) preds[ysup[b * 20 + s]] += logit[s] * invden;
        int yq = yqry[b * 5 + q];
        float pv = fminf(fmaxf(preds[yq], 1e-7f), 1.f - 1e-7f);
        ce_sh[tid] = -logf(pv);
        int best = 0;
        for (int wq = 1; wq < 20; wq++) if (preds[wq] > preds[best]) best = wq;
        eq_sh[tid] = (best == yq) ? 1.f : 0.f;
    }
    __syncthreads();
    if (tid < 32) {
        float s = 0.f;
        for (int q = 0; q < 5; q++) s += ce_sh[q * 32 + tid];
        out[tid] = s * 0.2f;
    }
    if (tid == 0) {
        float s = 0.f;
        for (int i = 0; i < 160; i++) s += eq_sh[i];
        out[32] = s / 160.f;
    }
}

// ---------------- launch ----------------
extern "C" void kernel_launch(void* const* d_in, const int* in_sizes, int n_in,
                              void* d_out, int out_size)
{
    (void)in_sizes; (void)n_in; (void)out_size;
    const float* xs = (const float*)d_in[0];
    const int* ysup = (const int*)d_in[1];
    const float* xq = (const float*)d_in[2];
    const int* yqry = (const int*)d_in[3];
    const float *k1=(const float*)d_in[4],  *b1=(const float*)d_in[5],  *g1=(const float*)d_in[6],  *be1=(const float*)d_in[7];
    const float *k2=(const float*)d_in[8],  *b2=(const float*)d_in[9],  *g2=(const float*)d_in[10], *be2=(const float*)d_in[11];
    const float *k3=(const float*)d_in[12], *b3=(const float*)d_in[13], *g3=(const float*)d_in[14], *be3=(const float*)d_in[15];
    const float *k4=(const float*)d_in[16], *b4=(const float*)d_in[17], *g4=(const float*)d_in[18], *be4=(const float*)d_in[19];
    const float *fk=(const float*)d_in[20], *fr=(const float*)d_in[21], *fb=(const float*)d_in[22];
    const float *bk=(const float*)d_in[23], *br=(const float*)d_in[24], *bb=(const float*)d_in[25];

    float *pool1, *pool2, *pool3, *pool4, *part, *Z, *outs, *ab;
    cudaGetSymbolAddress((void**)&pool1, g_pool1);
    cudaGetSymbolAddress((void**)&pool2, g_pool2);
    cudaGetSymbolAddress((void**)&pool3, g_pool3);
    cudaGetSymbolAddress((void**)&pool4, g_pool4);
    cudaGetSymbolAddress((void**)&part, g_part);
    cudaGetSymbolAddress((void**)&Z, g_Z);
    cudaGetSymbolAddress((void**)&outs, g_outs);
    cudaGetSymbolAddress((void**)&ab, g_ab);

    const int SM1  = 1024 + 7588 * 12 + 64 * 80 + 176 * 64 * 4;          // 142256
    const int SM42 = 1024 + 9 * 64 * 144 + 2 * (10 * 44) * 144;          // 210688
    const int SM21 = 1024 + 9 * 64 * 144 + 2 * (16 * 23) * 144;          // 189952
    const int SM10 = 1024 + 9 * 64 * 144 + 2 * (14 * 12) * 144;          // 132352
    cudaFuncSetAttribute(conv1mma2_kernel,        cudaFuncAttributeMaxDynamicSharedMemorySize, SM1);
    cudaFuncSetAttribute(mmaconv_kernel<42,6,7>,  cudaFuncAttributeMaxDynamicSharedMemorySize, SM42);
    cudaFuncSetAttribute(mmaconv_kernel<21,12,2>, cudaFuncAttributeMaxDynamicSharedMemorySize, SM21);
    cudaFuncSetAttribute(mmaconv_kernel<10,10,1>, cudaFuncAttributeMaxDynamicSharedMemorySize, SM10);

    // L1: MMA conv, fused stats + pool -> pool1
    conv1mma2_kernel<<<NIMG, 256, SM1>>>(xs, xq, k1, b1, pool1, part);
    abfin2_kernel<<<25, 64>>>(part, g1, be1, ab, 1.f / (32.f * 7056.f));
    // L2: fused conv+stats+pool -> pool2
    mmaconv_kernel<42,6,7><<<NIMG, 256, SM42>>>(pool1, ab, k2, b2, pool2, part);
    abfin2_kernel<<<25, 64>>>(part, g2, be2, ab, 1.f / (32.f * 1764.f));
    // L3 -> pool3
    mmaconv_kernel<21,12,2><<<NIMG, 256, SM21>>>(pool2, ab, k3, b3, pool3, part);
    abfin2_kernel<<<25, 64>>>(part, g3, be3, ab, 1.f / (32.f * 441.f));
    // L4 -> pool4
    mmaconv_kernel<10,10,1><<<NIMG, 256, SM10>>>(pool3, ab, k4, b4, pool4, part);
    abfin2_kernel<<<25, 64>>>(part, g4, be4, ab, 1.f / (32.f * 100.f));

    gemmz_kernel<<<dim3(25, 2), 256>>>(pool4, ab, fk, fb, bk, bb, Z);
    lstm_kernel<<<dim3(5, 2), 672>>>(Z, fr, br, outs);
    final_kernel<<<1, 256>>>(outs, ysup, yqry, (float*)d_out);
}

// round 14
// speedup vs baseline: 1.2086x; 1.0599x over previous
#include <cuda_runtime.h>
#include <cuda_fp16.h>
#include <math.h>
#include <stdint.h>

#define NIMG 800
typedef unsigned long long u64;

// ---------------- scratch ----------------
__device__ float g_pool1[(size_t)NIMG * 1764 * 64];
__device__ float g_pool2[(size_t)NIMG * 441 * 64];
__device__ float g_pool3[(size_t)NIMG * 100 * 64];
__device__ float g_pool4[(size_t)NIMG * 25 * 64];
__device__ float g_partA[(size_t)NIMG * 128];
__device__ float g_partB[(size_t)NIMG * 128];
__device__ float g_Z[2 * NIMG * 128];
__device__ float g_outs[5 * 21 * 32 * 64];

// ---------------- warp mma (fp16 in, f32 acc) ----------------
__device__ __forceinline__ void mma16816(float* d, uint32_t a0, uint32_t a1,
                                         uint32_t a2, uint32_t a3,
                                         uint32_t b0, uint32_t b1) {
    asm volatile(
        "mma.sync.aligned.m16n8k16.row.col.f32.f16.f16.f32 "
        "{%0,%1,%2,%3}, {%4,%5,%6,%7}, {%8,%9}, {%0,%1,%2,%3};"
        : "+f"(d[0]), "+f"(d[1]), "+f"(d[2]), "+f"(d[3])
        : "r"(a0), "r"(a1), "r"(a2), "r"(a3), "r"(b0), "r"(b1));
}
__device__ __forceinline__ uint32_t packh2(__half a, __half b) {
    __half2 h = __halves2half2(a, b);
    return *(uint32_t*)&h;
}
__device__ __forceinline__ uint32_t packf2(float a, float b) {
    __half2 h = __floats2half2_rn(a, b);
    return *(uint32_t*)&h;
}

// ================= conv1mma2: layer 1, direct gather, 2 pool-row-pairs/iter =================
__global__ void __launch_bounds__(256) conv1mma2_kernel(
    const float* __restrict__ xs, const float* __restrict__ xq,
    const float* __restrict__ w, const float* __restrict__ bias,
    float* __restrict__ pool1, float* __restrict__ part)
{
    constexpr int WP = 86, P = WP * WP;
    constexpr int PENT = 96 + P + 96;
    constexpr int AR = 80;
    constexpr int OFF_P   = 1024;
    constexpr int OFF_B   = OFF_P + PENT * 12;
    constexpr int OFF_RAW = OFF_B + 64 * AR;

    extern __shared__ __align__(16) char smem[];
    int tid = threadIdx.x;
    int g = blockIdx.x;
    float* bias_sh = (float*)(smem + 16);
    if (tid < 64) bias_sh[tid] = bias[tid];

    {
        int b = g & 31, slot = g >> 5;
        const float* src = (slot < 20)
            ? (xs + (size_t)(b * 20 + slot) * 84 * 84 * 3)
            : (xq + (size_t)(b * 5 + (slot - 20)) * 84 * 84 * 3);
        float* Pp = (float*)(smem + OFF_P);
        for (int i = tid; i < PENT * 3; i += 256) {
            int sp = i / 3 - 96;
            int c = i - (sp + 96) * 3;
            float v = 0.f;
            if (sp >= 0 && sp < P) {
                int py = sp / WP, px = sp - py * WP;
                if (px >= 1 && px <= 84 && py >= 1 && py <= 84)
                    v = src[(size_t)((py - 1) * 84 + (px - 1)) * 3 + c];
            }
            Pp[i] = v;
        }
    }
    for (int i = tid; i < 64 * 32; i += 256) {
        int oc = i >> 5, k = i & 31;
        float v = (k < 27) ? w[k * 64 + oc] : 0.f;
        *(__half*)(smem + OFF_B + oc * AR + k * 2) = __float2half_rn(v);
    }
    __syncthreads();

    int warp = tid >> 5, lane = tid & 31;
    int g_row = lane >> 2, four = lane & 3;
    int nmt = (warp < 6) ? 3 : 2;   // 22 mtiles over 8 warps

    int rel[8];
#pragma unroll
    for (int kc = 0; kc < 2; kc++)
#pragma unroll
        for (int kh = 0; kh < 2; kh++)
#pragma unroll
            for (int h = 0; h < 2; h++) {
                int k = kc * 16 + kh * 8 + four * 2 + h;
                int t = k / 3, c = k - 3 * t;
                int shift = (t / 3 - 1) * WP + (t % 3 - 1);
                rel[kc * 4 + kh * 2 + h] = shift * 3 + c;
            }

    const float* Pimg = (float*)(smem + OFF_P) + 96 * 3;
    float* rawp = (float*)(smem + OFF_RAW);

    float ps[8][2], qs[8][2];
#pragma unroll
    for (int nt = 0; nt < 8; nt++) { ps[nt][0]=0.f; ps[nt][1]=0.f; qs[nt][0]=0.f; qs[nt][1]=0.f; }

    for (int yp2 = 0; yp2 < 21; yp2++) {
        int s0 = (4 * yp2 + 1) * WP;    // 4 image rows per tile (2 pool-row pairs)
        float d[3][8][4];
#pragma unroll
        for (int im = 0; im < 3; im++)
#pragma unroll
            for (int nt = 0; nt < 8; nt++)
#pragma unroll
                for (int i = 0; i < 4; i++) d[im][nt][i] = 0.f;

#pragma unroll
        for (int kc = 0; kc < 2; kc++)
#pragma unroll
            for (int im = 0; im < 3; im++) {
                if (im >= nmt) break;
                int mt = warp + im * 8;
                uint32_t ah[4], al[4];
#pragma unroll
                for (int r = 0; r < 4; r++) {
                    int row = mt * 16 + g_row + (r & 1) * 8;
                    int base = (s0 + row) * 3;
                    int kh = r >> 1;
                    float v0 = Pimg[base + rel[kc * 4 + kh * 2 + 0]];
                    float v1 = Pimg[base + rel[kc * 4 + kh * 2 + 1]];
                    uint32_t hh = packf2(v0, v1);
                    __half2 hf = *(__half2*)&hh;
                    float2 hb = __half22float2(hf);
                    al[r] = packf2(v0 - hb.x, v1 - hb.y);
                    ah[r] = hh;
                }
#pragma unroll
                for (int nt = 0; nt < 8; nt++) {
                    const char* bp = smem + OFF_B + (nt * 8 + g_row) * AR + kc * 32 + four * 4;
                    uint32_t b0 = *(const uint32_t*)bp;
                    uint32_t b1 = *(const uint32_t*)(bp + 16);
                    mma16816(d[im][nt], ah[0], ah[1], ah[2], ah[3], b0, b1);
                    mma16816(d[im][nt], al[0], al[1], al[2], al[3], b0, b1);
                }
            }

#pragma unroll
        for (int im = 0; im < 3; im++) {
            if (im >= nmt) break;
            int mt = warp + im * 8;
#pragma unroll
            for (int rr = 0; rr < 2; rr++) {
                int m = mt * 16 + g_row + rr * 8;
                bool stat = false;
                if (m < 344) {
                    int px = m % WP;
                    stat = (px >= 1 && px <= 84);
                }
#pragma unroll
                for (int nt = 0; nt < 8; nt++) {
                    int oc = nt * 8 + four * 2;
                    float vx = d[im][nt][rr * 2]     + bias_sh[oc];
                    float vy = d[im][nt][rr * 2 + 1] + bias_sh[oc + 1];
                    *(float2*)(rawp + m * 64 + oc) = make_float2(vx, vy);
                    if (stat) {
                        ps[nt][0] += vx; qs[nt][0] += vx * vx;
                        ps[nt][1] += vy; qs[nt][1] += vy * vy;
                    }
                }
            }
        }
        __syncthreads();
        for (int i = tid; i < 2 * 42 * 64; i += 256) {
            int lpr = i / (42 * 64);
            int rest = i - lpr * (42 * 64);
            int ox = rest >> 6, c = rest & 63;
            int m0 = lpr * 172 + 2 * ox + 1;
            float v = fmaxf(fmaxf(rawp[m0 * 64 + c], rawp[(m0 + 1) * 64 + c]),
                            fmaxf(rawp[(m0 + WP) * 64 + c], rawp[(m0 + WP + 1) * 64 + c]));
            pool1[((size_t)g * 1764 + (2 * yp2 + lpr) * 42 + ox) * 64 + c] = v;
        }
        __syncthreads();
    }

#pragma unroll
    for (int nt = 0; nt < 8; nt++)
#pragma unroll
        for (int j = 0; j < 2; j++) {
#pragma unroll
            for (int off = 16; off >= 4; off >>= 1) {
                ps[nt][j] += __shfl_down_sync(~0u, ps[nt][j], off);
                qs[nt][j] += __shfl_down_sync(~0u, qs[nt][j], off);
            }
        }
    float* wst = rawp;
    if (lane < 4) {
#pragma unroll
        for (int nt = 0; nt < 8; nt++)
#pragma unroll
            for (int j = 0; j < 2; j++) {
                int oc = nt * 8 + lane * 2 + j;
                wst[warp * 128 + oc]      = ps[nt][j];
                wst[warp * 128 + 64 + oc] = qs[nt][j];
            }
    }
    __syncthreads();
    if (tid < 128) {
        float s = 0.f;
#pragma unroll
        for (int wi = 0; wi < 8; wi++) s += wst[wi * 128 + tid];
        part[(size_t)g * 128 + tid] = s;
    }
}

// ================= mmaconv: L2-4, fused BN-affine prologue + fused pool + merged hi/lo =================
template <int NX, int TR, int NT>
__global__ void __launch_bounds__(256) mmaconv_kernel(
    const float* __restrict__ in, const float* __restrict__ partin,
    const float* __restrict__ gamma, const float* __restrict__ beta, float invPrev,
    const float* __restrict__ w, const float* __restrict__ bias,
    float* __restrict__ pooled, float* __restrict__ partout)
{
    constexpr int W = NX + 2, PIX = NX * NX, Np = NX / 2;
    constexpr int SROWS = (TR + 4) * W;
    constexpr int SROW = 144;
    constexpr int BTAP = 64 * SROW;
    constexpr int OFF_B  = 1024;
    constexpr int OFF_SH = OFF_B + 9 * BTAP;
    constexpr int OFF_SL = OFF_SH + SROWS * SROW;

    extern __shared__ __align__(16) char smem[];
    int tid = threadIdx.x;
    int g = blockIdx.x, slot = g >> 5;
    float* bias_sh = (float*)(smem + 16);
    float* ab_sh   = (float*)(smem + 304);
    if (tid < 64) bias_sh[tid] = bias[tid];
    // fused BN-affine of previous layer (from its per-image partials)
    if (tid >= 64 && tid < 128) {
        int c = tid - 64;
        float s = 0.f, q = 0.f;
        for (int b = 0; b < 32; b++) {
            s += partin[(size_t)(slot * 32 + b) * 128 + c];
            q += partin[(size_t)(slot * 32 + b) * 128 + 64 + c];
        }
        float mn = s * invPrev;
        float var = q * invPrev - mn * mn;
        float sc = gamma[c] * rsqrtf(var + 1e-3f);
        ab_sh[c * 2] = sc;
        ab_sh[c * 2 + 1] = beta[c] - mn * sc;
    }

    for (int i = tid; i < 9 * 64 * 64; i += 256) {
        int t = i >> 12, r = i & 4095, ci = r >> 6, oc = r & 63;
        *(__half*)(smem + OFF_B + (t * 64 + oc) * SROW + ci * 2) = __float2half_rn(w[i]);
    }

    int warp = tid >> 5, lane = tid & 31;
    int g_row = lane >> 2, four = lane & 3;

    float ps[8][2], qs[8][2];
#pragma unroll
    for (int nt = 0; nt < 8; nt++) { ps[nt][0]=0.f; ps[nt][1]=0.f; qs[nt][0]=0.f; qs[nt][1]=0.f; }

    float* rawp = (float*)(smem + OFF_SH);

    for (int tile = 0; tile < NT; tile++) {
        int r0 = tile * TR;
        int rows = (NX - r0 < TR) ? (NX - r0) : TR;
        int pxc = rows * NX;
        int mtiles = (pxc + 15) >> 4;
        bool v0 = warp < mtiles, v1 = warp + 8 < mtiles;

        __syncthreads();
        int nstrip = (rows + 2) * W;
        for (int i = tid; i < nstrip * 16; i += 256) {
            int s = i >> 4, c4 = (i & 15) * 4;
            int p = r0 + s / W, px = s % W;
            float4 v = make_float4(0.f, 0.f, 0.f, 0.f);
            if (px >= 1 && px <= NX && p >= 1 && p <= NX) {
                float4 rv = *(const float4*)&in[((size_t)g * PIX + (p - 1) * NX + (px - 1)) * 64 + c4];
                v.x = fmaxf(fmaf(ab_sh[(c4 + 0) * 2], rv.x, ab_sh[(c4 + 0) * 2 + 1]), 0.f);
                v.y = fmaxf(fmaf(ab_sh[(c4 + 1) * 2], rv.y, ab_sh[(c4 + 1) * 2 + 1]), 0.f);
                v.z = fmaxf(fmaf(ab_sh[(c4 + 2) * 2], rv.z, ab_sh[(c4 + 2) * 2 + 1]), 0.f);
                v.w = fmaxf(fmaf(ab_sh[(c4 + 3) * 2], rv.w, ab_sh[(c4 + 3) * 2 + 1]), 0.f);
            }
            uint32_t hx = packf2(v.x, v.y), hz = packf2(v.z, v.w);
            float2 bx = __half22float2(*(__half2*)&hx);
            float2 bz = __half22float2(*(__half2*)&hz);
            *(uint2*)(smem + OFF_SH + s * SROW + c4 * 2) = make_uint2(hx, hz);
            *(uint2*)(smem + OFF_SL + s * SROW + c4 * 2) =
                make_uint2(packf2(v.x - bx.x, v.y - bx.y), packf2(v.z - bz.x, v.w - bz.y));
        }
        __syncthreads();

        int rA[2][2] = {{0, 0}, {0, 0}};
#pragma unroll
        for (int im = 0; im < 2; im++) {
            if (im == 0 ? v0 : v1) {
#pragma unroll
                for (int h = 0; h < 2; h++) {
                    int ml = (warp + im * 8) * 16 + h * 8 + g_row;
                    rA[im][h] = (ml / NX) * W + (ml % NX);
                }
            }
        }

        float d[2][8][4];
#pragma unroll
        for (int mt = 0; mt < 2; mt++)
#pragma unroll
            for (int nt = 0; nt < 8; nt++)
#pragma unroll
                for (int i = 0; i < 4; i++) d[mt][nt][i] = 0.f;

#pragma unroll 1
        for (int t = 0; t < 9; t++) {
            int rshift = (t / 3) * W + (t % 3);
            const char* bt = smem + OFF_B + t * BTAP;
#pragma unroll
            for (int kc = 0; kc < 4; kc++) {
                int cb = kc * 32 + four * 4;
                if (v0) {
                    uint32_t a0h[4], a0l[4], a1h[4], a1l[4];
                    {
                        const char* p0 = smem + OFF_SH + (rA[0][0] + rshift) * SROW + cb;
                        const char* p1 = smem + OFF_SH + (rA[0][1] + rshift) * SROW + cb;
                        const char* q0 = smem + OFF_SL + (rA[0][0] + rshift) * SROW + cb;
                        const char* q1 = smem + OFF_SL + (rA[0][1] + rshift) * SROW + cb;
                        a0h[0] = *(const uint32_t*)p0; a0h[1] = *(const uint32_t*)p1;
                        a0h[2] = *(const uint32_t*)(p0 + 16); a0h[3] = *(const uint32_t*)(p1 + 16);
                        a0l[0] = *(const uint32_t*)q0; a0l[1] = *(const uint32_t*)q1;
                        a0l[2] = *(const uint32_t*)(q0 + 16); a0l[3] = *(const uint32_t*)(q1 + 16);
                    }
                    if (v1) {
                        const char* p0 = smem + OFF_SH + (rA[1][0] + rshift) * SROW + cb;
                        const char* p1 = smem + OFF_SH + (rA[1][1] + rshift) * SROW + cb;
                        const char* q0 = smem + OFF_SL + (rA[1][0] + rshift) * SROW + cb;
                        const char* q1 = smem + OFF_SL + (rA[1][1] + rshift) * SROW + cb;
                        a1h[0] = *(const uint32_t*)p0; a1h[1] = *(const uint32_t*)p1;
                        a1h[2] = *(const uint32_t*)(p0 + 16); a1h[3] = *(const uint32_t*)(p1 + 16);
                        a1l[0] = *(const uint32_t*)q0; a1l[1] = *(const uint32_t*)q1;
                        a1l[2] = *(const uint32_t*)(q0 + 16); a1l[3] = *(const uint32_t*)(q1 + 16);
                    }
#pragma unroll
                    for (int nt = 0; nt < 8; nt++) {
                        const char* bp = bt + (nt * 8 + g_row) * SROW + cb;
                        uint32_t b0 = *(const uint32_t*)bp;
                        uint32_t b1 = *(const uint32_t*)(bp + 16);
                        mma16816(d[0][nt], a0h[0], a0h[1], a0h[2], a0h[3], b0, b1);
                        mma16816(d[0][nt], a0l[0], a0l[1], a0l[2], a0l[3], b0, b1);
                        if (v1) {
                            mma16816(d[1][nt], a1h[0], a1h[1], a1h[2], a1h[3], b0, b1);
                            mma16816(d[1][nt], a1l[0], a1l[1], a1l[2], a1l[3], b0, b1);
                        }
                    }
                }
            }
        }
        __syncthreads();

#pragma unroll
        for (int im = 0; im < 2; im++) {
            if (im == 0 ? !v0 : !v1) continue;
            int mt = warp + im * 8;
#pragma unroll
            for (int rr = 0; rr < 2; rr++) {
                int ml = mt * 16 + g_row + rr * 8;
                if (ml < pxc) {
#pragma unroll
                    for (int nt = 0; nt < 8; nt++) {
                        int oc = nt * 8 + four * 2;
                        float vx = d[im][nt][rr * 2]     + bias_sh[oc];
                        float vy = d[im][nt][rr * 2 + 1] + bias_sh[oc + 1];
                        *(float2*)(rawp + ml * 64 + oc) = make_float2(vx, vy);
                        ps[nt][0] += vx; qs[nt][0] += vx * vx;
                        ps[nt][1] += vy; qs[nt][1] += vy * vy;
                    }
                }
            }
        }
        __syncthreads();

        int pr0 = r0 >> 1;
        int rend = r0 + rows; if (rend > 2 * Np) rend = 2 * Np;
        int prn = (rend >> 1) - pr0;
        for (int i = tid; i < prn * Np * 64; i += 256) {
            int lpr = i / (Np * 64);
            int rest = i - lpr * (Np * 64);
            int ox = rest >> 6, c = rest & 63;
            int base = ((2 * lpr) * NX + 2 * ox) * 64 + c;
            float v = fmaxf(fmaxf(rawp[base], rawp[base + 64]),
                            fmaxf(rawp[base + NX * 64], rawp[base + NX * 64 + 64]));
            pooled[((size_t)g * (Np * Np) + (pr0 + lpr) * Np + ox) * 64 + c] = v;
        }
    }

#pragma unroll
    for (int nt = 0; nt < 8; nt++)
#pragma unroll
        for (int j = 0; j < 2; j++) {
#pragma unroll
            for (int off = 16; off >= 4; off >>= 1) {
                ps[nt][j] += __shfl_down_sync(~0u, ps[nt][j], off);
                qs[nt][j] += __shfl_down_sync(~0u, qs[nt][j], off);
            }
        }
    __syncthreads();
    float* wst = (float*)(smem + OFF_SH);
    if (lane < 4) {
#pragma unroll
        for (int nt = 0; nt < 8; nt++)
#pragma unroll
            for (int j = 0; j < 2; j++) {
                int oc = nt * 8 + lane * 2 + j;
                wst[warp * 128 + oc]      = ps[nt][j];
                wst[warp * 128 + 64 + oc] = qs[nt][j];
            }
    }
    __syncthreads();
    if (tid < 128) {
        float s = 0.f;
#pragma unroll
        for (int wi = 0; wi < 8; wi++) s += wst[wi * 128 + tid];
        partout[(size_t)g * 128 + tid] = s;
    }
}

// ---------------- gemmz: fused BN4 affine prologue ----------------
__global__ void __launch_bounds__(256) gemmz_kernel(
    const float* __restrict__ emb, const float* __restrict__ partin,
    const float* __restrict__ gamma, const float* __restrict__ beta, float invPrev,
    const float* __restrict__ fk, const float* __restrict__ fb,
    const float* __restrict__ bk, const float* __restrict__ bb,
    float* __restrict__ Z)
{
    int gb = blockIdx.x, dir = blockIdx.y;
    const float* W = dir ? bk : fk;
    const float* bias = dir ? bb : fb;
    float* Zo = Z + (size_t)dir * NIMG * 128;
    __shared__ float A_sh[32][33];
    __shared__ __align__(16) float B_sh[32][128];
    __shared__ float ab_sh[128];
    int tid = threadIdx.x, jj = tid & 31, gg = tid >> 5;
    if (tid < 64) {
        float s = 0.f, q = 0.f;
        for (int b = 0; b < 32; b++) {
            s += partin[(size_t)(gb * 32 + b) * 128 + tid];
            q += partin[(size_t)(gb * 32 + b) * 128 + 64 + tid];
        }
        float mn = s * invPrev;
        float var = q * invPrev - mn * mn;
        float sc = gamma[tid] * rsqrtf(var + 1e-3f);
        ab_sh[tid * 2] = sc;
        ab_sh[tid * 2 + 1] = beta[tid] - mn * sc;
    }
    __syncthreads();
    float acc[4][4] = {};
    for (int d0 = 0; d0 < 1600; d0 += 32) {
        for (int i = tid; i < 1024; i += 256) {
            int r = i >> 5, dd = i & 31, d = d0 + dd, c = d & 63;
            float raw = emb[(size_t)(gb * 32 + r) * 1600 + d];
            A_sh[r][dd] = fmaxf(fmaf(ab_sh[c * 2], raw, ab_sh[c * 2 + 1]), 0.f);
        }
        for (int i = tid; i < 4096; i += 256)
            B_sh[i >> 7][i & 127] = W[(size_t)(d0 + (i >> 7)) * 128 + (i & 127)];
        __syncthreads();
#pragma unroll
        for (int dd = 0; dd < 32; dd++) {
            float4 bv = *(const float4*)&B_sh[dd][jj * 4];
#pragma unroll
            for (int r = 0; r < 4; r++) {
                float a = A_sh[gg * 4 + r][dd];
                acc[r][0] += a * bv.x; acc[r][1] += a * bv.y;
                acc[r][2] += a * bv.z; acc[r][3] += a * bv.w;
            }
        }
        __syncthreads();
    }
#pragma unroll
    for (int r = 0; r < 4; r++)
#pragma unroll
        for (int c = 0; c < 4; c++)
            Zo[(size_t)(gb * 32 + gg * 4 + r) * 128 + jj * 4 + c] = acc[r][c] + bias[jj * 4 + c];
}

// ---------------- LSTM ----------------
__global__ void __launch_bounds__(672) lstm_kernel(
    const float* __restrict__ Z,
    const float* __restrict__ fr, const float* __restrict__ br,
    float* __restrict__ outs)
{
    int q = blockIdx.x, dir = blockIdx.y;
    const float* R = dir ? br : fr;
    const float* Zp = Z + (size_t)dir * NIMG * 128;
    __shared__ float Wh[32][128];
    __shared__ float h_sh[21][32], c_sh[21][32];
    int tid = threadIdx.x;
    for (int i = tid; i < 4096; i += 672) Wh[i >> 7][i & 127] = R[i];
    int p = tid >> 5, j = tid & 31;
    h_sh[p][j] = 0.f; c_sh[p][j] = 0.f;
    __syncthreads();
    int slot = (p < 20) ? p : (20 + q);
    for (int step = 0; step < 32; step++) {
        int t = dir ? (31 - step) : step;
        const float* zr = Zp + (size_t)(slot * 32 + t) * 128;
        float z0 = zr[j], z1 = zr[32 + j], z2 = zr[64 + j], z3 = zr[96 + j];
#pragma unroll
        for (int k = 0; k < 32; k++) {
            float hk = h_sh[p][k];
            z0 += hk * Wh[k][j]; z1 += hk * Wh[k][32 + j];
            z2 += hk * Wh[k][64 + j]; z3 += hk * Wh[k][96 + j];
        }
        float ig = 1.f / (1.f + expf(-z0)), fg = 1.f / (1.f + expf(-z1));
        float gg = tanhf(z2), og = 1.f / (1.f + expf(-z3));
        float cn = fg * c_sh[p][j] + ig * gg;
        float hn = og * tanhf(cn);
        __syncthreads();
        h_sh[p][j] = hn; c_sh[p][j] = cn;
        outs[(size_t)((q * 21 + p) * 32 + t) * 64 + dir * 32 + j] = hn;
        __syncthreads();
    }
}

// ---------------- attention + CE + acc ----------------
__global__ void __launch_bounds__(256) final_kernel(
    const float* __restrict__ outs,
    const int* __restrict__ ysup, const int* __restrict__ yqry,
    float* __restrict__ out)
{
    __shared__ float ce_sh[160], eq_sh[160];
    int tid = threadIdx.x;
    if (tid < 160) {
        int q = tid / 32, b = tid % 32;
        const float* qry = outs + (size_t)((q * 21 + 20) * 32 + b) * 64;
        float logit[20];
        for (int s = 0; s < 20; s++) {
            const float* sp = outs + (size_t)((q * 21 + s) * 32 + b) * 64;
            float d = 0.f, n2 = 0.f;
            for (int k = 0; k < 64; k++) { d += qry[k] * sp[k]; n2 += sp[k] * sp[k]; }
            logit[s] = d * rsqrtf(fmaxf(n2, 1e-10f));
        }
        float mx = logit[0];
        for (int s = 1; s < 20; s++) mx = fmaxf(mx, logit[s]);
        float den = 0.f;
        for (int s = 0; s < 20; s++) { logit[s] = expf(logit[s] - mx); den += logit[s]; }
        float invden = 1.f / den;
        float preds[20];
        for (int wq = 0; wq < 20; wq++) preds[wq] = 0.f;
        for (int s = 0; s < 20; s++) preds[ysup[b * 20 + s]] += logit[s] * invden;
        int yq = yqry[b * 5 + q];
        float pv = fminf(fmaxf(preds[yq], 1e-7f), 1.f - 1e-7f);
        ce_sh[tid] = -logf(pv);
        int best = 0;
        for (int wq = 1; wq < 20; wq++) if (preds[wq] > preds[best]) best = wq;
        eq_sh[tid] = (best == yq) ? 1.f : 0.f;
    }
    __syncthreads();
    if (tid < 32) {
        float s = 0.f;
        for (int q = 0; q < 5; q++) s += ce_sh[q * 32 + tid];
        out[tid] = s * 0.2f;
    }
    if (tid == 0) {
        float s = 0.f;
        for (int i = 0; i < 160; i++) s += eq_sh[i];
        out[32] = s / 160.f;
    }
}

// ---------------- launch ----------------
extern "C" void kernel_launch(void* const* d_in, const int* in_sizes, int n_in,
                              void* d_out, int out_size)
{
    (void)in_sizes; (void)n_in; (void)out_size;
    const float* xs = (const float*)d_in[0];
    const int* ysup = (const int*)d_in[1];
    const float* xq = (const float*)d_in[2];
    const int* yqry = (const int*)d_in[3];
    const float *k1=(const float*)d_in[4],  *b1=(const float*)d_in[5],  *g1=(const float*)d_in[6],  *be1=(const float*)d_in[7];
    const float *k2=(const float*)d_in[8],  *b2=(const float*)d_in[9],  *g2=(const float*)d_in[10], *be2=(const float*)d_in[11];
    const float *k3=(const float*)d_in[12], *b3=(const float*)d_in[13], *g3=(const float*)d_in[14], *be3=(const float*)d_in[15];
    const float *k4=(const float*)d_in[16], *b4=(const float*)d_in[17], *g4=(const float*)d_in[18], *be4=(const float*)d_in[19];
    const float *fk=(const float*)d_in[20], *fr=(const float*)d_in[21], *fb=(const float*)d_in[22];
    const float *bk=(const float*)d_in[23], *br=(const float*)d_in[24], *bb=(const float*)d_in[25];

    float *pool1, *pool2, *pool3, *pool4, *partA, *partB, *Z, *outs;
    cudaGetSymbolAddress((void**)&pool1, g_pool1);
    cudaGetSymbolAddress((void**)&pool2, g_pool2);
    cudaGetSymbolAddress((void**)&pool3, g_pool3);
    cudaGetSymbolAddress((void**)&pool4, g_pool4);
    cudaGetSymbolAddress((void**)&partA, g_partA);
    cudaGetSymbolAddress((void**)&partB, g_partB);
    cudaGetSymbolAddress((void**)&Z, g_Z);
    cudaGetSymbolAddress((void**)&outs, g_outs);

    const int SM1  = 1024 + 7588 * 12 + 64 * 80 + 352 * 64 * 4;          // 187312
    const int SM42 = 1024 + 9 * 64 * 144 + 2 * (10 * 44) * 144;          // 210688
    const int SM21 = 1024 + 9 * 64 * 144 + 2 * (16 * 23) * 144;          // 189952
    const int SM10 = 1024 + 9 * 64 * 144 + 2 * (14 * 12) * 144;          // 132352
    cudaFuncSetAttribute(conv1mma2_kernel,        cudaFuncAttributeMaxDynamicSharedMemorySize, SM1);
    cudaFuncSetAttribute(mmaconv_kernel<42,6,7>,  cudaFuncAttributeMaxDynamicSharedMemorySize, SM42);
    cudaFuncSetAttribute(mmaconv_kernel<21,12,2>, cudaFuncAttributeMaxDynamicSharedMemorySize, SM21);
    cudaFuncSetAttribute(mmaconv_kernel<10,10,1>, cudaFuncAttributeMaxDynamicSharedMemorySize, SM10);

    // L1 -> pool1, partA
    conv1mma2_kernel<<<NIMG, 256, SM1>>>(xs, xq, k1, b1, pool1, partA);
    // L2: BN1 affine computed in-prologue from partA -> pool2, partB
    mmaconv_kernel<42,6,7><<<NIMG, 256, SM42>>>(pool1, partA, g1, be1, 1.f / (32.f * 7056.f),
                                                k2, b2, pool2, partB);
    // L3: BN2 from partB -> pool3, partA
    mmaconv_kernel<21,12,2><<<NIMG, 256, SM21>>>(pool2, partB, g2, be2, 1.f / (32.f * 1764.f),
                                                 k3, b3, pool3, partA);
    // L4: BN3 from partA -> pool4, partB
    mmaconv_kernel<10,10,1><<<NIMG, 256, SM10>>>(pool3, partA, g3, be3, 1.f / (32.f * 441.f),
                                                 k4, b4, pool4, partB);
    // gemmz: BN4 from partB
    gemmz_kernel<<<dim3(25, 2), 256>>>(pool4, partB, g4, be4, 1.f / (32.f * 100.f),
                                       fk, fb, bk, bb, Z);
    lstm_kernel<<<dim3(5, 2), 672>>>(Z, fr, br, outs);
    final_kernel<<<1, 256>>>(outs, ysup, yqry, (float*)d_out);
}

// round 15
// speedup vs baseline: 1.2568x; 1.0399x over previous
#include <cuda_runtime.h>
#include <cuda_fp16.h>
#include <math.h>
#include <stdint.h>

#define NIMG 800
typedef unsigned long long u64;

// ---------------- scratch ----------------
__device__ float g_pool1[(size_t)NIMG * 1764 * 64];
__device__ float g_pool2[(size_t)NIMG * 441 * 64];
__device__ float g_pool3[(size_t)NIMG * 100 * 64];
__device__ float g_pool4[(size_t)NIMG * 25 * 64];
__device__ float g_partA[(size_t)NIMG * 128];
__device__ float g_partB[(size_t)NIMG * 128];
__device__ float g_Z[2 * NIMG * 128];
__device__ float g_outs[5 * 21 * 32 * 64];
__device__ uint4 g_wh[3 * 4608];   // fp16 weights, B layout [layer][t][oc][ci]

// ---------------- warp mma (fp16 in, f32 acc) ----------------
__device__ __forceinline__ void mma16816(float* d, uint32_t a0, uint32_t a1,
                                         uint32_t a2, uint32_t a3,
                                         uint32_t b0, uint32_t b1) {
    asm volatile(
        "mma.sync.aligned.m16n8k16.row.col.f32.f16.f16.f32 "
        "{%0,%1,%2,%3}, {%4,%5,%6,%7}, {%8,%9}, {%0,%1,%2,%3};"
        : "+f"(d[0]), "+f"(d[1]), "+f"(d[2]), "+f"(d[3])
        : "r"(a0), "r"(a1), "r"(a2), "r"(a3), "r"(b0), "r"(b1));
}
__device__ __forceinline__ uint32_t packf2(float a, float b) {
    __half2 h = __floats2half2_rn(a, b);
    return *(uint32_t*)&h;
}

// ---------------- wconv: transpose + fp16-convert conv weights once ----------------
__global__ void __launch_bounds__(256) wconv_kernel(
    const float* __restrict__ k2, const float* __restrict__ k3,
    const float* __restrict__ k4, uint4* __restrict__ wh)
{
    int idx = blockIdx.x * 256 + threadIdx.x;
    if (idx >= 3 * 4608) return;
    int layer = idx / 4608, rem = idx - layer * 4608;
    const float* w = (layer == 0) ? k2 : ((layer == 1) ? k3 : k4);
    int row = rem >> 3, ch = rem & 7;       // row = t*64 + oc
    int t = row >> 6, oc = row & 63, ci0 = ch * 8;
    __half h[8];
#pragma unroll
    for (int j = 0; j < 8; j++)
        h[j] = __float2half_rn(w[t * 4096 + (ci0 + j) * 64 + oc]);
    wh[idx] = *(uint4*)h;
}

// ================= conv1mma2: layer 1 (unchanged R14) =================
__global__ void __launch_bounds__(256) conv1mma2_kernel(
    const float* __restrict__ xs, const float* __restrict__ xq,
    const float* __restrict__ w, const float* __restrict__ bias,
    float* __restrict__ pool1, float* __restrict__ part)
{
    constexpr int WP = 86, P = WP * WP;
    constexpr int PENT = 96 + P + 96;
    constexpr int AR = 80;
    constexpr int OFF_P   = 1024;
    constexpr int OFF_B   = OFF_P + PENT * 12;
    constexpr int OFF_RAW = OFF_B + 64 * AR;

    extern __shared__ __align__(16) char smem[];
    int tid = threadIdx.x;
    int g = blockIdx.x;
    float* bias_sh = (float*)(smem + 16);
    if (tid < 64) bias_sh[tid] = bias[tid];

    {
        int b = g & 31, slot = g >> 5;
        const float* src = (slot < 20)
            ? (xs + (size_t)(b * 20 + slot) * 84 * 84 * 3)
            : (xq + (size_t)(b * 5 + (slot - 20)) * 84 * 84 * 3);
        float* Pp = (float*)(smem + OFF_P);
        for (int i = tid; i < PENT * 3; i += 256) {
            int sp = i / 3 - 96;
            int c = i - (sp + 96) * 3;
            float v = 0.f;
            if (sp >= 0 && sp < P) {
                int py = sp / WP, px = sp - py * WP;
                if (px >= 1 && px <= 84 && py >= 1 && py <= 84)
                    v = src[(size_t)((py - 1) * 84 + (px - 1)) * 3 + c];
            }
            Pp[i] = v;
        }
    }
    for (int i = tid; i < 64 * 32; i += 256) {
        int oc = i >> 5, k = i & 31;
        float v = (k < 27) ? w[k * 64 + oc] : 0.f;
        *(__half*)(smem + OFF_B + oc * AR + k * 2) = __float2half_rn(v);
    }
    __syncthreads();

    int warp = tid >> 5, lane = tid & 31;
    int g_row = lane >> 2, four = lane & 3;
    int nmt = (warp < 6) ? 3 : 2;

    int rel[8];
#pragma unroll
    for (int kc = 0; kc < 2; kc++)
#pragma unroll
        for (int kh = 0; kh < 2; kh++)
#pragma unroll
            for (int h = 0; h < 2; h++) {
                int k = kc * 16 + kh * 8 + four * 2 + h;
                int t = k / 3, c = k - 3 * t;
                int shift = (t / 3 - 1) * WP + (t % 3 - 1);
                rel[kc * 4 + kh * 2 + h] = shift * 3 + c;
            }

    const float* Pimg = (float*)(smem + OFF_P) + 96 * 3;
    float* rawp = (float*)(smem + OFF_RAW);

    float ps[8][2], qs[8][2];
#pragma unroll
    for (int nt = 0; nt < 8; nt++) { ps[nt][0]=0.f; ps[nt][1]=0.f; qs[nt][0]=0.f; qs[nt][1]=0.f; }

    for (int yp2 = 0; yp2 < 21; yp2++) {
        int s0 = (4 * yp2 + 1) * WP;
        float d[3][8][4];
#pragma unroll
        for (int im = 0; im < 3; im++)
#pragma unroll
            for (int nt = 0; nt < 8; nt++)
#pragma unroll
                for (int i = 0; i < 4; i++) d[im][nt][i] = 0.f;

#pragma unroll
        for (int kc = 0; kc < 2; kc++)
#pragma unroll
            for (int im = 0; im < 3; im++) {
                if (im >= nmt) break;
                int mt = warp + im * 8;
                uint32_t ah[4], al[4];
#pragma unroll
                for (int r = 0; r < 4; r++) {
                    int row = mt * 16 + g_row + (r & 1) * 8;
                    int base = (s0 + row) * 3;
                    int kh = r >> 1;
                    float v0 = Pimg[base + rel[kc * 4 + kh * 2 + 0]];
                    float v1 = Pimg[base + rel[kc * 4 + kh * 2 + 1]];
                    uint32_t hh = packf2(v0, v1);
                    float2 hb = __half22float2(*(__half2*)&hh);
                    al[r] = packf2(v0 - hb.x, v1 - hb.y);
                    ah[r] = hh;
                }
#pragma unroll
                for (int nt = 0; nt < 8; nt++) {
                    const char* bp = smem + OFF_B + (nt * 8 + g_row) * AR + kc * 32 + four * 4;
                    uint32_t b0 = *(const uint32_t*)bp;
                    uint32_t b1 = *(const uint32_t*)(bp + 16);
                    mma16816(d[im][nt], ah[0], ah[1], ah[2], ah[3], b0, b1);
                    mma16816(d[im][nt], al[0], al[1], al[2], al[3], b0, b1);
                }
            }

#pragma unroll
        for (int im = 0; im < 3; im++) {
            if (im >= nmt) break;
            int mt = warp + im * 8;
#pragma unroll
            for (int rr = 0; rr < 2; rr++) {
                int m = mt * 16 + g_row + rr * 8;
                bool stat = false;
                if (m < 344) {
                    int px = m % WP;
                    stat = (px >= 1 && px <= 84);
                }
#pragma unroll
                for (int nt = 0; nt < 8; nt++) {
                    int oc = nt * 8 + four * 2;
                    float vx = d[im][nt][rr * 2]     + bias_sh[oc];
                    float vy = d[im][nt][rr * 2 + 1] + bias_sh[oc + 1];
                    *(float2*)(rawp + m * 64 + oc) = make_float2(vx, vy);
                    if (stat) {
                        ps[nt][0] += vx; qs[nt][0] += vx * vx;
                        ps[nt][1] += vy; qs[nt][1] += vy * vy;
                    }
                }
            }
        }
        __syncthreads();
        for (int i = tid; i < 2 * 42 * 64; i += 256) {
            int lpr = i / (42 * 64);
            int rest = i - lpr * (42 * 64);
            int ox = rest >> 6, c = rest & 63;
            int m0 = lpr * 172 + 2 * ox + 1;
            float v = fmaxf(fmaxf(rawp[m0 * 64 + c], rawp[(m0 + 1) * 64 + c]),
                            fmaxf(rawp[(m0 + WP) * 64 + c], rawp[(m0 + WP + 1) * 64 + c]));
            pool1[((size_t)g * 1764 + (2 * yp2 + lpr) * 42 + ox) * 64 + c] = v;
        }
        __syncthreads();
    }

#pragma unroll
    for (int nt = 0; nt < 8; nt++)
#pragma unroll
        for (int j = 0; j < 2; j++) {
#pragma unroll
            for (int off = 16; off >= 4; off >>= 1) {
                ps[nt][j] += __shfl_down_sync(~0u, ps[nt][j], off);
                qs[nt][j] += __shfl_down_sync(~0u, qs[nt][j], off);
            }
        }
    float* wst = rawp;
    if (lane < 4) {
#pragma unroll
        for (int nt = 0; nt < 8; nt++)
#pragma unroll
            for (int j = 0; j < 2; j++) {
                int oc = nt * 8 + lane * 2 + j;
                wst[warp * 128 + oc]      = ps[nt][j];
                wst[warp * 128 + 64 + oc] = qs[nt][j];
            }
    }
    __syncthreads();
    if (tid < 128) {
        float s = 0.f;
#pragma unroll
        for (int wi = 0; wi < 8; wi++) s += wst[wi * 128 + tid];
        part[(size_t)g * 128 + tid] = s;
    }
}

// ================= mmaconv: L2-4, multi-image blocks, vectorized B-fill =================
template <int NX, int TR, int NT, int IMGS>
__global__ void __launch_bounds__(256) mmaconv_kernel(
    const float* __restrict__ in, const float* __restrict__ partin,
    const float* __restrict__ gamma, const float* __restrict__ beta, float invPrev,
    const uint4* __restrict__ whl, const float* __restrict__ bias,
    float* __restrict__ pooled, float* __restrict__ partout)
{
    constexpr int W = NX + 2, PIX = NX * NX, Np = NX / 2;
    constexpr int SROWS = (TR + 4) * W;
    constexpr int SROW = 144;
    constexpr int BTAP = 64 * SROW;
    constexpr int OFF_B  = 1024;
    constexpr int OFF_SH = OFF_B + 9 * BTAP;
    constexpr int OFF_SL = OFF_SH + SROWS * SROW;

    extern __shared__ __align__(16) char smem[];
    int tid = threadIdx.x;
    int g0 = blockIdx.x * IMGS, slot = g0 >> 5;   // same slot for all IMGS images
    float* bias_sh = (float*)(smem + 16);
    float* ab_sh   = (float*)(smem + 304);
    if (tid < 64) bias_sh[tid] = bias[tid];
    if (tid >= 64 && tid < 128) {
        int c = tid - 64;
        float s = 0.f, q = 0.f;
        for (int b = 0; b < 32; b++) {
            s += partin[(size_t)(slot * 32 + b) * 128 + c];
            q += partin[(size_t)(slot * 32 + b) * 128 + 64 + c];
        }
        float mn = s * invPrev;
        float var = q * invPrev - mn * mn;
        float sc = gamma[c] * rsqrtf(var + 1e-3f);
        ab_sh[c * 2] = sc;
        ab_sh[c * 2 + 1] = beta[c] - mn * sc;
    }
    // vectorized B-fill from pre-converted global fp16
    for (int i = tid; i < 4608; i += 256) {
        int row = i >> 3, ch = i & 7;
        *(uint4*)(smem + OFF_B + row * SROW + ch * 16) = whl[i];
    }

    int warp = tid >> 5, lane = tid & 31;
    int g_row = lane >> 2, four = lane & 3;
    float* rawp = (float*)(smem + OFF_SH);

    for (int img = 0; img < IMGS; img++) {
        int g = g0 + img;
        float ps[8][2], qs[8][2];
#pragma unroll
        for (int nt = 0; nt < 8; nt++) { ps[nt][0]=0.f; ps[nt][1]=0.f; qs[nt][0]=0.f; qs[nt][1]=0.f; }

        for (int tile = 0; tile < NT; tile++) {
            int r0 = tile * TR;
            int rows = (NX - r0 < TR) ? (NX - r0) : TR;
            int pxc = rows * NX;
            int mtiles = (pxc + 15) >> 4;
            bool v0 = warp < mtiles, v1 = warp + 8 < mtiles;

            __syncthreads();
            int nstrip = (rows + 2) * W;
            for (int i = tid; i < nstrip * 16; i += 256) {
                int s = i >> 4, c4 = (i & 15) * 4;
                int p = r0 + s / W, px = s % W;
                float4 v = make_float4(0.f, 0.f, 0.f, 0.f);
                if (px >= 1 && px <= NX && p >= 1 && p <= NX) {
                    float4 rv = *(const float4*)&in[((size_t)g * PIX + (p - 1) * NX + (px - 1)) * 64 + c4];
                    v.x = fmaxf(fmaf(ab_sh[(c4 + 0) * 2], rv.x, ab_sh[(c4 + 0) * 2 + 1]), 0.f);
                    v.y = fmaxf(fmaf(ab_sh[(c4 + 1) * 2], rv.y, ab_sh[(c4 + 1) * 2 + 1]), 0.f);
                    v.z = fmaxf(fmaf(ab_sh[(c4 + 2) * 2], rv.z, ab_sh[(c4 + 2) * 2 + 1]), 0.f);
                    v.w = fmaxf(fmaf(ab_sh[(c4 + 3) * 2], rv.w, ab_sh[(c4 + 3) * 2 + 1]), 0.f);
                }
                uint32_t hx = packf2(v.x, v.y), hz = packf2(v.z, v.w);
                float2 bx = __half22float2(*(__half2*)&hx);
                float2 bz = __half22float2(*(__half2*)&hz);
                *(uint2*)(smem + OFF_SH + s * SROW + c4 * 2) = make_uint2(hx, hz);
                *(uint2*)(smem + OFF_SL + s * SROW + c4 * 2) =
                    make_uint2(packf2(v.x - bx.x, v.y - bx.y), packf2(v.z - bz.x, v.w - bz.y));
            }
            __syncthreads();

            int rA[2][2] = {{0, 0}, {0, 0}};
#pragma unroll
            for (int im = 0; im < 2; im++) {
                if (im == 0 ? v0 : v1) {
#pragma unroll
                    for (int h = 0; h < 2; h++) {
                        int ml = (warp + im * 8) * 16 + h * 8 + g_row;
                        rA[im][h] = (ml / NX) * W + (ml % NX);
                    }
                }
            }

            float d[2][8][4];
#pragma unroll
            for (int mt = 0; mt < 2; mt++)
#pragma unroll
                for (int nt = 0; nt < 8; nt++)
#pragma unroll
                    for (int i = 0; i < 4; i++) d[mt][nt][i] = 0.f;

#pragma unroll 1
            for (int t = 0; t < 9; t++) {
                int rshift = (t / 3) * W + (t % 3);
                const char* bt = smem + OFF_B + t * BTAP;
#pragma unroll
                for (int kc = 0; kc < 4; kc++) {
                    int cb = kc * 32 + four * 4;
                    if (v0) {
                        uint32_t a0h[4], a0l[4], a1h[4], a1l[4];
                        {
                            const char* p0 = smem + OFF_SH + (rA[0][0] + rshift) * SROW + cb;
                            const char* p1 = smem + OFF_SH + (rA[0][1] + rshift) * SROW + cb;
                            const char* q0 = smem + OFF_SL + (rA[0][0] + rshift) * SROW + cb;
                            const char* q1 = smem + OFF_SL + (rA[0][1] + rshift) * SROW + cb;
                            a0h[0] = *(const uint32_t*)p0; a0h[1] = *(const uint32_t*)p1;
                            a0h[2] = *(const uint32_t*)(p0 + 16); a0h[3] = *(const uint32_t*)(p1 + 16);
                            a0l[0] = *(const uint32_t*)q0; a0l[1] = *(const uint32_t*)q1;
                            a0l[2] = *(const uint32_t*)(q0 + 16); a0l[3] = *(const uint32_t*)(q1 + 16);
                        }
                        if (v1) {
                            const char* p0 = smem + OFF_SH + (rA[1][0] + rshift) * SROW + cb;
                            const char* p1 = smem + OFF_SH + (rA[1][1] + rshift) * SROW + cb;
                            const char* q0 = smem + OFF_SL + (rA[1][0] + rshift) * SROW + cb;
                            const char* q1 = smem + OFF_SL + (rA[1][1] + rshift) * SROW + cb;
                            a1h[0] = *(const uint32_t*)p0; a1h[1] = *(const uint32_t*)p1;
                            a1h[2] = *(const uint32_t*)(p0 + 16); a1h[3] = *(const uint32_t*)(p1 + 16);
                            a1l[0] = *(const uint32_t*)q0; a1l[1] = *(const uint32_t*)q1;
                            a1l[2] = *(const uint32_t*)(q0 + 16); a1l[3] = *(const uint32_t*)(q1 + 16);
                        }
#pragma unroll
                        for (int nt = 0; nt < 8; nt++) {
                            const char* bp = bt + (nt * 8 + g_row) * SROW + cb;
                            uint32_t b0 = *(const uint32_t*)bp;
                            uint32_t b1 = *(const uint32_t*)(bp + 16);
                            mma16816(d[0][nt], a0h[0], a0h[1], a0h[2], a0h[3], b0, b1);
                            mma16816(d[0][nt], a0l[0], a0l[1], a0l[2], a0l[3], b0, b1);
                            if (v1) {
                                mma16816(d[1][nt], a1h[0], a1h[1], a1h[2], a1h[3], b0, b1);
                                mma16816(d[1][nt], a1l[0], a1l[1], a1l[2], a1l[3], b0, b1);
                            }
                        }
                    }
                }
            }
            __syncthreads();

#pragma unroll
            for (int im = 0; im < 2; im++) {
                if (im == 0 ? !v0 : !v1) continue;
                int mt = warp + im * 8;
#pragma unroll
                for (int rr = 0; rr < 2; rr++) {
                    int ml = mt * 16 + g_row + rr * 8;
                    if (ml < pxc) {
#pragma unroll
                        for (int nt = 0; nt < 8; nt++) {
                            int oc = nt * 8 + four * 2;
                            float vx = d[im][nt][rr * 2]     + bias_sh[oc];
                            float vy = d[im][nt][rr * 2 + 1] + bias_sh[oc + 1];
                            *(float2*)(rawp + ml * 64 + oc) = make_float2(vx, vy);
                            ps[nt][0] += vx; qs[nt][0] += vx * vx;
                            ps[nt][1] += vy; qs[nt][1] += vy * vy;
                        }
                    }
                }
            }
            __syncthreads();

            int pr0 = r0 >> 1;
            int rend = r0 + rows; if (rend > 2 * Np) rend = 2 * Np;
            int prn = (rend >> 1) - pr0;
            for (int i = tid; i < prn * Np * 64; i += 256) {
                int lpr = i / (Np * 64);
                int rest = i - lpr * (Np * 64);
                int ox = rest >> 6, c = rest & 63;
                int base = ((2 * lpr) * NX + 2 * ox) * 64 + c;
                float v = fmaxf(fmaxf(rawp[base], rawp[base + 64]),
                                fmaxf(rawp[base + NX * 64], rawp[base + NX * 64 + 64]));
                pooled[((size_t)g * (Np * Np) + (pr0 + lpr) * Np + ox) * 64 + c] = v;
            }
        }

        // stats reduction for this image
#pragma unroll
        for (int nt = 0; nt < 8; nt++)
#pragma unroll
            for (int j = 0; j < 2; j++) {
#pragma unroll
                for (int off = 16; off >= 4; off >>= 1) {
                    ps[nt][j] += __shfl_down_sync(~0u, ps[nt][j], off);
                    qs[nt][j] += __shfl_down_sync(~0u, qs[nt][j], off);
                }
            }
        __syncthreads();
        float* wst = (float*)(smem + OFF_SH);
        if (lane < 4) {
#pragma unroll
            for (int nt = 0; nt < 8; nt++)
#pragma unroll
                for (int j = 0; j < 2; j++) {
                    int oc = nt * 8 + lane * 2 + j;
                    wst[warp * 128 + oc]      = ps[nt][j];
                    wst[warp * 128 + 64 + oc] = qs[nt][j];
                }
        }
        __syncthreads();
        if (tid < 128) {
            float s = 0.f;
#pragma unroll
            for (int wi = 0; wi < 8; wi++) s += wst[wi * 128 + tid];
            partout[(size_t)g * 128 + tid] = s;
        }
    }
}

// ---------------- gemmz: fused BN4 affine prologue (unchanged R14) ----------------
__global__ void __launch_bounds__(256) gemmz_kernel(
    const float* __restrict__ emb, const float* __restrict__ partin,
    const float* __restrict__ gamma, const float* __restrict__ beta, float invPrev,
    const float* __restrict__ fk, const float* __restrict__ fb,
    const float* __restrict__ bk, const float* __restrict__ bb,
    float* __restrict__ Z)
{
    int gb = blockIdx.x, dir = blockIdx.y;
    const float* W = dir ? bk : fk;
    const float* bias = dir ? bb : fb;
    float* Zo = Z + (size_t)dir * NIMG * 128;
    __shared__ float A_sh[32][33];
    __shared__ __align__(16) float B_sh[32][128];
    __shared__ float ab_sh[128];
    int tid = threadIdx.x, jj = tid & 31, gg = tid >> 5;
    if (tid < 64) {
        float s = 0.f, q = 0.f;
        for (int b = 0; b < 32; b++) {
            s += partin[(size_t)(gb * 32 + b) * 128 + tid];
            q += partin[(size_t)(gb * 32 + b) * 128 + 64 + tid];
        }
        float mn = s * invPrev;
        float var = q * invPrev - mn * mn;
        float sc = gamma[tid] * rsqrtf(var + 1e-3f);
        ab_sh[tid * 2] = sc;
        ab_sh[tid * 2 + 1] = beta[tid] - mn * sc;
    }
    __syncthreads();
    float acc[4][4] = {};
    for (int d0 = 0; d0 < 1600; d0 += 32) {
        for (int i = tid; i < 1024; i += 256) {
            int r = i >> 5, dd = i & 31, d = d0 + dd, c = d & 63;
            float raw = emb[(size_t)(gb * 32 + r) * 1600 + d];
            A_sh[r][dd] = fmaxf(fmaf(ab_sh[c * 2], raw, ab_sh[c * 2 + 1]), 0.f);
        }
        for (int i = tid; i < 4096; i += 256)
            B_sh[i >> 7][i & 127] = W[(size_t)(d0 + (i >> 7)) * 128 + (i & 127)];
        __syncthreads();
#pragma unroll
        for (int dd = 0; dd < 32; dd++) {
            float4 bv = *(const float4*)&B_sh[dd][jj * 4];
#pragma unroll
            for (int r = 0; r < 4; r++) {
                float a = A_sh[gg * 4 + r][dd];
                acc[r][0] += a * bv.x; acc[r][1] += a * bv.y;
                acc[r][2] += a * bv.z; acc[r][3] += a * bv.w;
            }
        }
        __syncthreads();
    }
#pragma unroll
    for (int r = 0; r < 4; r++)
#pragma unroll
        for (int c = 0; c < 4; c++)
            Zo[(size_t)(gb * 32 + gg * 4 + r) * 128 + jj * 4 + c] = acc[r][c] + bias[jj * 4 + c];
}

// ---------------- LSTM ----------------
__global__ void __launch_bounds__(672) lstm_kernel(
    const float* __restrict__ Z,
    const float* __restrict__ fr, const float* __restrict__ br,
    float* __restrict__ outs)
{
    int q = blockIdx.x, dir = blockIdx.y;
    const float* R = dir ? br : fr;
    const float* Zp = Z + (size_t)dir * NIMG * 128;
    __shared__ float Wh[32][128];
    __shared__ float h_sh[21][32], c_sh[21][32];
    int tid = threadIdx.x;
    for (int i = tid; i < 4096; i += 672) Wh[i >> 7][i & 127] = R[i];
    int p = tid >> 5, j = tid & 31;
    h_sh[p][j] = 0.f; c_sh[p][j] = 0.f;
    __syncthreads();
    int slot = (p < 20) ? p : (20 + q);
    for (int step = 0; step < 32; step++) {
        int t = dir ? (31 - step) : step;
        const float* zr = Zp + (size_t)(slot * 32 + t) * 128;
        float z0 = zr[j], z1 = zr[32 + j], z2 = zr[64 + j], z3 = zr[96 + j];
#pragma unroll
        for (int k = 0; k < 32; k++) {
            float hk = h_sh[p][k];
            z0 += hk * Wh[k][j]; z1 += hk * Wh[k][32 + j];
            z2 += hk * Wh[k][64 + j]; z3 += hk * Wh[k][96 + j];
        }
        float ig = 1.f / (1.f + expf(-z0)), fg = 1.f / (1.f + expf(-z1));
        float gg = tanhf(z2), og = 1.f / (1.f + expf(-z3));
        float cn = fg * c_sh[p][j] + ig * gg;
        float hn = og * tanhf(cn);
        __syncthreads();
        h_sh[p][j] = hn; c_sh[p][j] = cn;
        outs[(size_t)((q * 21 + p) * 32 + t) * 64 + dir * 32 + j] = hn;
        __syncthreads();
    }
}

// ---------------- attention + CE + acc ----------------
__global__ void __launch_bounds__(256) final_kernel(
    const float* __restrict__ outs,
    const int* __restrict__ ysup, const int* __restrict__ yqry,
    float* __restrict__ out)
{
    __shared__ float ce_sh[160], eq_sh[160];
    int tid = threadIdx.x;
    if (tid < 160) {
        int q = tid / 32, b = tid % 32;
        const float* qry = outs + (size_t)((q * 21 + 20) * 32 + b) * 64;
        float logit[20];
        for (int s = 0; s < 20; s++) {
            const float* sp = outs + (size_t)((q * 21 + s) * 32 + b) * 64;
            float d = 0.f, n2 = 0.f;
            for (int k = 0; k < 64; k++) { d += qry[k] * sp[k]; n2 += sp[k] * sp[k]; }
            logit[s] = d * rsqrtf(fmaxf(n2, 1e-10f));
        }
        float mx = logit[0];
        for (int s = 1; s < 20; s++) mx = fmaxf(mx, logit[s]);
        float den = 0.f;
        for (int s = 0; s < 20; s++) { logit[s] = expf(logit[s] - mx); den += logit[s]; }
        float invden = 1.f / den;
        float preds[20];
        for (int wq = 0; wq < 20; wq++) preds[wq] = 0.f;
        for (int s = 0; s < 20; s++) preds[ysup[b * 20 + s]] += logit[s] * invden;
        int yq = yqry[b * 5 + q];
        float pv = fminf(fmaxf(preds[yq], 1e-7f), 1.f - 1e-7f);
        ce_sh[tid] = -logf(pv);
        int best = 0;
        for (int wq = 1; wq < 20; wq++) if (preds[wq] > preds[best]) best = wq;
        eq_sh[tid] = (best == yq) ? 1.f : 0.f;
    }
    __syncthreads();
    if (tid < 32) {
        float s = 0.f;
        for (int q = 0; q < 5; q++) s += ce_sh[q * 32 + tid];
        out[tid] = s * 0.2f;
    }
    if (tid == 0) {
        float s = 0.f;
        for (int i = 0; i < 160; i++) s += eq_sh[i];
        out[32] = s / 160.f;
    }
}

// ---------------- launch ----------------
extern "C" void kernel_launch(void* const* d_in, const int* in_sizes, int n_in,
                              void* d_out, int out_size)
{
    (void)in_sizes; (void)n_in; (void)out_size;
    const float* xs = (const float*)d_in[0];
    const int* ysup = (const int*)d_in[1];
    const float* xq = (const float*)d_in[2];
    const int* yqry = (const int*)d_in[3];
    const float *k1=(const float*)d_in[4],  *b1=(const float*)d_in[5],  *g1=(const float*)d_in[6],  *be1=(const float*)d_in[7];
    const float *k2=(const float*)d_in[8],  *b2=(const float*)d_in[9],  *g2=(const float*)d_in[10], *be2=(const float*)d_in[11];
    const float *k3=(const float*)d_in[12], *b3=(const float*)d_in[13], *g3=(const float*)d_in[14], *be3=(const float*)d_in[15];
    const float *k4=(const float*)d_in[16], *b4=(const float*)d_in[17], *g4=(const float*)d_in[18], *be4=(const float*)d_in[19];
    const float *fk=(const float*)d_in[20], *fr=(const float*)d_in[21], *fb=(const float*)d_in[22];
    const float *bk=(const float*)d_in[23], *br=(const float*)d_in[24], *bb=(const float*)d_in[25];

    float *pool1, *pool2, *pool3, *pool4, *partA, *partB, *Z, *outs;
    uint4* wh;
    cudaGetSymbolAddress((void**)&pool1, g_pool1);
    cudaGetSymbolAddress((void**)&pool2, g_pool2);
    cudaGetSymbolAddress((void**)&pool3, g_pool3);
    cudaGetSymbolAddress((void**)&pool4, g_pool4);
    cudaGetSymbolAddress((void**)&partA, g_partA);
    cudaGetSymbolAddress((void**)&partB, g_partB);
    cudaGetSymbolAddress((void**)&Z, g_Z);
    cudaGetSymbolAddress((void**)&outs, g_outs);
    cudaGetSymbolAddress((void**)&wh, g_wh);

    const int SM1  = 1024 + 7588 * 12 + 64 * 80 + 352 * 64 * 4;          // 187312
    const int SM42 = 1024 + 9 * 64 * 144 + 2 * (10 * 44) * 144;          // 210688
    const int SM21 = 1024 + 9 * 64 * 144 + 2 * (16 * 23) * 144;          // 189952
    const int SM10 = 1024 + 9 * 64 * 144 + 2 * (14 * 12) * 144;          // 132352
    cudaFuncSetAttribute(conv1mma2_kernel,          cudaFuncAttributeMaxDynamicSharedMemorySize, SM1);
    cudaFuncSetAttribute(mmaconv_kernel<42,6,7,1>,  cudaFuncAttributeMaxDynamicSharedMemorySize, SM42);
    cudaFuncSetAttribute(mmaconv_kernel<21,12,2,2>, cudaFuncAttributeMaxDynamicSharedMemorySize, SM21);
    cudaFuncSetAttribute(mmaconv_kernel<10,10,1,4>, cudaFuncAttributeMaxDynamicSharedMemorySize, SM10);

    // weight pre-conversion (all 3 MMA layers)
    wconv_kernel<<<(3 * 4608 + 255) / 256, 256>>>(k2, k3, k4, wh);
    // L1 -> pool1, partA
    conv1mma2_kernel<<<NIMG, 256, SM1>>>(xs, xq, k1, b1, pool1, partA);
    // L2 -> pool2, partB
    mmaconv_kernel<42,6,7,1><<<NIMG, 256, SM42>>>(pool1, partA, g1, be1, 1.f / (32.f * 7056.f),
                                                  wh, b2, pool2, partB);
    // L3 (2 imgs/block) -> pool3, partA
    mmaconv_kernel<21,12,2,2><<<NIMG / 2, 256, SM21>>>(pool2, partB, g2, be2, 1.f / (32.f * 1764.f),
                                                       wh + 4608, b3, pool3, partA);
    // L4 (4 imgs/block) -> pool4, partB
    mmaconv_kernel<10,10,1,4><<<NIMG / 4, 256, SM10>>>(pool3, partA, g3, be3, 1.f / (32.f * 441.f),
                                                       wh + 2 * 4608, b4, pool4, partB);
    // gemmz: BN4 from partB
    gemmz_kernel<<<dim3(25, 2), 256>>>(pool4, partB, g4, be4, 1.f / (32.f * 100.f),
                                       fk, fb, bk, bb, Z);
    lstm_kernel<<<dim3(5, 2), 672>>>(Z, fr, br, outs);
    final_kernel<<<1, 256>>>(outs, ysup, yqry, (float*)d_out);
}

// round 16
// speedup vs baseline: 1.4975x; 1.1915x over previous
#include <cuda_runtime.h>
#include <cuda_fp16.h>
#include <math.h>
#include <stdint.h>

#define NIMG 800
typedef unsigned long long u64;

// ---------------- scratch ----------------
__device__ float g_pool1[(size_t)NIMG * 1764 * 64];
__device__ float g_pool2[(size_t)NIMG * 441 * 64];
__device__ float g_pool3[(size_t)NIMG * 100 * 64];
__device__ float g_pool4[(size_t)NIMG * 25 * 64];
__device__ float g_partA[(size_t)NIMG * 128];
__device__ float g_partB[(size_t)NIMG * 128];
__device__ float g_Z[2 * NIMG * 128];
__device__ float g_outs[5 * 21 * 32 * 64];
__device__ uint4 g_wh[3 * 4608];   // fp16 weights, B layout [layer][t][oc][ci]

// ---------------- warp mma (fp16 in, f32 acc) ----------------
__device__ __forceinline__ void mma16816(float* d, uint32_t a0, uint32_t a1,
                                         uint32_t a2, uint32_t a3,
                                         uint32_t b0, uint32_t b1) {
    asm volatile(
        "mma.sync.aligned.m16n8k16.row.col.f32.f16.f16.f32 "
        "{%0,%1,%2,%3}, {%4,%5,%6,%7}, {%8,%9}, {%0,%1,%2,%3};"
        : "+f"(d[0]), "+f"(d[1]), "+f"(d[2]), "+f"(d[3])
        : "r"(a0), "r"(a1), "r"(a2), "r"(a3), "r"(b0), "r"(b1));
}
__device__ __forceinline__ uint32_t packf2(float a, float b) {
    __half2 h = __floats2half2_rn(a, b);
    return *(uint32_t*)&h;
}

// ---------------- wconv: transpose + fp16-convert conv weights once ----------------
__global__ void __launch_bounds__(256) wconv_kernel(
    const float* __restrict__ k2, const float* __restrict__ k3,
    const float* __restrict__ k4, uint4* __restrict__ wh)
{
    int idx = blockIdx.x * 256 + threadIdx.x;
    if (idx >= 3 * 4608) return;
    int layer = idx / 4608, rem = idx - layer * 4608;
    const float* w = (layer == 0) ? k2 : ((layer == 1) ? k3 : k4);
    int row = rem >> 3, ch = rem & 7;
    int t = row >> 6, oc = row & 63, ci0 = ch * 8;
    __half h[8];
#pragma unroll
    for (int j = 0; j < 8; j++)
        h[j] = __float2half_rn(w[t * 4096 + (ci0 + j) * 64 + oc]);
    wh[idx] = *(uint4*)h;
}

// ================= conv1mma2: layer 1, 512 threads, 16 warps =================
__global__ void __launch_bounds__(512) conv1mma2_kernel(
    const float* __restrict__ xs, const float* __restrict__ xq,
    const float* __restrict__ w, const float* __restrict__ bias,
    float* __restrict__ pool1, float* __restrict__ part)
{
    constexpr int WP = 86, P = WP * WP;
    constexpr int PENT = 96 + P + 96;
    constexpr int AR = 80;
    constexpr int OFF_P   = 1024;
    constexpr int OFF_B   = OFF_P + PENT * 12;
    constexpr int OFF_RAW = OFF_B + 64 * AR;

    extern __shared__ __align__(16) char smem[];
    int tid = threadIdx.x;
    int g = blockIdx.x;
    float* bias_sh = (float*)(smem + 16);
    if (tid < 64) bias_sh[tid] = bias[tid];

    {
        int b = g & 31, slot = g >> 5;
        const float* src = (slot < 20)
            ? (xs + (size_t)(b * 20 + slot) * 84 * 84 * 3)
            : (xq + (size_t)(b * 5 + (slot - 20)) * 84 * 84 * 3);
        float* Pp = (float*)(smem + OFF_P);
        for (int i = tid; i < PENT * 3; i += 512) {
            int sp = i / 3 - 96;
            int c = i - (sp + 96) * 3;
            float v = 0.f;
            if (sp >= 0 && sp < P) {
                int py = sp / WP, px = sp - py * WP;
                if (px >= 1 && px <= 84 && py >= 1 && py <= 84)
                    v = src[(size_t)((py - 1) * 84 + (px - 1)) * 3 + c];
            }
            Pp[i] = v;
        }
    }
    for (int i = tid; i < 64 * 32; i += 512) {
        int oc = i >> 5, k = i & 31;
        float v = (k < 27) ? w[k * 64 + oc] : 0.f;
        *(__half*)(smem + OFF_B + oc * AR + k * 2) = __float2half_rn(v);
    }
    __syncthreads();

    int warp = tid >> 5, lane = tid & 31;
    int g_row = lane >> 2, four = lane & 3;
    int nmt = (warp < 6) ? 2 : 1;      // 22 mtiles: warps 0-5 take {w, 16+w}, rest take {w}

    int rel[8];
#pragma unroll
    for (int kc = 0; kc < 2; kc++)
#pragma unroll
        for (int kh = 0; kh < 2; kh++)
#pragma unroll
            for (int h = 0; h < 2; h++) {
                int k = kc * 16 + kh * 8 + four * 2 + h;
                int t = k / 3, c = k - 3 * t;
                int shift = (t / 3 - 1) * WP + (t % 3 - 1);
                rel[kc * 4 + kh * 2 + h] = shift * 3 + c;
            }

    const float* Pimg = (float*)(smem + OFF_P) + 96 * 3;
    float* rawp = (float*)(smem + OFF_RAW);

    float ps[8][2], qs[8][2];
#pragma unroll
    for (int nt = 0; nt < 8; nt++) { ps[nt][0]=0.f; ps[nt][1]=0.f; qs[nt][0]=0.f; qs[nt][1]=0.f; }

    for (int yp2 = 0; yp2 < 21; yp2++) {
        int s0 = (4 * yp2 + 1) * WP;
        float d[2][8][4];
#pragma unroll
        for (int im = 0; im < 2; im++)
#pragma unroll
            for (int nt = 0; nt < 8; nt++)
#pragma unroll
                for (int i = 0; i < 4; i++) d[im][nt][i] = 0.f;

#pragma unroll
        for (int kc = 0; kc < 2; kc++)
#pragma unroll
            for (int im = 0; im < 2; im++) {
                if (im >= nmt) break;
                int mt = warp + im * 16;
                uint32_t ah[4], al[4];
#pragma unroll
                for (int r = 0; r < 4; r++) {
                    int row = mt * 16 + g_row + (r & 1) * 8;
                    int base = (s0 + row) * 3;
                    int kh = r >> 1;
                    float v0 = Pimg[base + rel[kc * 4 + kh * 2 + 0]];
                    float v1 = Pimg[base + rel[kc * 4 + kh * 2 + 1]];
                    uint32_t hh = packf2(v0, v1);
                    float2 hb = __half22float2(*(__half2*)&hh);
                    al[r] = packf2(v0 - hb.x, v1 - hb.y);
                    ah[r] = hh;
                }
#pragma unroll
                for (int nt = 0; nt < 8; nt++) {
                    const char* bp = smem + OFF_B + (nt * 8 + g_row) * AR + kc * 32 + four * 4;
                    uint32_t b0 = *(const uint32_t*)bp;
                    uint32_t b1 = *(const uint32_t*)(bp + 16);
                    mma16816(d[im][nt], ah[0], ah[1], ah[2], ah[3], b0, b1);
                    mma16816(d[im][nt], al[0], al[1], al[2], al[3], b0, b1);
                }
            }

#pragma unroll
        for (int im = 0; im < 2; im++) {
            if (im >= nmt) break;
            int mt = warp + im * 16;
#pragma unroll
            for (int rr = 0; rr < 2; rr++) {
                int m = mt * 16 + g_row + rr * 8;
                bool stat = false;
                if (m < 344) {
                    int px = m % WP;
                    stat = (px >= 1 && px <= 84);
                }
#pragma unroll
                for (int nt = 0; nt < 8; nt++) {
                    int oc = nt * 8 + four * 2;
                    float vx = d[im][nt][rr * 2]     + bias_sh[oc];
                    float vy = d[im][nt][rr * 2 + 1] + bias_sh[oc + 1];
                    *(float2*)(rawp + m * 64 + oc) = make_float2(vx, vy);
                    if (stat) {
                        ps[nt][0] += vx; qs[nt][0] += vx * vx;
                        ps[nt][1] += vy; qs[nt][1] += vy * vy;
                    }
                }
            }
        }
        __syncthreads();
        for (int i = tid; i < 2 * 42 * 64; i += 512) {
            int lpr = i / (42 * 64);
            int rest = i - lpr * (42 * 64);
            int ox = rest >> 6, c = rest & 63;
            int m0 = lpr * 172 + 2 * ox + 1;
            float v = fmaxf(fmaxf(rawp[m0 * 64 + c], rawp[(m0 + 1) * 64 + c]),
                            fmaxf(rawp[(m0 + WP) * 64 + c], rawp[(m0 + WP + 1) * 64 + c]));
            pool1[((size_t)g * 1764 + (2 * yp2 + lpr) * 42 + ox) * 64 + c] = v;
        }
        __syncthreads();
    }

#pragma unroll
    for (int nt = 0; nt < 8; nt++)
#pragma unroll
        for (int j = 0; j < 2; j++) {
#pragma unroll
            for (int off = 16; off >= 4; off >>= 1) {
                ps[nt][j] += __shfl_down_sync(~0u, ps[nt][j], off);
                qs[nt][j] += __shfl_down_sync(~0u, qs[nt][j], off);
            }
        }
    float* wst = rawp;
    if (lane < 4) {
#pragma unroll
        for (int nt = 0; nt < 8; nt++)
#pragma unroll
            for (int j = 0; j < 2; j++) {
                int oc = nt * 8 + lane * 2 + j;
                wst[warp * 128 + oc]      = ps[nt][j];
                wst[warp * 128 + 64 + oc] = qs[nt][j];
            }
    }
    __syncthreads();
    if (tid < 128) {
        float s = 0.f;
#pragma unroll
        for (int wi = 0; wi < 16; wi++) s += wst[wi * 128 + tid];
        part[(size_t)g * 128 + tid] = s;
    }
}

// ================= mmaconv: L2-4, 512 threads, 1 mtile/warp =================
template <int NX, int TR, int NT, int IMGS>
__global__ void __launch_bounds__(512) mmaconv_kernel(
    const float* __restrict__ in, const float* __restrict__ partin,
    const float* __restrict__ gamma, const float* __restrict__ beta, float invPrev,
    const uint4* __restrict__ whl, const float* __restrict__ bias,
    float* __restrict__ pooled, float* __restrict__ partout)
{
    constexpr int W = NX + 2, PIX = NX * NX, Np = NX / 2;
    constexpr int SROWS = (TR + 4) * W;
    constexpr int SROW = 144;
    constexpr int BTAP = 64 * SROW;
    constexpr int OFF_B  = 1024;
    constexpr int OFF_SH = OFF_B + 9 * BTAP;
    constexpr int OFF_SL = OFF_SH + SROWS * SROW;

    extern __shared__ __align__(16) char smem[];
    int tid = threadIdx.x;
    int g0 = blockIdx.x * IMGS, slot = g0 >> 5;
    float* bias_sh = (float*)(smem + 16);
    float* ab_sh   = (float*)(smem + 304);
    if (tid < 64) bias_sh[tid] = bias[tid];
    if (tid >= 64 && tid < 128) {
        int c = tid - 64;
        float s = 0.f, q = 0.f;
        for (int b = 0; b < 32; b++) {
            s += partin[(size_t)(slot * 32 + b) * 128 + c];
            q += partin[(size_t)(slot * 32 + b) * 128 + 64 + c];
        }
        float mn = s * invPrev;
        float var = q * invPrev - mn * mn;
        float sc = gamma[c] * rsqrtf(var + 1e-3f);
        ab_sh[c * 2] = sc;
        ab_sh[c * 2 + 1] = beta[c] - mn * sc;
    }
    for (int i = tid; i < 4608; i += 512) {
        int row = i >> 3, ch = i & 7;
        *(uint4*)(smem + OFF_B + row * SROW + ch * 16) = whl[i];
    }

    int warp = tid >> 5, lane = tid & 31;
    int g_row = lane >> 2, four = lane & 3;
    float* rawp = (float*)(smem + OFF_SH);

    for (int img = 0; img < IMGS; img++) {
        int g = g0 + img;
        float ps[8][2], qs[8][2];
#pragma unroll
        for (int nt = 0; nt < 8; nt++) { ps[nt][0]=0.f; ps[nt][1]=0.f; qs[nt][0]=0.f; qs[nt][1]=0.f; }

        for (int tile = 0; tile < NT; tile++) {
            int r0 = tile * TR;
            int rows = (NX - r0 < TR) ? (NX - r0) : TR;
            int pxc = rows * NX;
            int mtiles = (pxc + 15) >> 4;
            bool vw = warp < mtiles;

            __syncthreads();
            int nstrip = (rows + 2) * W;
            for (int i = tid; i < nstrip * 16; i += 512) {
                int s = i >> 4, c4 = (i & 15) * 4;
                int p = r0 + s / W, px = s % W;
                float4 v = make_float4(0.f, 0.f, 0.f, 0.f);
                if (px >= 1 && px <= NX && p >= 1 && p <= NX) {
                    float4 rv = *(const float4*)&in[((size_t)g * PIX + (p - 1) * NX + (px - 1)) * 64 + c4];
                    v.x = fmaxf(fmaf(ab_sh[(c4 + 0) * 2], rv.x, ab_sh[(c4 + 0) * 2 + 1]), 0.f);
                    v.y = fmaxf(fmaf(ab_sh[(c4 + 1) * 2], rv.y, ab_sh[(c4 + 1) * 2 + 1]), 0.f);
                    v.z = fmaxf(fmaf(ab_sh[(c4 + 2) * 2], rv.z, ab_sh[(c4 + 2) * 2 + 1]), 0.f);
                    v.w = fmaxf(fmaf(ab_sh[(c4 + 3) * 2], rv.w, ab_sh[(c4 + 3) * 2 + 1]), 0.f);
                }
                uint32_t hx = packf2(v.x, v.y), hz = packf2(v.z, v.w);
                float2 bx = __half22float2(*(__half2*)&hx);
                float2 bz = __half22float2(*(__half2*)&hz);
                *(uint2*)(smem + OFF_SH + s * SROW + c4 * 2) = make_uint2(hx, hz);
                *(uint2*)(smem + OFF_SL + s * SROW + c4 * 2) =
                    make_uint2(packf2(v.x - bx.x, v.y - bx.y), packf2(v.z - bz.x, v.w - bz.y));
            }
            __syncthreads();

            int rA[2] = {0, 0};
            if (vw) {
#pragma unroll
                for (int h = 0; h < 2; h++) {
                    int ml = warp * 16 + h * 8 + g_row;
                    rA[h] = (ml / NX) * W + (ml % NX);
                }
            }

            float d[8][4];
#pragma unroll
            for (int nt = 0; nt < 8; nt++)
#pragma unroll
                for (int i = 0; i < 4; i++) d[nt][i] = 0.f;

#pragma unroll 1
            for (int t = 0; t < 9; t++) {
                int rshift = (t / 3) * W + (t % 3);
                const char* bt = smem + OFF_B + t * BTAP;
#pragma unroll
                for (int kc = 0; kc < 4; kc++) {
                    int cb = kc * 32 + four * 4;
                    if (vw) {
                        uint32_t ah[4], al[4];
                        const char* p0 = smem + OFF_SH + (rA[0] + rshift) * SROW + cb;
                        const char* p1 = smem + OFF_SH + (rA[1] + rshift) * SROW + cb;
                        const char* q0 = smem + OFF_SL + (rA[0] + rshift) * SROW + cb;
                        const char* q1 = smem + OFF_SL + (rA[1] + rshift) * SROW + cb;
                        ah[0] = *(const uint32_t*)p0; ah[1] = *(const uint32_t*)p1;
                        ah[2] = *(const uint32_t*)(p0 + 16); ah[3] = *(const uint32_t*)(p1 + 16);
                        al[0] = *(const uint32_t*)q0; al[1] = *(const uint32_t*)q1;
                        al[2] = *(const uint32_t*)(q0 + 16); al[3] = *(const uint32_t*)(q1 + 16);
#pragma unroll
                        for (int nt = 0; nt < 8; nt++) {
                            const char* bp = bt + (nt * 8 + g_row) * SROW + cb;
                            uint32_t b0 = *(const uint32_t*)bp;
                            uint32_t b1 = *(const uint32_t*)(bp + 16);
                            mma16816(d[nt], ah[0], ah[1], ah[2], ah[3], b0, b1);
                            mma16816(d[nt], al[0], al[1], al[2], al[3], b0, b1);
                        }
                    }
                }
            }
            __syncthreads();

            if (vw) {
#pragma unroll
                for (int rr = 0; rr < 2; rr++) {
                    int ml = warp * 16 + g_row + rr * 8;
                    if (ml < pxc) {
#pragma unroll
                        for (int nt = 0; nt < 8; nt++) {
                            int oc = nt * 8 + four * 2;
                            float vx = d[nt][rr * 2]     + bias_sh[oc];
                            float vy = d[nt][rr * 2 + 1] + bias_sh[oc + 1];
                            *(float2*)(rawp + ml * 64 + oc) = make_float2(vx, vy);
                            ps[nt][0] += vx; qs[nt][0] += vx * vx;
                            ps[nt][1] += vy; qs[nt][1] += vy * vy;
                        }
                    }
                }
            }
            __syncthreads();

            int pr0 = r0 >> 1;
            int rend = r0 + rows; if (rend > 2 * Np) rend = 2 * Np;
            int prn = (rend >> 1) - pr0;
            for (int i = tid; i < prn * Np * 64; i += 512) {
                int lpr = i / (Np * 64);
                int rest = i - lpr * (Np * 64);
                int ox = rest >> 6, c = rest & 63;
                int base = ((2 * lpr) * NX + 2 * ox) * 64 + c;
                float v = fmaxf(fmaxf(rawp[base], rawp[base + 64]),
                                fmaxf(rawp[base + NX * 64], rawp[base + NX * 64 + 64]));
                pooled[((size_t)g * (Np * Np) + (pr0 + lpr) * Np + ox) * 64 + c] = v;
            }
        }

#pragma unroll
        for (int nt = 0; nt < 8; nt++)
#pragma unroll
            for (int j = 0; j < 2; j++) {
#pragma unroll
                for (int off = 16; off >= 4; off >>= 1) {
                    ps[nt][j] += __shfl_down_sync(~0u, ps[nt][j], off);
                    qs[nt][j] += __shfl_down_sync(~0u, qs[nt][j], off);
                }
            }
        __syncthreads();
        float* wst = (float*)(smem + OFF_SH);
        if (lane < 4) {
#pragma unroll
            for (int nt = 0; nt < 8; nt++)
#pragma unroll
                for (int j = 0; j < 2; j++) {
                    int oc = nt * 8 + lane * 2 + j;
                    wst[warp * 128 + oc]      = ps[nt][j];
                    wst[warp * 128 + 64 + oc] = qs[nt][j];
                }
        }
        __syncthreads();
        if (tid < 128) {
            float s = 0.f;
#pragma unroll
            for (int wi = 0; wi < 16; wi++) s += wst[wi * 128 + tid];
            partout[(size_t)g * 128 + tid] = s;
        }
    }
}

// ---------------- gemmz: fused BN4 affine prologue ----------------
__global__ void __launch_bounds__(256) gemmz_kernel(
    const float* __restrict__ emb, const float* __restrict__ partin,
    const float* __restrict__ gamma, const float* __restrict__ beta, float invPrev,
    const float* __restrict__ fk, const float* __restrict__ fb,
    const float* __restrict__ bk, const float* __restrict__ bb,
    float* __restrict__ Z)
{
    int gb = blockIdx.x, dir = blockIdx.y;
    const float* W = dir ? bk : fk;
    const float* bias = dir ? bb : fb;
    float* Zo = Z + (size_t)dir * NIMG * 128;
    __shared__ float A_sh[32][33];
    __shared__ __align__(16) float B_sh[32][128];
    __shared__ float ab_sh[128];
    int tid = threadIdx.x, jj = tid & 31, gg = tid >> 5;
    if (tid < 64) {
        float s = 0.f, q = 0.f;
        for (int b = 0; b < 32; b++) {
            s += partin[(size_t)(gb * 32 + b) * 128 + tid];
            q += partin[(size_t)(gb * 32 + b) * 128 + 64 + tid];
        }
        float mn = s * invPrev;
        float var = q * invPrev - mn * mn;
        float sc = gamma[tid] * rsqrtf(var + 1e-3f);
        ab_sh[tid * 2] = sc;
        ab_sh[tid * 2 + 1] = beta[tid] - mn * sc;
    }
    __syncthreads();
    float acc[4][4] = {};
    for (int d0 = 0; d0 < 1600; d0 += 32) {
        for (int i = tid; i < 1024; i += 256) {
            int r = i >> 5, dd = i & 31, d = d0 + dd, c = d & 63;
            float raw = emb[(size_t)(gb * 32 + r) * 1600 + d];
            A_sh[r][dd] = fmaxf(fmaf(ab_sh[c * 2], raw, ab_sh[c * 2 + 1]), 0.f);
        }
        for (int i = tid; i < 4096; i += 256)
            B_sh[i >> 7][i & 127] = W[(size_t)(d0 + (i >> 7)) * 128 + (i & 127)];
        __syncthreads();
#pragma unroll
        for (int dd = 0; dd < 32; dd++) {
            float4 bv = *(const float4*)&B_sh[dd][jj * 4];
#pragma unroll
            for (int r = 0; r < 4; r++) {
                float a = A_sh[gg * 4 + r][dd];
                acc[r][0] += a * bv.x; acc[r][1] += a * bv.y;
                acc[r][2] += a * bv.z; acc[r][3] += a * bv.w;
            }
        }
        __syncthreads();
    }
#pragma unroll
    for (int r = 0; r < 4; r++)
#pragma unroll
        for (int c = 0; c < 4; c++)
            Zo[(size_t)(gb * 32 + gg * 4 + r) * 128 + jj * 4 + c] = acc[r][c] + bias[jj * 4 + c];
}

// ---------------- LSTM ----------------
__global__ void __launch_bounds__(672) lstm_kernel(
    const float* __restrict__ Z,
    const float* __restrict__ fr, const float* __restrict__ br,
    float* __restrict__ outs)
{
    int q = blockIdx.x, dir = blockIdx.y;
    const float* R = dir ? br : fr;
    const float* Zp = Z + (size_t)dir * NIMG * 128;
    __shared__ float Wh[32][128];
    __shared__ float h_sh[21][32], c_sh[21][32];
    int tid = threadIdx.x;
    for (int i = tid; i < 4096; i += 672) Wh[i >> 7][i & 127] = R[i];
    int p = tid >> 5, j = tid & 31;
    h_sh[p][j] = 0.f; c_sh[p][j] = 0.f;
    __syncthreads();
    int slot = (p < 20) ? p : (20 + q);
    for (int step = 0; step < 32; step++) {
        int t = dir ? (31 - step) : step;
        const float* zr = Zp + (size_t)(slot * 32 + t) * 128;
        float z0 = zr[j], z1 = zr[32 + j], z2 = zr[64 + j], z3 = zr[96 + j];
#pragma unroll
        for (int k = 0; k < 32; k++) {
            float hk = h_sh[p][k];
            z0 += hk * Wh[k][j]; z1 += hk * Wh[k][32 + j];
            z2 += hk * Wh[k][64 + j]; z3 += hk * Wh[k][96 + j];
        }
        float ig = 1.f / (1.f + expf(-z0)), fg = 1.f / (1.f + expf(-z1));
        float gg = tanhf(z2), og = 1.f / (1.f + expf(-z3));
        float cn = fg * c_sh[p][j] + ig * gg;
        float hn = og * tanhf(cn);
        __syncthreads();
        h_sh[p][j] = hn; c_sh[p][j] = cn;
        outs[(size_t)((q * 21 + p) * 32 + t) * 64 + dir * 32 + j] = hn;
        __syncthreads();
    }
}

// ---------------- attention + CE + acc ----------------
__global__ void __launch_bounds__(256) final_kernel(
    const float* __restrict__ outs,
    const int* __restrict__ ysup, const int* __restrict__ yqry,
    float* __restrict__ out)
{
    __shared__ float ce_sh[160], eq_sh[160];
    int tid = threadIdx.x;
    if (tid < 160) {
        int q = tid / 32, b = tid % 32;
        const float* qry = outs + (size_t)((q * 21 + 20) * 32 + b) * 64;
        float logit[20];
        for (int s = 0; s < 20; s++) {
            const float* sp = outs + (size_t)((q * 21 + s) * 32 + b) * 64;
            float d = 0.f, n2 = 0.f;
            for (int k = 0; k < 64; k++) { d += qry[k] * sp[k]; n2 += sp[k] * sp[k]; }
            logit[s] = d * rsqrtf(fmaxf(n2, 1e-10f));
        }
        float mx = logit[0];
        for (int s = 1; s < 20; s++) mx = fmaxf(mx, logit[s]);
        float den = 0.f;
        for (int s = 0; s < 20; s++) { logit[s] = expf(logit[s] - mx); den += logit[s]; }
        float invden = 1.f / den;
        float preds[20];
        for (int wq = 0; wq < 20; wq++) preds[wq] = 0.f;
        for (int s = 0; s < 20; s++) preds[ysup[b * 20 + s]] += logit[s] * invden;
        int yq = yqry[b * 5 + q];
        float pv = fminf(fmaxf(preds[yq], 1e-7f), 1.f - 1e-7f);
        ce_sh[tid] = -logf(pv);
        int best = 0;
        for (int wq = 1; wq < 20; wq++) if (preds[wq] > preds[best]) best = wq;
        eq_sh[tid] = (best == yq) ? 1.f : 0.f;
    }
    __syncthreads();
    if (tid < 32) {
        float s = 0.f;
        for (int q = 0; q < 5; q++) s += ce_sh[q * 32 + tid];
        out[tid] = s * 0.2f;
    }
    if (tid == 0) {
        float s = 0.f;
        for (int i = 0; i < 160; i++) s += eq_sh[i];
        out[32] = s / 160.f;
    }
}

// ---------------- launch ----------------
extern "C" void kernel_launch(void* const* d_in, const int* in_sizes, int n_in,
                              void* d_out, int out_size)
{
    (void)in_sizes; (void)n_in; (void)out_size;
    const float* xs = (const float*)d_in[0];
    const int* ysup = (const int*)d_in[1];
    const float* xq = (const float*)d_in[2];
    const int* yqry = (const int*)d_in[3];
    const float *k1=(const float*)d_in[4],  *b1=(const float*)d_in[5],  *g1=(const float*)d_in[6],  *be1=(const float*)d_in[7];
    const float *k2=(const float*)d_in[8],  *b2=(const float*)d_in[9],  *g2=(const float*)d_in[10], *be2=(const float*)d_in[11];
    const float *k3=(const float*)d_in[12], *b3=(const float*)d_in[13], *g3=(const float*)d_in[14], *be3=(const float*)d_in[15];
    const float *k4=(const float*)d_in[16], *b4=(const float*)d_in[17], *g4=(const float*)d_in[18], *be4=(const float*)d_in[19];
    const float *fk=(const float*)d_in[20], *fr=(const float*)d_in[21], *fb=(const float*)d_in[22];
    const float *bk=(const float*)d_in[23], *br=(const float*)d_in[24], *bb=(const float*)d_in[25];

    float *pool1, *pool2, *pool3, *pool4, *partA, *partB, *Z, *outs;
    uint4* wh;
    cudaGetSymbolAddress((void**)&pool1, g_pool1);
    cudaGetSymbolAddress((void**)&pool2, g_pool2);
    cudaGetSymbolAddress((void**)&pool3, g_pool3);
    cudaGetSymbolAddress((void**)&pool4, g_pool4);
    cudaGetSymbolAddress((void**)&partA, g_partA);
    cudaGetSymbolAddress((void**)&partB, g_partB);
    cudaGetSymbolAddress((void**)&Z, g_Z);
    cudaGetSymbolAddress((void**)&outs, g_outs);
    cudaGetSymbolAddress((void**)&wh, g_wh);

    const int SM1  = 1024 + 7588 * 12 + 64 * 80 + 352 * 64 * 4;          // 187312
    const int SM42 = 1024 + 9 * 64 * 144 + 2 * (10 * 44) * 144;          // 210688
    const int SM21 = 1024 + 9 * 64 * 144 + 2 * (16 * 23) * 144;          // 189952
    const int SM10 = 1024 + 9 * 64 * 144 + 2 * (14 * 12) * 144;          // 132352
    cudaFuncSetAttribute(conv1mma2_kernel,          cudaFuncAttributeMaxDynamicSharedMemorySize, SM1);
    cudaFuncSetAttribute(mmaconv_kernel<42,6,7,1>,  cudaFuncAttributeMaxDynamicSharedMemorySize, SM42);
    cudaFuncSetAttribute(mmaconv_kernel<21,12,2,2>, cudaFuncAttributeMaxDynamicSharedMemorySize, SM21);
    cudaFuncSetAttribute(mmaconv_kernel<10,10,1,4>, cudaFuncAttributeMaxDynamicSharedMemorySize, SM10);

    wconv_kernel<<<(3 * 4608 + 255) / 256, 256>>>(k2, k3, k4, wh);
    // L1 -> pool1, partA
    conv1mma2_kernel<<<NIMG, 512, SM1>>>(xs, xq, k1, b1, pool1, partA);
    // L2 -> pool2, partB
    mmaconv_kernel<42,6,7,1><<<NIMG, 512, SM42>>>(pool1, partA, g1, be1, 1.f / (32.f * 7056.f),
                                                  wh, b2, pool2, partB);
    // L3 (2 imgs/block) -> pool3, partA
    mmaconv_kernel<21,12,2,2><<<NIMG / 2, 512, SM21>>>(pool2, partB, g2, be2, 1.f / (32.f * 1764.f),
                                                       wh + 4608, b3, pool3, partA);
    // L4 (4 imgs/block) -> pool4, partB
    mmaconv_kernel<10,10,1,4><<<NIMG / 4, 512, SM10>>>(pool3, partA, g3, be3, 1.f / (32.f * 441.f),
                                                       wh + 2 * 4608, b4, pool4, partB);
    // gemmz: BN4 from partB
    gemmz_kernel<<<dim3(25, 2), 256>>>(pool4, partB, g4, be4, 1.f / (32.f * 100.f),
                                       fk, fb, bk, bb, Z);
    lstm_kernel<<<dim3(5, 2), 672>>>(Z, fr, br, outs);
    final_kernel<<<1, 256>>>(outs, ysup, yqry, (float*)d_out);
}